// round 1
// baseline (speedup 1.0000x reference)
#include <cuda_runtime.h>
#include <math.h>

#define B_    4
#define S_    4096
#define E_    1024
#define H_    64
#define QKV_  192
#define M_TOT (B_ * S_)   // 16384

// Scratch (no cudaMalloc allowed): qkv projection output and attention context.
__device__ float g_qkv[B_ * S_ * QKV_];   // [16384, 192]
__device__ float g_ctx[B_ * S_ * H_];     // [16384, 64]

// ---------------------------------------------------------------------------
// Kernel 1: QKV projection. C[16384,192] = x[16384,1024] @ W[1024,192] + b
// Tiling: BM=128, BN=64, BK=16, 256 threads, 8x4 microtile.
// ---------------------------------------------------------------------------
__global__ __launch_bounds__(256) void qkv_kernel(const float* __restrict__ A,
                                                  const float* __restrict__ W,
                                                  const float* __restrict__ bias) {
    __shared__ float As[16][128];   // k-major: As[k][m]
    __shared__ float Bs[16][64];    // natural: Bs[k][n]

    const int m0  = blockIdx.y * 128;
    const int n0  = blockIdx.x * 64;
    const int tid = threadIdx.x;
    const int ty  = tid >> 4;   // 0..15
    const int tx  = tid & 15;   // 0..15

    float acc[8][4];
#pragma unroll
    for (int i = 0; i < 8; i++)
#pragma unroll
        for (int j = 0; j < 4; j++) acc[i][j] = 0.0f;

    for (int k0 = 0; k0 < E_; k0 += 16) {
        __syncthreads();
        // Load A tile transposed into As[k][m]. Lane owns a distinct row ->
        // conflict-free scatter stores.
#pragma unroll
        for (int i = 0; i < 2; i++) {
            int lin = i * 256 + tid;          // 0..511 (float4 index)
            int row = lin & 127;              // 0..127
            int c4  = lin >> 7;               // 0..3
            float4 v = *reinterpret_cast<const float4*>(
                &A[(size_t)(m0 + row) * E_ + k0 + c4 * 4]);
            As[c4 * 4 + 0][row] = v.x;
            As[c4 * 4 + 1][row] = v.y;
            As[c4 * 4 + 2][row] = v.z;
            As[c4 * 4 + 3][row] = v.w;
        }
        {
            int row = tid >> 4;               // 0..15
            int c4  = tid & 15;               // 0..15
            float4 v = *reinterpret_cast<const float4*>(
                &W[(size_t)(k0 + row) * QKV_ + n0 + c4 * 4]);
            *reinterpret_cast<float4*>(&Bs[row][c4 * 4]) = v;
        }
        __syncthreads();

#pragma unroll
        for (int kk = 0; kk < 16; kk++) {
            float a[8], b[4];
            *reinterpret_cast<float4*>(a)     = *reinterpret_cast<const float4*>(&As[kk][ty * 8]);
            *reinterpret_cast<float4*>(a + 4) = *reinterpret_cast<const float4*>(&As[kk][ty * 8 + 4]);
            *reinterpret_cast<float4*>(b)     = *reinterpret_cast<const float4*>(&Bs[kk][tx * 4]);
#pragma unroll
            for (int i = 0; i < 8; i++)
#pragma unroll
                for (int j = 0; j < 4; j++) acc[i][j] += a[i] * b[j];
        }
    }

    float bb[4];
    *reinterpret_cast<float4*>(bb) = *reinterpret_cast<const float4*>(&bias[n0 + tx * 4]);
#pragma unroll
    for (int i = 0; i < 8; i++) {
        float4 v;
        v.x = acc[i][0] + bb[0];
        v.y = acc[i][1] + bb[1];
        v.z = acc[i][2] + bb[2];
        v.w = acc[i][3] + bb[3];
        *reinterpret_cast<float4*>(&g_qkv[(size_t)(m0 + ty * 8 + i) * QKV_ + n0 + tx * 4]) = v;
    }
}

// ---------------------------------------------------------------------------
// Kernel 2: flash attention per batch. BQ=64, BK=64, H=64, 256 threads.
// Q,K stored contraction(h)-major in smem so the inner loop is float4 LDS.
// P stored natural [q][kv] with pad-65; V natural [kv][h].
// ---------------------------------------------------------------------------
#define ATTN_SMEM_FLOATS (3 * 64 * 64 + 64 * 65)

__global__ __launch_bounds__(256) void attn_kernel() {
    extern __shared__ float sm[];
    float* Qs = sm;                 // [h][q]  (64x64)
    float* Ks = sm + 64 * 64;       // [h][kv] (64x64)
    float* Vs = sm + 2 * 64 * 64;   // [kv][h] (64x64)
    float* Ps = sm + 3 * 64 * 64;   // [q][kv] stride 65

    const int b   = blockIdx.y;
    const int q0  = blockIdx.x * 64;
    const int tid = threadIdx.x;
    const int ty  = tid >> 4;       // 0..15 -> 4 q rows
    const int tx  = tid & 15;       // 0..15 -> 4 kv/h cols
    const size_t base = (size_t)b * S_ * QKV_;

    // Load Q transposed (h-major), scaled by 1/sqrt(H)=0.125.
    // Lane owns a distinct q row -> conflict-free smem stores.
#pragma unroll
    for (int i = 0; i < 4; i++) {
        int lin = i * 256 + tid;            // 0..1023 (float4 index)
        int q   = lin & 63;
        int h4  = (lin >> 6) * 4;
        float4 v = *reinterpret_cast<const float4*>(
            &g_qkv[base + (size_t)(q0 + q) * QKV_ + h4]);
        Qs[(h4 + 0) * 64 + q] = v.x * 0.125f;
        Qs[(h4 + 1) * 64 + q] = v.y * 0.125f;
        Qs[(h4 + 2) * 64 + q] = v.z * 0.125f;
        Qs[(h4 + 3) * 64 + q] = v.w * 0.125f;
    }

    float o[4][4];
    float m_r[4], l_r[4];
#pragma unroll
    for (int i = 0; i < 4; i++) {
        m_r[i] = -1e30f;
        l_r[i] = 0.0f;
#pragma unroll
        for (int j = 0; j < 4; j++) o[i][j] = 0.0f;
    }

    for (int kt = 0; kt < S_ / 64; kt++) {
        const int kv0 = kt * 64;
        __syncthreads();   // protects Qs (first iter) and Ks/Vs/Ps reuse

        // Load K transposed (h-major) + V natural.
#pragma unroll
        for (int i = 0; i < 4; i++) {
            int lin = i * 256 + tid;
            int r   = lin & 63;              // kv row
            int h4  = (lin >> 6) * 4;
            const float* src = &g_qkv[base + (size_t)(kv0 + r) * QKV_ + H_];
            float4 kv = *reinterpret_cast<const float4*>(src + h4);
            Ks[(h4 + 0) * 64 + r] = kv.x;
            Ks[(h4 + 1) * 64 + r] = kv.y;
            Ks[(h4 + 2) * 64 + r] = kv.z;
            Ks[(h4 + 3) * 64 + r] = kv.w;
            float4 vv = *reinterpret_cast<const float4*>(src + H_ + h4);
            *reinterpret_cast<float4*>(&Vs[r * 64 + h4]) = vv;
        }
        __syncthreads();

        // S tile: s[i][j], rows q = ty*4+i, cols kv = tx*4+j
        float s[4][4];
#pragma unroll
        for (int i = 0; i < 4; i++)
#pragma unroll
            for (int j = 0; j < 4; j++) s[i][j] = 0.0f;

#pragma unroll 8
        for (int h = 0; h < 64; h++) {
            float a[4], bq[4];
            *reinterpret_cast<float4*>(a)  = *reinterpret_cast<const float4*>(&Qs[h * 64 + ty * 4]);
            *reinterpret_cast<float4*>(bq) = *reinterpret_cast<const float4*>(&Ks[h * 64 + tx * 4]);
#pragma unroll
            for (int i = 0; i < 4; i++)
#pragma unroll
                for (int j = 0; j < 4; j++) s[i][j] += a[i] * bq[j];
        }

        // Online softmax. Row group = 16 consecutive lanes (same ty).
#pragma unroll
        for (int i = 0; i < 4; i++) {
            float mx = fmaxf(fmaxf(s[i][0], s[i][1]), fmaxf(s[i][2], s[i][3]));
#pragma unroll
            for (int d = 1; d < 16; d <<= 1)
                mx = fmaxf(mx, __shfl_xor_sync(0xffffffffu, mx, d));
            float m_new = fmaxf(m_r[i], mx);
            float alpha = __expf(m_r[i] - m_new);
            m_r[i] = m_new;
            float rs = 0.0f;
#pragma unroll
            for (int j = 0; j < 4; j++) {
                s[i][j] = __expf(s[i][j] - m_new);
                rs += s[i][j];
            }
#pragma unroll
            for (int d = 1; d < 16; d <<= 1)
                rs += __shfl_xor_sync(0xffffffffu, rs, d);
            l_r[i] = l_r[i] * alpha + rs;
#pragma unroll
            for (int j = 0; j < 4; j++) o[i][j] *= alpha;
        }

        // Store P (natural [q][kv], stride 65 to break bank conflicts).
#pragma unroll
        for (int i = 0; i < 4; i++)
#pragma unroll
            for (int j = 0; j < 4; j++)
                Ps[(ty * 4 + i) * 65 + tx * 4 + j] = s[i][j];
        __syncthreads();

        // O += P @ V
#pragma unroll 8
        for (int kv = 0; kv < 64; kv++) {
            float a[4], bv[4];
#pragma unroll
            for (int i = 0; i < 4; i++) a[i] = Ps[(ty * 4 + i) * 65 + kv];
            *reinterpret_cast<float4*>(bv) = *reinterpret_cast<const float4*>(&Vs[kv * 64 + tx * 4]);
#pragma unroll
            for (int i = 0; i < 4; i++)
#pragma unroll
                for (int j = 0; j < 4; j++) o[i][j] += a[i] * bv[j];
        }
    }

    // Normalize and write ctx.
#pragma unroll
    for (int i = 0; i < 4; i++) {
        float inv = 1.0f / l_r[i];
        float4 v;
        v.x = o[i][0] * inv;
        v.y = o[i][1] * inv;
        v.z = o[i][2] * inv;
        v.w = o[i][3] * inv;
        *reinterpret_cast<float4*>(
            &g_ctx[((size_t)b * S_ + q0 + ty * 4 + i) * H_ + tx * 4]) = v;
    }
}

// ---------------------------------------------------------------------------
// Kernel 3: out projection. out[16384,1024] = ctx[16384,64] @ W_out[64,1024] + b
// BM=64, BN=64, K=64 single pass, 256 threads, 4x4 microtile.
// ---------------------------------------------------------------------------
__global__ __launch_bounds__(256) void out_kernel(const float* __restrict__ W,
                                                  const float* __restrict__ bias,
                                                  float* __restrict__ out) {
    __shared__ float Cs[64][64];   // h-major: Cs[h][q]
    __shared__ float Ws[64][64];   // natural: Ws[h][e]

    const int m0  = blockIdx.y * 64;
    const int n0  = blockIdx.x * 64;
    const int tid = threadIdx.x;
    const int ty  = tid >> 4;
    const int tx  = tid & 15;

    // Load ctx tile transposed (lane owns distinct q row -> conflict-free).
#pragma unroll
    for (int i = 0; i < 4; i++) {
        int lin = i * 256 + tid;
        int q   = lin & 63;
        int h4  = (lin >> 6) * 4;
        float4 v = *reinterpret_cast<const float4*>(
            &g_ctx[(size_t)(m0 + q) * H_ + h4]);
        Cs[h4 + 0][q] = v.x;
        Cs[h4 + 1][q] = v.y;
        Cs[h4 + 2][q] = v.z;
        Cs[h4 + 3][q] = v.w;
    }
    // Load W tile natural.
#pragma unroll
    for (int i = 0; i < 4; i++) {
        int lin = i * 256 + tid;
        int r   = lin >> 4;
        int c4  = lin & 15;
        float4 v = *reinterpret_cast<const float4*>(
            &W[(size_t)r * E_ + n0 + c4 * 4]);
        *reinterpret_cast<float4*>(&Ws[r][c4 * 4]) = v;
    }
    __syncthreads();

    float acc[4][4];
#pragma unroll
    for (int i = 0; i < 4; i++)
#pragma unroll
        for (int j = 0; j < 4; j++) acc[i][j] = 0.0f;

#pragma unroll 8
    for (int h = 0; h < 64; h++) {
        float a[4], b[4];
        *reinterpret_cast<float4*>(a) = *reinterpret_cast<const float4*>(&Cs[h][ty * 4]);
        *reinterpret_cast<float4*>(b) = *reinterpret_cast<const float4*>(&Ws[h][tx * 4]);
#pragma unroll
        for (int i = 0; i < 4; i++)
#pragma unroll
            for (int j = 0; j < 4; j++) acc[i][j] += a[i] * b[j];
    }

    float bb[4];
    *reinterpret_cast<float4*>(bb) = *reinterpret_cast<const float4*>(&bias[n0 + tx * 4]);
#pragma unroll
    for (int i = 0; i < 4; i++) {
        float4 v;
        v.x = acc[i][0] + bb[0];
        v.y = acc[i][1] + bb[1];
        v.z = acc[i][2] + bb[2];
        v.w = acc[i][3] + bb[3];
        *reinterpret_cast<float4*>(&out[(size_t)(m0 + ty * 4 + i) * E_ + n0 + tx * 4]) = v;
    }
}

// ---------------------------------------------------------------------------
extern "C" void kernel_launch(void* const* d_in, const int* in_sizes, int n_in,
                              void* d_out, int out_size) {
    const float* x     = (const float*)d_in[0];
    const float* W_qkv = (const float*)d_in[1];
    const float* b_qkv = (const float*)d_in[2];
    const float* W_out = (const float*)d_in[3];
    const float* b_out = (const float*)d_in[4];
    float* out = (float*)d_out;

    // 1) QKV projection
    {
        dim3 grid(QKV_ / 64, M_TOT / 128);
        qkv_kernel<<<grid, 256>>>(x, W_qkv, b_qkv);
    }
    // 2) Flash attention
    {
        size_t smem = ATTN_SMEM_FLOATS * sizeof(float);   // ~65.8 KB
        cudaFuncSetAttribute(attn_kernel,
                             cudaFuncAttributeMaxDynamicSharedMemorySize,
                             (int)smem);
        dim3 grid(S_ / 64, B_);
        attn_kernel<<<grid, 256, smem>>>();
    }
    // 3) Out projection
    {
        dim3 grid(E_ / 64, M_TOT / 64);
        out_kernel<<<grid, 256>>>(W_out, b_out, out);
    }
}

// round 2
// speedup vs baseline: 2.6575x; 2.6575x over previous
#include <cuda_runtime.h>
#include <stdint.h>
#include <math.h>

#define B_    4
#define S_    4096
#define E_    1024
#define H_    64
#define QKV_  192
#define M_TOT (B_ * S_)   // 16384

// Scratch (no cudaMalloc allowed).
__device__ float g_qkv[B_ * S_ * QKV_];   // [16384, 192]
__device__ float g_ctx[B_ * S_ * H_];     // [16384, 64]

// ---------------------------------------------------------------------------
// tf32 helpers
// ---------------------------------------------------------------------------
__device__ __forceinline__ uint32_t f2tf(float f) {
    uint32_t u;
    asm("cvt.rna.tf32.f32 %0, %1;" : "=r"(u) : "f"(f));
    return u;
}

// D = A(16x8,row) * B(8x8,col) + D, tf32 inputs, fp32 accum. In-place on d.
__device__ __forceinline__ void mma_tf32(float d[4], const uint32_t a[4],
                                         const uint32_t b[2]) {
    asm volatile(
        "mma.sync.aligned.m16n8k8.row.col.f32.tf32.tf32.f32 "
        "{%0,%1,%2,%3},{%4,%5,%6,%7},{%8,%9},{%0,%1,%2,%3};\n"
        : "+f"(d[0]), "+f"(d[1]), "+f"(d[2]), "+f"(d[3])
        : "r"(a[0]), "r"(a[1]), "r"(a[2]), "r"(a[3]),
          "r"(b[0]), "r"(b[1]));
}

// ---------------------------------------------------------------------------
// Kernel 1: QKV projection. C[16384,192] = x[16384,1024] @ W[1024,192] + b
// BM=128, BN=192, BK=32. 256 threads (8 warps, 4x2), warp tile 32x96.
// ---------------------------------------------------------------------------
__global__ __launch_bounds__(256) void qkv_kernel(const float* __restrict__ A,
                                                  const float* __restrict__ W,
                                                  const float* __restrict__ bias) {
    __shared__ uint32_t As[128 * 36];   // [m][k] stride 36
    __shared__ uint32_t Ws[32 * 200];   // [k][n] stride 200

    const int m0   = blockIdx.x * 128;
    const int tid  = threadIdx.x;
    const int w    = tid >> 5;
    const int lane = tid & 31;
    const int g    = lane >> 2;
    const int t    = lane & 3;
    const int mw   = w >> 1;    // 0..3
    const int nw   = w & 1;     // 0..1

    float acc[2][12][4];
#pragma unroll
    for (int mt = 0; mt < 2; mt++)
#pragma unroll
        for (int n = 0; n < 12; n++)
#pragma unroll
            for (int j = 0; j < 4; j++) acc[mt][n][j] = 0.0f;

    for (int k0 = 0; k0 < E_; k0 += 32) {
        __syncthreads();
        // A tile: 128 x 32, row-major, stride 36.
#pragma unroll
        for (int i = 0; i < 4; i++) {
            int lin = i * 256 + tid;           // 0..1023 float4
            int r   = lin & 127;
            int c4  = (lin >> 7) * 4;          // 0,4,..,28
            float4 v = *reinterpret_cast<const float4*>(
                &A[(size_t)(m0 + r) * E_ + k0 + c4]);
            As[r * 36 + c4 + 0] = f2tf(v.x);
            As[r * 36 + c4 + 1] = f2tf(v.y);
            As[r * 36 + c4 + 2] = f2tf(v.z);
            As[r * 36 + c4 + 3] = f2tf(v.w);
        }
        // W tile: 32 x 192, row-major, stride 200.
#pragma unroll
        for (int i = 0; i < 6; i++) {
            int lin = i * 256 + tid;           // 0..1535 float4
            int r   = lin / 48;
            int c4  = (lin % 48) * 4;
            float4 v = *reinterpret_cast<const float4*>(
                &W[(size_t)(k0 + r) * QKV_ + c4]);
            Ws[r * 200 + c4 + 0] = f2tf(v.x);
            Ws[r * 200 + c4 + 1] = f2tf(v.y);
            Ws[r * 200 + c4 + 2] = f2tf(v.z);
            Ws[r * 200 + c4 + 3] = f2tf(v.w);
        }
        __syncthreads();

#pragma unroll
        for (int ko = 0; ko < 32; ko += 8) {
            uint32_t a[2][4];
#pragma unroll
            for (int mt = 0; mt < 2; mt++) {
                int row = mw * 32 + mt * 16 + g;
                a[mt][0] = As[row * 36 + ko + t];
                a[mt][1] = As[(row + 8) * 36 + ko + t];
                a[mt][2] = As[row * 36 + ko + t + 4];
                a[mt][3] = As[(row + 8) * 36 + ko + t + 4];
            }
#pragma unroll
            for (int n = 0; n < 12; n++) {
                uint32_t b[2];
                int nc = nw * 96 + 8 * n + g;
                b[0] = Ws[(ko + t) * 200 + nc];
                b[1] = Ws[(ko + t + 4) * 200 + nc];
                mma_tf32(acc[0][n], a[0], b);
                mma_tf32(acc[1][n], a[1], b);
            }
        }
    }

#pragma unroll
    for (int n = 0; n < 12; n++) {
        int col = nw * 96 + 8 * n + 2 * t;
        float b0 = bias[col], b1 = bias[col + 1];
#pragma unroll
        for (int mt = 0; mt < 2; mt++) {
            int row = m0 + mw * 32 + mt * 16 + g;
            float2 v0 = make_float2(acc[mt][n][0] + b0, acc[mt][n][1] + b1);
            *reinterpret_cast<float2*>(&g_qkv[(size_t)row * QKV_ + col]) = v0;
            float2 v1 = make_float2(acc[mt][n][2] + b0, acc[mt][n][3] + b1);
            *reinterpret_cast<float2*>(&g_qkv[(size_t)(row + 8) * QKV_ + col]) = v1;
        }
    }
}

// ---------------------------------------------------------------------------
// Kernel 2: flash attention, tf32 MMA. BQ=128, BK=64. 8 warps x 16 q rows.
// ---------------------------------------------------------------------------
#define ATTN_SMEM_WORDS (128 * 68 + 64 * 68 + 64 * 68 + 128 * 68)

__global__ __launch_bounds__(256) void attn_kernel() {
    extern __shared__ uint32_t sm[];
    uint32_t* Qs  = sm;                       // [128][68] (q x h)
    uint32_t* Ks  = Qs + 128 * 68;            // [64][68]  (kv x h)
    uint32_t* Vts = Ks + 64 * 68;             // [64][68]  (h x kv)  V^T
    uint32_t* Ps  = Vts + 64 * 68;            // [128][68] (q x kv)

    const int b    = blockIdx.y;
    const int q0   = blockIdx.x * 128;
    const int tid  = threadIdx.x;
    const int w    = tid >> 5;
    const int lane = tid & 31;
    const int g    = lane >> 2;
    const int t    = lane & 3;
    const int row0 = w * 16 + g;              // local q row (and +8)
    const size_t base = (size_t)b * S_ * QKV_;

    // Load Q (scaled by 1/sqrt(64)=0.125), row-major q x h.
#pragma unroll
    for (int i = 0; i < 8; i++) {
        int lin = i * 256 + tid;              // 0..2047 float4
        int q   = lin & 127;
        int h4  = (lin >> 7) * 4;
        float4 v = *reinterpret_cast<const float4*>(
            &g_qkv[base + (size_t)(q0 + q) * QKV_ + h4]);
        Qs[q * 68 + h4 + 0] = f2tf(v.x * 0.125f);
        Qs[q * 68 + h4 + 1] = f2tf(v.y * 0.125f);
        Qs[q * 68 + h4 + 2] = f2tf(v.z * 0.125f);
        Qs[q * 68 + h4 + 3] = f2tf(v.w * 0.125f);
    }

    float oacc[8][4];
#pragma unroll
    for (int n = 0; n < 8; n++)
#pragma unroll
        for (int j = 0; j < 4; j++) oacc[n][j] = 0.0f;
    float mr0 = -1e30f, mr1 = -1e30f, l0 = 0.0f, l1 = 0.0f;

    for (int kt = 0; kt < S_ / 64; kt++) {
        const int kv0 = kt * 64;
        __syncthreads();   // prior PV reads of Vts done
        // Load K (row-major kv x h) and V transposed (h x kv).
#pragma unroll
        for (int i = 0; i < 4; i++) {
            int lin = i * 256 + tid;          // 0..1023 float4
            int r   = lin & 63;
            int h4  = (lin >> 6) * 4;
            const float* src = &g_qkv[base + (size_t)(kv0 + r) * QKV_ + H_];
            float4 kq = *reinterpret_cast<const float4*>(src + h4);
            Ks[r * 68 + h4 + 0] = f2tf(kq.x);
            Ks[r * 68 + h4 + 1] = f2tf(kq.y);
            Ks[r * 68 + h4 + 2] = f2tf(kq.z);
            Ks[r * 68 + h4 + 3] = f2tf(kq.w);
            float4 vv = *reinterpret_cast<const float4*>(src + H_ + h4);
            Vts[(h4 + 0) * 68 + r] = f2tf(vv.x);
            Vts[(h4 + 1) * 68 + r] = f2tf(vv.y);
            Vts[(h4 + 2) * 68 + r] = f2tf(vv.z);
            Vts[(h4 + 3) * 68 + r] = f2tf(vv.w);
        }
        __syncthreads();

        // S = Q K^T  (16 x 64 per warp)
        float sacc[8][4];
#pragma unroll
        for (int n = 0; n < 8; n++)
#pragma unroll
            for (int j = 0; j < 4; j++) sacc[n][j] = 0.0f;

#pragma unroll
        for (int ko = 0; ko < 64; ko += 8) {
            uint32_t a[4];
            a[0] = Qs[row0 * 68 + ko + t];
            a[1] = Qs[(row0 + 8) * 68 + ko + t];
            a[2] = Qs[row0 * 68 + ko + t + 4];
            a[3] = Qs[(row0 + 8) * 68 + ko + t + 4];
#pragma unroll
            for (int n = 0; n < 8; n++) {
                uint32_t bb[2];
                bb[0] = Ks[(8 * n + g) * 68 + ko + t];
                bb[1] = Ks[(8 * n + g) * 68 + ko + t + 4];
                mma_tf32(sacc[n], a, bb);
            }
        }

        // Online softmax. Lane owns rows row0 (c0,c1) and row0+8 (c2,c3).
        float m0 = -1e30f, m1 = -1e30f;
#pragma unroll
        for (int n = 0; n < 8; n++) {
            m0 = fmaxf(m0, fmaxf(sacc[n][0], sacc[n][1]));
            m1 = fmaxf(m1, fmaxf(sacc[n][2], sacc[n][3]));
        }
        m0 = fmaxf(m0, __shfl_xor_sync(0xffffffffu, m0, 1));
        m0 = fmaxf(m0, __shfl_xor_sync(0xffffffffu, m0, 2));
        m1 = fmaxf(m1, __shfl_xor_sync(0xffffffffu, m1, 1));
        m1 = fmaxf(m1, __shfl_xor_sync(0xffffffffu, m1, 2));
        float mn0 = fmaxf(mr0, m0);
        float mn1 = fmaxf(mr1, m1);
        float alpha0 = __expf(mr0 - mn0);
        float alpha1 = __expf(mr1 - mn1);
        mr0 = mn0; mr1 = mn1;

        float s0 = 0.0f, s1 = 0.0f;
#pragma unroll
        for (int n = 0; n < 8; n++) {
            sacc[n][0] = __expf(sacc[n][0] - mn0);
            sacc[n][1] = __expf(sacc[n][1] - mn0);
            sacc[n][2] = __expf(sacc[n][2] - mn1);
            sacc[n][3] = __expf(sacc[n][3] - mn1);
            s0 += sacc[n][0] + sacc[n][1];
            s1 += sacc[n][2] + sacc[n][3];
        }
        s0 += __shfl_xor_sync(0xffffffffu, s0, 1);
        s0 += __shfl_xor_sync(0xffffffffu, s0, 2);
        s1 += __shfl_xor_sync(0xffffffffu, s1, 1);
        s1 += __shfl_xor_sync(0xffffffffu, s1, 2);
        l0 = l0 * alpha0 + s0;
        l1 = l1 * alpha1 + s1;
#pragma unroll
        for (int n = 0; n < 8; n++) {
            oacc[n][0] *= alpha0;
            oacc[n][1] *= alpha0;
            oacc[n][2] *= alpha1;
            oacc[n][3] *= alpha1;
        }

        // Write P (tf32) — rows are warp-private, so syncwarp suffices.
#pragma unroll
        for (int n = 0; n < 8; n++) {
            Ps[row0 * 68 + 8 * n + 2 * t]           = f2tf(sacc[n][0]);
            Ps[row0 * 68 + 8 * n + 2 * t + 1]       = f2tf(sacc[n][1]);
            Ps[(row0 + 8) * 68 + 8 * n + 2 * t]     = f2tf(sacc[n][2]);
            Ps[(row0 + 8) * 68 + 8 * n + 2 * t + 1] = f2tf(sacc[n][3]);
        }
        __syncwarp();

        // O += P @ V   (P: 16 x 64, V: 64 x 64 per warp)
#pragma unroll
        for (int ko = 0; ko < 64; ko += 8) {
            uint32_t a[4];
            a[0] = Ps[row0 * 68 + ko + t];
            a[1] = Ps[(row0 + 8) * 68 + ko + t];
            a[2] = Ps[row0 * 68 + ko + t + 4];
            a[3] = Ps[(row0 + 8) * 68 + ko + t + 4];
#pragma unroll
            for (int n = 0; n < 8; n++) {
                uint32_t bb[2];
                bb[0] = Vts[(8 * n + g) * 68 + ko + t];
                bb[1] = Vts[(8 * n + g) * 68 + ko + t + 4];
                mma_tf32(oacc[n], a, bb);
            }
        }
    }

    // Normalize + write ctx.
    float inv0 = 1.0f / l0;
    float inv1 = 1.0f / l1;
    size_t orow = (size_t)b * S_ + q0 + row0;
#pragma unroll
    for (int n = 0; n < 8; n++) {
        int col = 8 * n + 2 * t;
        float2 v0 = make_float2(oacc[n][0] * inv0, oacc[n][1] * inv0);
        *reinterpret_cast<float2*>(&g_ctx[orow * H_ + col]) = v0;
        float2 v1 = make_float2(oacc[n][2] * inv1, oacc[n][3] * inv1);
        *reinterpret_cast<float2*>(&g_ctx[(orow + 8) * H_ + col]) = v1;
    }
}

// ---------------------------------------------------------------------------
// Kernel 3: out projection. out[16384,1024] = ctx[16384,64] @ W_out[64,1024] + b
// BM=128, BN=128, K=64 single pass. 8 warps (4x2), warp tile 32x64.
// ---------------------------------------------------------------------------
#define OUT_SMEM_WORDS (128 * 68 + 64 * 136)

__global__ __launch_bounds__(256) void out_kernel(const float* __restrict__ W,
                                                  const float* __restrict__ bias,
                                                  float* __restrict__ out) {
    extern __shared__ uint32_t sm2[];
    uint32_t* Cs  = sm2;                 // [128][68] (m x k)
    uint32_t* Ws2 = sm2 + 128 * 68;      // [64][136] (k x n)

    const int m0   = blockIdx.y * 128;
    const int n0   = blockIdx.x * 128;
    const int tid  = threadIdx.x;
    const int w    = tid >> 5;
    const int lane = tid & 31;
    const int g    = lane >> 2;
    const int t    = lane & 3;
    const int mw   = w >> 1;
    const int nw   = w & 1;

    // ctx tile 128 x 64, row-major stride 68.
#pragma unroll
    for (int i = 0; i < 8; i++) {
        int lin = i * 256 + tid;          // 0..2047 float4
        int r   = lin & 127;
        int c4  = (lin >> 7) * 4;
        float4 v = *reinterpret_cast<const float4*>(
            &g_ctx[(size_t)(m0 + r) * H_ + c4]);
        Cs[r * 68 + c4 + 0] = f2tf(v.x);
        Cs[r * 68 + c4 + 1] = f2tf(v.y);
        Cs[r * 68 + c4 + 2] = f2tf(v.z);
        Cs[r * 68 + c4 + 3] = f2tf(v.w);
    }
    // W tile 64 x 128, row-major stride 136.
#pragma unroll
    for (int i = 0; i < 8; i++) {
        int lin = i * 256 + tid;          // 0..2047 float4
        int r   = lin >> 5;               // 0..63
        int c4  = (lin & 31) * 4;
        float4 v = *reinterpret_cast<const float4*>(
            &W[(size_t)r * E_ + n0 + c4]);
        Ws2[r * 136 + c4 + 0] = f2tf(v.x);
        Ws2[r * 136 + c4 + 1] = f2tf(v.y);
        Ws2[r * 136 + c4 + 2] = f2tf(v.z);
        Ws2[r * 136 + c4 + 3] = f2tf(v.w);
    }
    __syncthreads();

    float acc[2][8][4];
#pragma unroll
    for (int mt = 0; mt < 2; mt++)
#pragma unroll
        for (int n = 0; n < 8; n++)
#pragma unroll
            for (int j = 0; j < 4; j++) acc[mt][n][j] = 0.0f;

#pragma unroll
    for (int ko = 0; ko < 64; ko += 8) {
        uint32_t a[2][4];
#pragma unroll
        for (int mt = 0; mt < 2; mt++) {
            int row = mw * 32 + mt * 16 + g;
            a[mt][0] = Cs[row * 68 + ko + t];
            a[mt][1] = Cs[(row + 8) * 68 + ko + t];
            a[mt][2] = Cs[row * 68 + ko + t + 4];
            a[mt][3] = Cs[(row + 8) * 68 + ko + t + 4];
        }
#pragma unroll
        for (int n = 0; n < 8; n++) {
            uint32_t bb[2];
            int nc = nw * 64 + 8 * n + g;
            bb[0] = Ws2[(ko + t) * 136 + nc];
            bb[1] = Ws2[(ko + t + 4) * 136 + nc];
            mma_tf32(acc[0][n], a[0], bb);
            mma_tf32(acc[1][n], a[1], bb);
        }
    }

#pragma unroll
    for (int n = 0; n < 8; n++) {
        int col = n0 + nw * 64 + 8 * n + 2 * t;
        float b0 = bias[col], b1 = bias[col + 1];
#pragma unroll
        for (int mt = 0; mt < 2; mt++) {
            int row = m0 + mw * 32 + mt * 16 + g;
            float2 v0 = make_float2(acc[mt][n][0] + b0, acc[mt][n][1] + b1);
            *reinterpret_cast<float2*>(&out[(size_t)row * E_ + col]) = v0;
            float2 v1 = make_float2(acc[mt][n][2] + b0, acc[mt][n][3] + b1);
            *reinterpret_cast<float2*>(&out[(size_t)(row + 8) * E_ + col]) = v1;
        }
    }
}

// ---------------------------------------------------------------------------
extern "C" void kernel_launch(void* const* d_in, const int* in_sizes, int n_in,
                              void* d_out, int out_size) {
    const float* x     = (const float*)d_in[0];
    const float* W_qkv = (const float*)d_in[1];
    const float* b_qkv = (const float*)d_in[2];
    const float* W_out = (const float*)d_in[3];
    const float* b_out = (const float*)d_in[4];
    float* out = (float*)d_out;

    // 1) QKV projection (tf32 MMA): 128 blocks, single wave.
    qkv_kernel<<<M_TOT / 128, 256>>>(x, W_qkv, b_qkv);

    // 2) Flash attention (tf32 MMA): 32 x 4 = 128 blocks, single wave.
    {
        size_t smem = ATTN_SMEM_WORDS * sizeof(uint32_t);   // ~104 KB
        cudaFuncSetAttribute(attn_kernel,
                             cudaFuncAttributeMaxDynamicSharedMemorySize,
                             (int)smem);
        dim3 grid(S_ / 128, B_);
        attn_kernel<<<grid, 256, smem>>>();
    }
    // 3) Out projection (tf32 MMA).
    {
        size_t smem = OUT_SMEM_WORDS * sizeof(uint32_t);    // ~70 KB
        cudaFuncSetAttribute(out_kernel,
                             cudaFuncAttributeMaxDynamicSharedMemorySize,
                             (int)smem);
        dim3 grid(E_ / 128, M_TOT / 128);
        out_kernel<<<grid, 256, smem>>>(W_out, b_out, out);
    }
}

// round 3
// speedup vs baseline: 2.6624x; 1.0018x over previous
#include <cuda_runtime.h>
#include <stdint.h>
#include <math.h>

#define B_    4
#define S_    4096
#define E_    1024
#define H_    64
#define QKV_  192
#define M_TOT (B_ * S_)   // 16384

// Scratch (no cudaMalloc allowed).
__device__ float g_qkv[B_ * S_ * QKV_];   // [16384, 192]
__device__ float g_ctx[B_ * S_ * H_];     // [16384, 64]

// ---------------------------------------------------------------------------
// tf32 helpers
// ---------------------------------------------------------------------------
__device__ __forceinline__ uint32_t f2tf(float f) {
    uint32_t u;
    asm("cvt.rna.tf32.f32 %0, %1;" : "=r"(u) : "f"(f));
    return u;
}

// D = A(16x8,row) * B(8x8,col) + D, tf32 inputs, fp32 accum. In-place on d.
__device__ __forceinline__ void mma_tf32(float d[4], const uint32_t a[4],
                                         const uint32_t b[2]) {
    asm volatile(
        "mma.sync.aligned.m16n8k8.row.col.f32.tf32.tf32.f32 "
        "{%0,%1,%2,%3},{%4,%5,%6,%7},{%8,%9},{%0,%1,%2,%3};\n"
        : "+f"(d[0]), "+f"(d[1]), "+f"(d[2]), "+f"(d[3])
        : "r"(a[0]), "r"(a[1]), "r"(a[2]), "r"(a[3]),
          "r"(b[0]), "r"(b[1]));
}

// ---------------------------------------------------------------------------
// Kernel 1: QKV projection. C[16384,192] = x[16384,1024] @ W[1024,192] + b
// BM=128, BN=192, BK=32. 256 threads (8 warps, 4x2), warp tile 32x96.
// ---------------------------------------------------------------------------
__global__ __launch_bounds__(256) void qkv_kernel(const float* __restrict__ A,
                                                  const float* __restrict__ W,
                                                  const float* __restrict__ bias) {
    __shared__ uint32_t As[128 * 36];   // [m][k] stride 36
    __shared__ uint32_t Ws[32 * 200];   // [k][n] stride 200

    const int m0   = blockIdx.x * 128;
    const int tid  = threadIdx.x;
    const int w    = tid >> 5;
    const int lane = tid & 31;
    const int g    = lane >> 2;
    const int t    = lane & 3;
    const int mw   = w >> 1;    // 0..3
    const int nw   = w & 1;     // 0..1

    float acc[2][12][4];
#pragma unroll
    for (int mt = 0; mt < 2; mt++)
#pragma unroll
        for (int n = 0; n < 12; n++)
#pragma unroll
            for (int j = 0; j < 4; j++) acc[mt][n][j] = 0.0f;

    for (int k0 = 0; k0 < E_; k0 += 32) {
        __syncthreads();
        // A tile: 128 x 32, row-major, stride 36.
#pragma unroll
        for (int i = 0; i < 4; i++) {
            int lin = i * 256 + tid;           // 0..1023 float4
            int r   = lin & 127;
            int c4  = (lin >> 7) * 4;          // 0,4,..,28
            float4 v = *reinterpret_cast<const float4*>(
                &A[(size_t)(m0 + r) * E_ + k0 + c4]);
            As[r * 36 + c4 + 0] = f2tf(v.x);
            As[r * 36 + c4 + 1] = f2tf(v.y);
            As[r * 36 + c4 + 2] = f2tf(v.z);
            As[r * 36 + c4 + 3] = f2tf(v.w);
        }
        // W tile: 32 x 192, row-major, stride 200.
#pragma unroll
        for (int i = 0; i < 6; i++) {
            int lin = i * 256 + tid;           // 0..1535 float4
            int r   = lin / 48;
            int c4  = (lin % 48) * 4;
            float4 v = *reinterpret_cast<const float4*>(
                &W[(size_t)(k0 + r) * QKV_ + c4]);
            Ws[r * 200 + c4 + 0] = f2tf(v.x);
            Ws[r * 200 + c4 + 1] = f2tf(v.y);
            Ws[r * 200 + c4 + 2] = f2tf(v.z);
            Ws[r * 200 + c4 + 3] = f2tf(v.w);
        }
        __syncthreads();

#pragma unroll
        for (int ko = 0; ko < 32; ko += 8) {
            uint32_t a[2][4];
#pragma unroll
            for (int mt = 0; mt < 2; mt++) {
                int row = mw * 32 + mt * 16 + g;
                a[mt][0] = As[row * 36 + ko + t];
                a[mt][1] = As[(row + 8) * 36 + ko + t];
                a[mt][2] = As[row * 36 + ko + t + 4];
                a[mt][3] = As[(row + 8) * 36 + ko + t + 4];
            }
#pragma unroll
            for (int n = 0; n < 12; n++) {
                uint32_t b[2];
                int nc = nw * 96 + 8 * n + g;
                b[0] = Ws[(ko + t) * 200 + nc];
                b[1] = Ws[(ko + t + 4) * 200 + nc];
                mma_tf32(acc[0][n], a[0], b);
                mma_tf32(acc[1][n], a[1], b);
            }
        }
    }

#pragma unroll
    for (int n = 0; n < 12; n++) {
        int col = nw * 96 + 8 * n + 2 * t;
        float b0 = bias[col], b1 = bias[col + 1];
#pragma unroll
        for (int mt = 0; mt < 2; mt++) {
            int row = m0 + mw * 32 + mt * 16 + g;
            float2 v0 = make_float2(acc[mt][n][0] + b0, acc[mt][n][1] + b1);
            *reinterpret_cast<float2*>(&g_qkv[(size_t)row * QKV_ + col]) = v0;
            float2 v1 = make_float2(acc[mt][n][2] + b0, acc[mt][n][3] + b1);
            *reinterpret_cast<float2*>(&g_qkv[(size_t)(row + 8) * QKV_ + col]) = v1;
        }
    }
}

// ---------------------------------------------------------------------------
// Kernel 2: flash attention, tf32 MMA. BQ=128, BK=64. 8 warps x 16 q rows.
// ---------------------------------------------------------------------------
#define ATTN_SMEM_WORDS (128 * 68 + 64 * 68 + 64 * 68 + 128 * 68)

__global__ __launch_bounds__(256) void attn_kernel() {
    extern __shared__ uint32_t sm[];
    uint32_t* Qs  = sm;                       // [128][68] (q x h)
    uint32_t* Ks  = Qs + 128 * 68;            // [64][68]  (kv x h)
    uint32_t* Vts = Ks + 64 * 68;             // [64][68]  (h x kv)  V^T
    uint32_t* Ps  = Vts + 64 * 68;            // [128][68] (q x kv)

    const int b    = blockIdx.y;
    const int q0   = blockIdx.x * 128;
    const int tid  = threadIdx.x;
    const int w    = tid >> 5;
    const int lane = tid & 31;
    const int g    = lane >> 2;
    const int t    = lane & 3;
    const int row0 = w * 16 + g;              // local q row (and +8)
    const size_t base = (size_t)b * S_ * QKV_;

    // Load Q (scaled by 1/sqrt(64)=0.125), row-major q x h.
#pragma unroll
    for (int i = 0; i < 8; i++) {
        int lin = i * 256 + tid;              // 0..2047 float4
        int q   = lin & 127;
        int h4  = (lin >> 7) * 4;
        float4 v = *reinterpret_cast<const float4*>(
            &g_qkv[base + (size_t)(q0 + q) * QKV_ + h4]);
        Qs[q * 68 + h4 + 0] = f2tf(v.x * 0.125f);
        Qs[q * 68 + h4 + 1] = f2tf(v.y * 0.125f);
        Qs[q * 68 + h4 + 2] = f2tf(v.z * 0.125f);
        Qs[q * 68 + h4 + 3] = f2tf(v.w * 0.125f);
    }

    float oacc[8][4];
#pragma unroll
    for (int n = 0; n < 8; n++)
#pragma unroll
        for (int j = 0; j < 4; j++) oacc[n][j] = 0.0f;
    float mr0 = -1e30f, mr1 = -1e30f, l0 = 0.0f, l1 = 0.0f;

    for (int kt = 0; kt < S_ / 64; kt++) {
        const int kv0 = kt * 64;
        __syncthreads();   // prior PV reads of Vts done
        // Load K (row-major kv x h) and V transposed (h x kv).
#pragma unroll
        for (int i = 0; i < 4; i++) {
            int lin = i * 256 + tid;          // 0..1023 float4
            int r   = lin & 63;
            int h4  = (lin >> 6) * 4;
            const float* src = &g_qkv[base + (size_t)(kv0 + r) * QKV_ + H_];
            float4 kq = *reinterpret_cast<const float4*>(src + h4);
            Ks[r * 68 + h4 + 0] = f2tf(kq.x);
            Ks[r * 68 + h4 + 1] = f2tf(kq.y);
            Ks[r * 68 + h4 + 2] = f2tf(kq.z);
            Ks[r * 68 + h4 + 3] = f2tf(kq.w);
            float4 vv = *reinterpret_cast<const float4*>(src + H_ + h4);
            Vts[(h4 + 0) * 68 + r] = f2tf(vv.x);
            Vts[(h4 + 1) * 68 + r] = f2tf(vv.y);
            Vts[(h4 + 2) * 68 + r] = f2tf(vv.z);
            Vts[(h4 + 3) * 68 + r] = f2tf(vv.w);
        }
        __syncthreads();

        // S = Q K^T  (16 x 64 per warp)
        float sacc[8][4];
#pragma unroll
        for (int n = 0; n < 8; n++)
#pragma unroll
            for (int j = 0; j < 4; j++) sacc[n][j] = 0.0f;

#pragma unroll
        for (int ko = 0; ko < 64; ko += 8) {
            uint32_t a[4];
            a[0] = Qs[row0 * 68 + ko + t];
            a[1] = Qs[(row0 + 8) * 68 + ko + t];
            a[2] = Qs[row0 * 68 + ko + t + 4];
            a[3] = Qs[(row0 + 8) * 68 + ko + t + 4];
#pragma unroll
            for (int n = 0; n < 8; n++) {
                uint32_t bb[2];
                bb[0] = Ks[(8 * n + g) * 68 + ko + t];
                bb[1] = Ks[(8 * n + g) * 68 + ko + t + 4];
                mma_tf32(sacc[n], a, bb);
            }
        }

        // Online softmax. Lane owns rows row0 (c0,c1) and row0+8 (c2,c3).
        float m0 = -1e30f, m1 = -1e30f;
#pragma unroll
        for (int n = 0; n < 8; n++) {
            m0 = fmaxf(m0, fmaxf(sacc[n][0], sacc[n][1]));
            m1 = fmaxf(m1, fmaxf(sacc[n][2], sacc[n][3]));
        }
        m0 = fmaxf(m0, __shfl_xor_sync(0xffffffffu, m0, 1));
        m0 = fmaxf(m0, __shfl_xor_sync(0xffffffffu, m0, 2));
        m1 = fmaxf(m1, __shfl_xor_sync(0xffffffffu, m1, 1));
        m1 = fmaxf(m1, __shfl_xor_sync(0xffffffffu, m1, 2));
        float mn0 = fmaxf(mr0, m0);
        float mn1 = fmaxf(mr1, m1);
        float alpha0 = __expf(mr0 - mn0);
        float alpha1 = __expf(mr1 - mn1);
        mr0 = mn0; mr1 = mn1;

        float s0 = 0.0f, s1 = 0.0f;
#pragma unroll
        for (int n = 0; n < 8; n++) {
            sacc[n][0] = __expf(sacc[n][0] - mn0);
            sacc[n][1] = __expf(sacc[n][1] - mn0);
            sacc[n][2] = __expf(sacc[n][2] - mn1);
            sacc[n][3] = __expf(sacc[n][3] - mn1);
            s0 += sacc[n][0] + sacc[n][1];
            s1 += sacc[n][2] + sacc[n][3];
        }
        s0 += __shfl_xor_sync(0xffffffffu, s0, 1);
        s0 += __shfl_xor_sync(0xffffffffu, s0, 2);
        s1 += __shfl_xor_sync(0xffffffffu, s1, 1);
        s1 += __shfl_xor_sync(0xffffffffu, s1, 2);
        l0 = l0 * alpha0 + s0;
        l1 = l1 * alpha1 + s1;
#pragma unroll
        for (int n = 0; n < 8; n++) {
            oacc[n][0] *= alpha0;
            oacc[n][1] *= alpha0;
            oacc[n][2] *= alpha1;
            oacc[n][3] *= alpha1;
        }

        // Write P (tf32) — rows are warp-private, so syncwarp suffices.
#pragma unroll
        for (int n = 0; n < 8; n++) {
            Ps[row0 * 68 + 8 * n + 2 * t]           = f2tf(sacc[n][0]);
            Ps[row0 * 68 + 8 * n + 2 * t + 1]       = f2tf(sacc[n][1]);
            Ps[(row0 + 8) * 68 + 8 * n + 2 * t]     = f2tf(sacc[n][2]);
            Ps[(row0 + 8) * 68 + 8 * n + 2 * t + 1] = f2tf(sacc[n][3]);
        }
        __syncwarp();

        // O += P @ V   (P: 16 x 64, V: 64 x 64 per warp)
#pragma unroll
        for (int ko = 0; ko < 64; ko += 8) {
            uint32_t a[4];
            a[0] = Ps[row0 * 68 + ko + t];
            a[1] = Ps[(row0 + 8) * 68 + ko + t];
            a[2] = Ps[row0 * 68 + ko + t + 4];
            a[3] = Ps[(row0 + 8) * 68 + ko + t + 4];
#pragma unroll
            for (int n = 0; n < 8; n++) {
                uint32_t bb[2];
                bb[0] = Vts[(8 * n + g) * 68 + ko + t];
                bb[1] = Vts[(8 * n + g) * 68 + ko + t + 4];
                mma_tf32(oacc[n], a, bb);
            }
        }
    }

    // Normalize + write ctx.
    float inv0 = 1.0f / l0;
    float inv1 = 1.0f / l1;
    size_t orow = (size_t)b * S_ + q0 + row0;
#pragma unroll
    for (int n = 0; n < 8; n++) {
        int col = 8 * n + 2 * t;
        float2 v0 = make_float2(oacc[n][0] * inv0, oacc[n][1] * inv0);
        *reinterpret_cast<float2*>(&g_ctx[orow * H_ + col]) = v0;
        float2 v1 = make_float2(oacc[n][2] * inv1, oacc[n][3] * inv1);
        *reinterpret_cast<float2*>(&g_ctx[(orow + 8) * H_ + col]) = v1;
    }
}

// ---------------------------------------------------------------------------
// Kernel 3: out projection. out[16384,1024] = ctx[16384,64] @ W_out[64,1024] + b
// BM=128, BN=128, K=64 single pass. 8 warps (4x2), warp tile 32x64.
// ---------------------------------------------------------------------------
#define OUT_SMEM_WORDS (128 * 68 + 64 * 136)

__global__ __launch_bounds__(256) void out_kernel(const float* __restrict__ W,
                                                  const float* __restrict__ bias,
                                                  float* __restrict__ out) {
    extern __shared__ uint32_t sm2[];
    uint32_t* Cs  = sm2;                 // [128][68] (m x k)
    uint32_t* Ws2 = sm2 + 128 * 68;      // [64][136] (k x n)

    const int m0   = blockIdx.y * 128;
    const int n0   = blockIdx.x * 128;
    const int tid  = threadIdx.x;
    const int w    = tid >> 5;
    const int lane = tid & 31;
    const int g    = lane >> 2;
    const int t    = lane & 3;
    const int mw   = w >> 1;
    const int nw   = w & 1;

    // ctx tile 128 x 64, row-major stride 68.
#pragma unroll
    for (int i = 0; i < 8; i++) {
        int lin = i * 256 + tid;          // 0..2047 float4
        int r   = lin & 127;
        int c4  = (lin >> 7) * 4;
        float4 v = *reinterpret_cast<const float4*>(
            &g_ctx[(size_t)(m0 + r) * H_ + c4]);
        Cs[r * 68 + c4 + 0] = f2tf(v.x);
        Cs[r * 68 + c4 + 1] = f2tf(v.y);
        Cs[r * 68 + c4 + 2] = f2tf(v.z);
        Cs[r * 68 + c4 + 3] = f2tf(v.w);
    }
    // W tile 64 x 128, row-major stride 136.
#pragma unroll
    for (int i = 0; i < 8; i++) {
        int lin = i * 256 + tid;          // 0..2047 float4
        int r   = lin >> 5;               // 0..63
        int c4  = (lin & 31) * 4;
        float4 v = *reinterpret_cast<const float4*>(
            &W[(size_t)r * E_ + n0 + c4]);
        Ws2[r * 136 + c4 + 0] = f2tf(v.x);
        Ws2[r * 136 + c4 + 1] = f2tf(v.y);
        Ws2[r * 136 + c4 + 2] = f2tf(v.z);
        Ws2[r * 136 + c4 + 3] = f2tf(v.w);
    }
    __syncthreads();

    float acc[2][8][4];
#pragma unroll
    for (int mt = 0; mt < 2; mt++)
#pragma unroll
        for (int n = 0; n < 8; n++)
#pragma unroll
            for (int j = 0; j < 4; j++) acc[mt][n][j] = 0.0f;

#pragma unroll
    for (int ko = 0; ko < 64; ko += 8) {
        uint32_t a[2][4];
#pragma unroll
        for (int mt = 0; mt < 2; mt++) {
            int row = mw * 32 + mt * 16 + g;
            a[mt][0] = Cs[row * 68 + ko + t];
            a[mt][1] = Cs[(row + 8) * 68 + ko + t];
            a[mt][2] = Cs[row * 68 + ko + t + 4];
            a[mt][3] = Cs[(row + 8) * 68 + ko + t + 4];
        }
#pragma unroll
        for (int n = 0; n < 8; n++) {
            uint32_t bb[2];
            int nc = nw * 64 + 8 * n + g;
            bb[0] = Ws2[(ko + t) * 136 + nc];
            bb[1] = Ws2[(ko + t + 4) * 136 + nc];
            mma_tf32(acc[0][n], a[0], bb);
            mma_tf32(acc[1][n], a[1], bb);
        }
    }

#pragma unroll
    for (int n = 0; n < 8; n++) {
        int col = n0 + nw * 64 + 8 * n + 2 * t;
        float b0 = bias[col], b1 = bias[col + 1];
#pragma unroll
        for (int mt = 0; mt < 2; mt++) {
            int row = m0 + mw * 32 + mt * 16 + g;
            float2 v0 = make_float2(acc[mt][n][0] + b0, acc[mt][n][1] + b1);
            *reinterpret_cast<float2*>(&out[(size_t)row * E_ + col]) = v0;
            float2 v1 = make_float2(acc[mt][n][2] + b0, acc[mt][n][3] + b1);
            *reinterpret_cast<float2*>(&out[(size_t)(row + 8) * E_ + col]) = v1;
        }
    }
}

// ---------------------------------------------------------------------------
extern "C" void kernel_launch(void* const* d_in, const int* in_sizes, int n_in,
                              void* d_out, int out_size) {
    const float* x     = (const float*)d_in[0];
    const float* W_qkv = (const float*)d_in[1];
    const float* b_qkv = (const float*)d_in[2];
    const float* W_out = (const float*)d_in[3];
    const float* b_out = (const float*)d_in[4];
    float* out = (float*)d_out;

    // 1) QKV projection (tf32 MMA): 128 blocks, single wave.
    qkv_kernel<<<M_TOT / 128, 256>>>(x, W_qkv, b_qkv);

    // 2) Flash attention (tf32 MMA): 32 x 4 = 128 blocks, single wave.
    {
        size_t smem = ATTN_SMEM_WORDS * sizeof(uint32_t);   // ~104 KB
        cudaFuncSetAttribute(attn_kernel,
                             cudaFuncAttributeMaxDynamicSharedMemorySize,
                             (int)smem);
        dim3 grid(S_ / 128, B_);
        attn_kernel<<<grid, 256, smem>>>();
    }
    // 3) Out projection (tf32 MMA).
    {
        size_t smem = OUT_SMEM_WORDS * sizeof(uint32_t);    // ~70 KB
        cudaFuncSetAttribute(out_kernel,
                             cudaFuncAttributeMaxDynamicSharedMemorySize,
                             (int)smem);
        dim3 grid(E_ / 128, M_TOT / 128);
        out_kernel<<<grid, 256, smem>>>(W_out, b_out, out);
    }
}

// round 4
// speedup vs baseline: 2.7182x; 1.0210x over previous
#include <cuda_runtime.h>
#include <stdint.h>
#include <math.h>

#define B_    4
#define S_    4096
#define E_    1024
#define H_    64
#define QKV_  192
#define M_TOT (B_ * S_)   // 16384

// Scratch (no cudaMalloc allowed).
__device__ float g_qkv[B_ * S_ * QKV_];   // [16384, 192]
__device__ float g_ctx[B_ * S_ * H_];     // [16384, 64]

// ---------------------------------------------------------------------------
// tf32 helpers
// ---------------------------------------------------------------------------
__device__ __forceinline__ uint32_t f2tf(float f) {
    uint32_t u;
    asm("cvt.rna.tf32.f32 %0, %1;" : "=r"(u) : "f"(f));
    return u;
}

// D = A(16x8,row) * B(8x8,col) + D, tf32 inputs, fp32 accum. In-place on d.
__device__ __forceinline__ void mma_tf32(float d[4], const uint32_t a[4],
                                         const uint32_t b[2]) {
    asm volatile(
        "mma.sync.aligned.m16n8k8.row.col.f32.tf32.tf32.f32 "
        "{%0,%1,%2,%3},{%4,%5,%6,%7},{%8,%9},{%0,%1,%2,%3};\n"
        : "+f"(d[0]), "+f"(d[1]), "+f"(d[2]), "+f"(d[3])
        : "r"(a[0]), "r"(a[1]), "r"(a[2]), "r"(a[3]),
          "r"(b[0]), "r"(b[1]));
}

// ---------------------------------------------------------------------------
// Kernel 1: QKV projection. C[16384,192] = x[16384,1024] @ W[1024,192] + b
// BM=128, BN=192, BK=32. 256 threads (8 warps, 4x2), warp tile 32x96.
// ---------------------------------------------------------------------------
__global__ __launch_bounds__(256) void qkv_kernel(const float* __restrict__ A,
                                                  const float* __restrict__ W,
                                                  const float* __restrict__ bias) {
    __shared__ uint32_t As[128 * 36];   // [m][k] stride 36
    __shared__ uint32_t Ws[32 * 200];   // [k][n] stride 200

    const int m0   = blockIdx.x * 128;
    const int tid  = threadIdx.x;
    const int w    = tid >> 5;
    const int lane = tid & 31;
    const int g    = lane >> 2;
    const int t    = lane & 3;
    const int mw   = w >> 1;    // 0..3
    const int nw   = w & 1;     // 0..1

    float acc[2][12][4];
#pragma unroll
    for (int mt = 0; mt < 2; mt++)
#pragma unroll
        for (int n = 0; n < 12; n++)
#pragma unroll
            for (int j = 0; j < 4; j++) acc[mt][n][j] = 0.0f;

    for (int k0 = 0; k0 < E_; k0 += 32) {
        __syncthreads();
        // A tile: 128 x 32, row-major, stride 36.
#pragma unroll
        for (int i = 0; i < 4; i++) {
            int lin = i * 256 + tid;           // 0..1023 float4
            int r   = lin & 127;
            int c4  = (lin >> 7) * 4;          // 0,4,..,28
            float4 v = *reinterpret_cast<const float4*>(
                &A[(size_t)(m0 + r) * E_ + k0 + c4]);
            As[r * 36 + c4 + 0] = f2tf(v.x);
            As[r * 36 + c4 + 1] = f2tf(v.y);
            As[r * 36 + c4 + 2] = f2tf(v.z);
            As[r * 36 + c4 + 3] = f2tf(v.w);
        }
        // W tile: 32 x 192, row-major, stride 200.
#pragma unroll
        for (int i = 0; i < 6; i++) {
            int lin = i * 256 + tid;           // 0..1535 float4
            int r   = lin / 48;
            int c4  = (lin % 48) * 4;
            float4 v = *reinterpret_cast<const float4*>(
                &W[(size_t)(k0 + r) * QKV_ + c4]);
            Ws[r * 200 + c4 + 0] = f2tf(v.x);
            Ws[r * 200 + c4 + 1] = f2tf(v.y);
            Ws[r * 200 + c4 + 2] = f2tf(v.z);
            Ws[r * 200 + c4 + 3] = f2tf(v.w);
        }
        __syncthreads();

#pragma unroll
        for (int ko = 0; ko < 32; ko += 8) {
            uint32_t a[2][4];
#pragma unroll
            for (int mt = 0; mt < 2; mt++) {
                int row = mw * 32 + mt * 16 + g;
                a[mt][0] = As[row * 36 + ko + t];
                a[mt][1] = As[(row + 8) * 36 + ko + t];
                a[mt][2] = As[row * 36 + ko + t + 4];
                a[mt][3] = As[(row + 8) * 36 + ko + t + 4];
            }
#pragma unroll
            for (int n = 0; n < 12; n++) {
                uint32_t b[2];
                int nc = nw * 96 + 8 * n + g;
                b[0] = Ws[(ko + t) * 200 + nc];
                b[1] = Ws[(ko + t + 4) * 200 + nc];
                mma_tf32(acc[0][n], a[0], b);
                mma_tf32(acc[1][n], a[1], b);
            }
        }
    }

#pragma unroll
    for (int n = 0; n < 12; n++) {
        int col = nw * 96 + 8 * n + 2 * t;
        float b0 = bias[col], b1 = bias[col + 1];
#pragma unroll
        for (int mt = 0; mt < 2; mt++) {
            int row = m0 + mw * 32 + mt * 16 + g;
            float2 v0 = make_float2(acc[mt][n][0] + b0, acc[mt][n][1] + b1);
            *reinterpret_cast<float2*>(&g_qkv[(size_t)row * QKV_ + col]) = v0;
            float2 v1 = make_float2(acc[mt][n][2] + b0, acc[mt][n][3] + b1);
            *reinterpret_cast<float2*>(&g_qkv[(size_t)(row + 8) * QKV_ + col]) = v1;
        }
    }
}

// ---------------------------------------------------------------------------
// Kernel 2: flash attention, tf32 MMA. BQ=128, BK=64. 8 warps x 16 q rows.
// ---------------------------------------------------------------------------
#define ATTN_SMEM_WORDS (128 * 68 + 64 * 68 + 64 * 68 + 128 * 68)

__global__ __launch_bounds__(256) void attn_kernel() {
    extern __shared__ uint32_t sm[];
    uint32_t* Qs  = sm;                       // [128][68] (q x h)
    uint32_t* Ks  = Qs + 128 * 68;            // [64][68]  (kv x h)
    uint32_t* Vts = Ks + 64 * 68;             // [64][68]  (h x kv)  V^T
    uint32_t* Ps  = Vts + 64 * 68;            // [128][68] (q x kv)

    const int b    = blockIdx.y;
    const int q0   = blockIdx.x * 128;
    const int tid  = threadIdx.x;
    const int w    = tid >> 5;
    const int lane = tid & 31;
    const int g    = lane >> 2;
    const int t    = lane & 3;
    const int row0 = w * 16 + g;              // local q row (and +8)
    const size_t base = (size_t)b * S_ * QKV_;

    // Load Q (scaled by 1/sqrt(64)=0.125), row-major q x h.
#pragma unroll
    for (int i = 0; i < 8; i++) {
        int lin = i * 256 + tid;              // 0..2047 float4
        int q   = lin & 127;
        int h4  = (lin >> 7) * 4;
        float4 v = *reinterpret_cast<const float4*>(
            &g_qkv[base + (size_t)(q0 + q) * QKV_ + h4]);
        Qs[q * 68 + h4 + 0] = f2tf(v.x * 0.125f);
        Qs[q * 68 + h4 + 1] = f2tf(v.y * 0.125f);
        Qs[q * 68 + h4 + 2] = f2tf(v.z * 0.125f);
        Qs[q * 68 + h4 + 3] = f2tf(v.w * 0.125f);
    }

    float oacc[8][4];
#pragma unroll
    for (int n = 0; n < 8; n++)
#pragma unroll
        for (int j = 0; j < 4; j++) oacc[n][j] = 0.0f;
    float mr0 = -1e30f, mr1 = -1e30f, l0 = 0.0f, l1 = 0.0f;

    for (int kt = 0; kt < S_ / 64; kt++) {
        const int kv0 = kt * 64;
        __syncthreads();   // prior PV reads of Vts done
        // Load K (row-major kv x h) and V transposed (h x kv).
#pragma unroll
        for (int i = 0; i < 4; i++) {
            int lin = i * 256 + tid;          // 0..1023 float4
            int r   = lin & 63;
            int h4  = (lin >> 6) * 4;
            const float* src = &g_qkv[base + (size_t)(kv0 + r) * QKV_ + H_];
            float4 kq = *reinterpret_cast<const float4*>(src + h4);
            Ks[r * 68 + h4 + 0] = f2tf(kq.x);
            Ks[r * 68 + h4 + 1] = f2tf(kq.y);
            Ks[r * 68 + h4 + 2] = f2tf(kq.z);
            Ks[r * 68 + h4 + 3] = f2tf(kq.w);
            float4 vv = *reinterpret_cast<const float4*>(src + H_ + h4);
            Vts[(h4 + 0) * 68 + r] = f2tf(vv.x);
            Vts[(h4 + 1) * 68 + r] = f2tf(vv.y);
            Vts[(h4 + 2) * 68 + r] = f2tf(vv.z);
            Vts[(h4 + 3) * 68 + r] = f2tf(vv.w);
        }
        __syncthreads();

        // S = Q K^T  (16 x 64 per warp)
        float sacc[8][4];
#pragma unroll
        for (int n = 0; n < 8; n++)
#pragma unroll
            for (int j = 0; j < 4; j++) sacc[n][j] = 0.0f;

#pragma unroll
        for (int ko = 0; ko < 64; ko += 8) {
            uint32_t a[4];
            a[0] = Qs[row0 * 68 + ko + t];
            a[1] = Qs[(row0 + 8) * 68 + ko + t];
            a[2] = Qs[row0 * 68 + ko + t + 4];
            a[3] = Qs[(row0 + 8) * 68 + ko + t + 4];
#pragma unroll
            for (int n = 0; n < 8; n++) {
                uint32_t bb[2];
                bb[0] = Ks[(8 * n + g) * 68 + ko + t];
                bb[1] = Ks[(8 * n + g) * 68 + ko + t + 4];
                mma_tf32(sacc[n], a, bb);
            }
        }

        // Online softmax. Lane owns rows row0 (c0,c1) and row0+8 (c2,c3).
        float m0 = -1e30f, m1 = -1e30f;
#pragma unroll
        for (int n = 0; n < 8; n++) {
            m0 = fmaxf(m0, fmaxf(sacc[n][0], sacc[n][1]));
            m1 = fmaxf(m1, fmaxf(sacc[n][2], sacc[n][3]));
        }
        m0 = fmaxf(m0, __shfl_xor_sync(0xffffffffu, m0, 1));
        m0 = fmaxf(m0, __shfl_xor_sync(0xffffffffu, m0, 2));
        m1 = fmaxf(m1, __shfl_xor_sync(0xffffffffu, m1, 1));
        m1 = fmaxf(m1, __shfl_xor_sync(0xffffffffu, m1, 2));
        float mn0 = fmaxf(mr0, m0);
        float mn1 = fmaxf(mr1, m1);
        float alpha0 = __expf(mr0 - mn0);
        float alpha1 = __expf(mr1 - mn1);
        mr0 = mn0; mr1 = mn1;

        float s0 = 0.0f, s1 = 0.0f;
#pragma unroll
        for (int n = 0; n < 8; n++) {
            sacc[n][0] = __expf(sacc[n][0] - mn0);
            sacc[n][1] = __expf(sacc[n][1] - mn0);
            sacc[n][2] = __expf(sacc[n][2] - mn1);
            sacc[n][3] = __expf(sacc[n][3] - mn1);
            s0 += sacc[n][0] + sacc[n][1];
            s1 += sacc[n][2] + sacc[n][3];
        }
        s0 += __shfl_xor_sync(0xffffffffu, s0, 1);
        s0 += __shfl_xor_sync(0xffffffffu, s0, 2);
        s1 += __shfl_xor_sync(0xffffffffu, s1, 1);
        s1 += __shfl_xor_sync(0xffffffffu, s1, 2);
        l0 = l0 * alpha0 + s0;
        l1 = l1 * alpha1 + s1;
#pragma unroll
        for (int n = 0; n < 8; n++) {
            oacc[n][0] *= alpha0;
            oacc[n][1] *= alpha0;
            oacc[n][2] *= alpha1;
            oacc[n][3] *= alpha1;
        }

        // Write P (tf32) — rows are warp-private, so syncwarp suffices.
#pragma unroll
        for (int n = 0; n < 8; n++) {
            Ps[row0 * 68 + 8 * n + 2 * t]           = f2tf(sacc[n][0]);
            Ps[row0 * 68 + 8 * n + 2 * t + 1]       = f2tf(sacc[n][1]);
            Ps[(row0 + 8) * 68 + 8 * n + 2 * t]     = f2tf(sacc[n][2]);
            Ps[(row0 + 8) * 68 + 8 * n + 2 * t + 1] = f2tf(sacc[n][3]);
        }
        __syncwarp();

        // O += P @ V   (P: 16 x 64, V: 64 x 64 per warp)
#pragma unroll
        for (int ko = 0; ko < 64; ko += 8) {
            uint32_t a[4];
            a[0] = Ps[row0 * 68 + ko + t];
            a[1] = Ps[(row0 + 8) * 68 + ko + t];
            a[2] = Ps[row0 * 68 + ko + t + 4];
            a[3] = Ps[(row0 + 8) * 68 + ko + t + 4];
#pragma unroll
            for (int n = 0; n < 8; n++) {
                uint32_t bb[2];
                bb[0] = Vts[(8 * n + g) * 68 + ko + t];
                bb[1] = Vts[(8 * n + g) * 68 + ko + t + 4];
                mma_tf32(oacc[n], a, bb);
            }
        }
    }

    // Normalize + write ctx.
    float inv0 = 1.0f / l0;
    float inv1 = 1.0f / l1;
    size_t orow = (size_t)b * S_ + q0 + row0;
#pragma unroll
    for (int n = 0; n < 8; n++) {
        int col = 8 * n + 2 * t;
        float2 v0 = make_float2(oacc[n][0] * inv0, oacc[n][1] * inv0);
        *reinterpret_cast<float2*>(&g_ctx[orow * H_ + col]) = v0;
        float2 v1 = make_float2(oacc[n][2] * inv1, oacc[n][3] * inv1);
        *reinterpret_cast<float2*>(&g_ctx[(orow + 8) * H_ + col]) = v1;
    }
}

// ---------------------------------------------------------------------------
// Kernel 3: out projection. out[16384,1024] = ctx[16384,64] @ W_out[64,1024] + b
// BM=128, BN=128, K=64 single pass. 8 warps (4x2), warp tile 32x64.
// ---------------------------------------------------------------------------
#define OUT_SMEM_WORDS (128 * 68 + 64 * 136)

__global__ __launch_bounds__(256) void out_kernel(const float* __restrict__ W,
                                                  const float* __restrict__ bias,
                                                  float* __restrict__ out) {
    extern __shared__ uint32_t sm2[];
    uint32_t* Cs  = sm2;                 // [128][68] (m x k)
    uint32_t* Ws2 = sm2 + 128 * 68;      // [64][136] (k x n)

    const int m0   = blockIdx.y * 128;
    const int n0   = blockIdx.x * 128;
    const int tid  = threadIdx.x;
    const int w    = tid >> 5;
    const int lane = tid & 31;
    const int g    = lane >> 2;
    const int t    = lane & 3;
    const int mw   = w >> 1;
    const int nw   = w & 1;

    // ctx tile 128 x 64, row-major stride 68.
#pragma unroll
    for (int i = 0; i < 8; i++) {
        int lin = i * 256 + tid;          // 0..2047 float4
        int r   = lin & 127;
        int c4  = (lin >> 7) * 4;
        float4 v = *reinterpret_cast<const float4*>(
            &g_ctx[(size_t)(m0 + r) * H_ + c4]);
        Cs[r * 68 + c4 + 0] = f2tf(v.x);
        Cs[r * 68 + c4 + 1] = f2tf(v.y);
        Cs[r * 68 + c4 + 2] = f2tf(v.z);
        Cs[r * 68 + c4 + 3] = f2tf(v.w);
    }
    // W tile 64 x 128, row-major stride 136.
#pragma unroll
    for (int i = 0; i < 8; i++) {
        int lin = i * 256 + tid;          // 0..2047 float4
        int r   = lin >> 5;               // 0..63
        int c4  = (lin & 31) * 4;
        float4 v = *reinterpret_cast<const float4*>(
            &W[(size_t)r * E_ + n0 + c4]);
        Ws2[r * 136 + c4 + 0] = f2tf(v.x);
        Ws2[r * 136 + c4 + 1] = f2tf(v.y);
        Ws2[r * 136 + c4 + 2] = f2tf(v.z);
        Ws2[r * 136 + c4 + 3] = f2tf(v.w);
    }
    __syncthreads();

    float acc[2][8][4];
#pragma unroll
    for (int mt = 0; mt < 2; mt++)
#pragma unroll
        for (int n = 0; n < 8; n++)
#pragma unroll
            for (int j = 0; j < 4; j++) acc[mt][n][j] = 0.0f;

#pragma unroll
    for (int ko = 0; ko < 64; ko += 8) {
        uint32_t a[2][4];
#pragma unroll
        for (int mt = 0; mt < 2; mt++) {
            int row = mw * 32 + mt * 16 + g;
            a[mt][0] = Cs[row * 68 + ko + t];
            a[mt][1] = Cs[(row + 8) * 68 + ko + t];
            a[mt][2] = Cs[row * 68 + ko + t + 4];
            a[mt][3] = Cs[(row + 8) * 68 + ko + t + 4];
        }
#pragma unroll
        for (int n = 0; n < 8; n++) {
            uint32_t bb[2];
            int nc = nw * 64 + 8 * n + g;
            bb[0] = Ws2[(ko + t) * 136 + nc];
            bb[1] = Ws2[(ko + t + 4) * 136 + nc];
            mma_tf32(acc[0][n], a[0], bb);
            mma_tf32(acc[1][n], a[1], bb);
        }
    }

#pragma unroll
    for (int n = 0; n < 8; n++) {
        int col = n0 + nw * 64 + 8 * n + 2 * t;
        float b0 = bias[col], b1 = bias[col + 1];
#pragma unroll
        for (int mt = 0; mt < 2; mt++) {
            int row = m0 + mw * 32 + mt * 16 + g;
            float2 v0 = make_float2(acc[mt][n][0] + b0, acc[mt][n][1] + b1);
            *reinterpret_cast<float2*>(&out[(size_t)row * E_ + col]) = v0;
            float2 v1 = make_float2(acc[mt][n][2] + b0, acc[mt][n][3] + b1);
            *reinterpret_cast<float2*>(&out[(size_t)(row + 8) * E_ + col]) = v1;
        }
    }
}

// ---------------------------------------------------------------------------
extern "C" void kernel_launch(void* const* d_in, const int* in_sizes, int n_in,
                              void* d_out, int out_size) {
    const float* x     = (const float*)d_in[0];
    const float* W_qkv = (const float*)d_in[1];
    const float* b_qkv = (const float*)d_in[2];
    const float* W_out = (const float*)d_in[3];
    const float* b_out = (const float*)d_in[4];
    float* out = (float*)d_out;

    // 1) QKV projection (tf32 MMA): 128 blocks, single wave.
    qkv_kernel<<<M_TOT / 128, 256>>>(x, W_qkv, b_qkv);

    // 2) Flash attention (tf32 MMA): 32 x 4 = 128 blocks, single wave.
    {
        size_t smem = ATTN_SMEM_WORDS * sizeof(uint32_t);   // ~104 KB
        cudaFuncSetAttribute(attn_kernel,
                             cudaFuncAttributeMaxDynamicSharedMemorySize,
                             (int)smem);
        dim3 grid(S_ / 128, B_);
        attn_kernel<<<grid, 256, smem>>>();
    }
    // 3) Out projection (tf32 MMA).
    {
        size_t smem = OUT_SMEM_WORDS * sizeof(uint32_t);    // ~70 KB
        cudaFuncSetAttribute(out_kernel,
                             cudaFuncAttributeMaxDynamicSharedMemorySize,
                             (int)smem);
        dim3 grid(E_ / 128, M_TOT / 128);
        out_kernel<<<grid, 256, smem>>>(W_out, b_out, out);
    }
}

// round 5
// speedup vs baseline: 3.5852x; 1.3190x over previous
#include <cuda_runtime.h>
#include <stdint.h>
#include <math.h>

#define B_    4
#define S_    4096
#define E_    1024
#define H_    64
#define QKV_  192
#define M_TOT (B_ * S_)   // 16384

__device__ float g_qkv[B_ * S_ * QKV_];   // [16384, 192]
__device__ float g_ctx[B_ * S_ * H_];     // [16384, 64]

// ---------------------------------------------------------------------------
// helpers
// ---------------------------------------------------------------------------
__device__ __forceinline__ uint32_t f2tf(float f) {
    uint32_t u;
    asm("cvt.rna.tf32.f32 %0, %1;" : "=r"(u) : "f"(f));
    return u;
}
__device__ __forceinline__ uint4 cvt4(float4 v) {
    uint4 u;
    u.x = f2tf(v.x); u.y = f2tf(v.y); u.z = f2tf(v.z); u.w = f2tf(v.w);
    return u;
}
__device__ __forceinline__ void mma_tf32(float d[4], const uint32_t a[4],
                                         const uint32_t b[2]) {
    asm volatile(
        "mma.sync.aligned.m16n8k8.row.col.f32.tf32.tf32.f32 "
        "{%0,%1,%2,%3},{%4,%5,%6,%7},{%8,%9},{%0,%1,%2,%3};\n"
        : "+f"(d[0]), "+f"(d[1]), "+f"(d[2]), "+f"(d[3])
        : "r"(a[0]), "r"(a[1]), "r"(a[2]), "r"(a[3]),
          "r"(b[0]), "r"(b[1]));
}
// tf32 fragment loads via b16 ldmatrix (1 row = 16B = 4 tf32).
__device__ __forceinline__ void ldsm_x4(uint32_t d[4], uint32_t saddr) {
    asm volatile("ldmatrix.sync.aligned.m8n8.x4.shared.b16 {%0,%1,%2,%3}, [%4];"
                 : "=r"(d[0]), "=r"(d[1]), "=r"(d[2]), "=r"(d[3]) : "r"(saddr));
}
__device__ __forceinline__ void ldsm_x2(uint32_t d[2], uint32_t saddr) {
    asm volatile("ldmatrix.sync.aligned.m8n8.x2.shared.b16 {%0,%1}, [%2];"
                 : "=r"(d[0]), "=r"(d[1]) : "r"(saddr));
}
__device__ __forceinline__ uint32_t smem_u32(const void* p) {
    return (uint32_t)__cvta_generic_to_shared(p);
}

// ---------------------------------------------------------------------------
// Kernel 1: QKV projection. C[16384,192] = x[16384,1024] @ W[1024,192] + b
// BM=128, BN=192, BK=32, 8 warps (4x2), warp tile 32x96. LDG prefetch + ldmatrix A.
// ---------------------------------------------------------------------------
__global__ __launch_bounds__(256) void qkv_kernel(const float* __restrict__ A,
                                                  const float* __restrict__ W,
                                                  const float* __restrict__ bias) {
    __shared__ uint32_t As[128 * 36];   // [m][k] stride 36
    __shared__ uint32_t Ws[32 * 200];   // [k][n] stride 200

    const int m0   = blockIdx.x * 128;
    const int tid  = threadIdx.x;
    const int w    = tid >> 5;
    const int lane = tid & 31;
    const int g    = lane >> 2;
    const int t    = lane & 3;
    const int mw   = w >> 1;
    const int nw   = w & 1;

    const uint32_t Ab = smem_u32(As);
    // per-lane ldmatrix offsets (words) for A fragments, mt = 0/1
    const int aoff0 = (mw * 32 + (lane & 15)) * 36 + (lane >> 4) * 4;
    const int aoff1 = aoff0 + 16 * 36;

    float acc[2][12][4];
#pragma unroll
    for (int mt = 0; mt < 2; mt++)
#pragma unroll
        for (int n = 0; n < 12; n++)
#pragma unroll
            for (int j = 0; j < 4; j++) acc[mt][n][j] = 0.0f;

    float4 areg[4], wreg[6];
    // prefetch k0 = 0 (coalesced: 8 consecutive lanes per row)
#pragma unroll
    for (int i = 0; i < 4; i++) {
        int lin = i * 256 + tid;
        int r = lin >> 3, c4 = lin & 7;
        areg[i] = *reinterpret_cast<const float4*>(&A[(size_t)(m0 + r) * E_ + c4 * 4]);
    }
#pragma unroll
    for (int i = 0; i < 6; i++) {
        int lin = i * 256 + tid;
        int r = lin / 48, c = lin % 48;
        wreg[i] = *reinterpret_cast<const float4*>(&W[(size_t)r * QKV_ + c * 4]);
    }

    for (int k0 = 0; k0 < E_; k0 += 32) {
        __syncthreads();
#pragma unroll
        for (int i = 0; i < 4; i++) {
            int lin = i * 256 + tid;
            int r = lin >> 3, c4 = lin & 7;
            *reinterpret_cast<uint4*>(&As[r * 36 + c4 * 4]) = cvt4(areg[i]);
        }
#pragma unroll
        for (int i = 0; i < 6; i++) {
            int lin = i * 256 + tid;
            int r = lin / 48, c = lin % 48;
            *reinterpret_cast<uint4*>(&Ws[r * 200 + c * 4]) = cvt4(wreg[i]);
        }
        __syncthreads();

        if (k0 + 32 < E_) {
#pragma unroll
            for (int i = 0; i < 4; i++) {
                int lin = i * 256 + tid;
                int r = lin >> 3, c4 = lin & 7;
                areg[i] = *reinterpret_cast<const float4*>(
                    &A[(size_t)(m0 + r) * E_ + k0 + 32 + c4 * 4]);
            }
#pragma unroll
            for (int i = 0; i < 6; i++) {
                int lin = i * 256 + tid;
                int r = lin / 48, c = lin % 48;
                wreg[i] = *reinterpret_cast<const float4*>(
                    &W[(size_t)(k0 + 32 + r) * QKV_ + c * 4]);
            }
        }

#pragma unroll
        for (int ko8 = 0; ko8 < 4; ko8++) {
            const int ko = ko8 * 8;
            uint32_t a[2][4];
            ldsm_x4(a[0], Ab + 4u * (aoff0 + ko));
            ldsm_x4(a[1], Ab + 4u * (aoff1 + ko));
#pragma unroll
            for (int n = 0; n < 12; n++) {
                uint32_t b[2];
                int nc = nw * 96 + 8 * n + g;
                b[0] = Ws[(ko + t) * 200 + nc];
                b[1] = Ws[(ko + t + 4) * 200 + nc];
                mma_tf32(acc[0][n], a[0], b);
                mma_tf32(acc[1][n], a[1], b);
            }
        }
    }

#pragma unroll
    for (int n = 0; n < 12; n++) {
        int col = nw * 96 + 8 * n + 2 * t;
        float b0 = bias[col], b1 = bias[col + 1];
#pragma unroll
        for (int mt = 0; mt < 2; mt++) {
            int row = m0 + mw * 32 + mt * 16 + g;
            float2 v0 = make_float2(acc[mt][n][0] + b0, acc[mt][n][1] + b1);
            *reinterpret_cast<float2*>(&g_qkv[(size_t)row * QKV_ + col]) = v0;
            float2 v1 = make_float2(acc[mt][n][2] + b0, acc[mt][n][3] + b1);
            *reinterpret_cast<float2*>(&g_qkv[(size_t)(row + 8) * QKV_ + col]) = v1;
        }
    }
}

// ---------------------------------------------------------------------------
// Kernel 2: flash attention. BQ=128, BK=64. 8 warps = 4(m=32) x 2(kv-half).
// Per-warp online softmax over its kv half; final cross-warp merge.
// ---------------------------------------------------------------------------
#define Q_OFF 0
#define K_OFF (128 * 68)
#define V_OFF (K_OFF + 64 * 68)
#define P_OFF (V_OFF + 64 * 68)
#define MS_OFF (P_OFF + 128 * 68)
#define LS_OFF (MS_OFF + 128)
#define ATTN_SMEM_WORDS (LS_OFF + 128)

__global__ __launch_bounds__(256) void attn_kernel() {
    extern __shared__ uint32_t sm[];
    uint32_t* Qs  = sm + Q_OFF;     // [128 q][68] (q x h)
    uint32_t* Ks  = sm + K_OFF;     // [64 kv][68] (kv x h)
    uint32_t* Vts = sm + V_OFF;     // [64 h][68]  (h x kv)
    uint32_t* Ps  = sm + P_OFF;     // [128 q][68] (q x kv)
    float* sm_m = reinterpret_cast<float*>(sm + MS_OFF);
    float* sm_l = reinterpret_cast<float*>(sm + LS_OFF);
    float* Psf  = reinterpret_cast<float*>(Ps);

    const int b    = blockIdx.y;
    const int q0   = blockIdx.x * 128;
    const int tid  = threadIdx.x;
    const int w    = tid >> 5;
    const int lane = tid & 31;
    const int g    = lane >> 2;
    const int t    = lane & 3;
    const int mw   = w >> 1;            // 0..3 : 32 q rows
    const int nw   = w & 1;             // 0..1 : kv half
    const size_t base = (size_t)b * S_ * QKV_;

    const uint32_t Qb = smem_u32(Qs);
    const uint32_t Kb = smem_u32(Ks);
    const uint32_t Vb = smem_u32(Vts);
    const uint32_t Pb = smem_u32(Ps);

    // ldmatrix per-lane offsets (words)
    const int aoffQ0 = (mw * 32 + (lane & 15)) * 68 + (lane >> 4) * 4;
    const int aoffQ1 = aoffQ0 + 16 * 68;
    const int boffK  = (nw * 32 + (lane & 7)) * 68 + ((lane >> 3) & 1) * 4;
    const int aoffP0 = aoffQ0 + nw * 32;
    const int aoffP1 = aoffQ1 + nw * 32;
    const int boffV  = (lane & 7) * 68 + nw * 32 + ((lane >> 3) & 1) * 4;

    // Load Q (scaled), coalesced, f2tf, float4 STS.
#pragma unroll
    for (int i = 0; i < 8; i++) {
        int lin = i * 256 + tid;
        int r = lin >> 4, c4 = lin & 15;
        float4 v = *reinterpret_cast<const float4*>(
            &g_qkv[base + (size_t)(q0 + r) * QKV_ + c4 * 4]);
        v.x *= 0.125f; v.y *= 0.125f; v.z *= 0.125f; v.w *= 0.125f;
        *reinterpret_cast<uint4*>(&Qs[r * 68 + c4 * 4]) = cvt4(v);
    }

    float oacc[2][8][4];
#pragma unroll
    for (int mt = 0; mt < 2; mt++)
#pragma unroll
        for (int n = 0; n < 8; n++)
#pragma unroll
            for (int j = 0; j < 4; j++) oacc[mt][n][j] = 0.0f;
    float m_r[2][2], l_r[2][2];
#pragma unroll
    for (int mt = 0; mt < 2; mt++) {
        m_r[mt][0] = -1e30f; m_r[mt][1] = -1e30f;
        l_r[mt][0] = 0.0f;   l_r[mt][1] = 0.0f;
    }

    // prefetch tile 0 into regs
    float4 kreg[4], vreg[4];
    {
        const int kv0 = 0;
#pragma unroll
        for (int i = 0; i < 4; i++) {
            int lin = i * 256 + tid;
            int r = lin >> 4, c4 = lin & 15;
            kreg[i] = *reinterpret_cast<const float4*>(
                &g_qkv[base + (size_t)(kv0 + r) * QKV_ + H_ + c4 * 4]);
            int idx = i * 8 + w;
            int c4v = (idx & 7) * 2 + (lane >> 4);
            int rv  = (lane & 15) + 16 * (idx >> 3);
            vreg[i] = *reinterpret_cast<const float4*>(
                &g_qkv[base + (size_t)(kv0 + rv) * QKV_ + 2 * H_ + c4v * 4]);
        }
    }

    const int NT = S_ / 64;
    for (int kt = 0; kt < NT; kt++) {
        __syncthreads();   // previous tile consumers done
        // STS K natural, V transposed
#pragma unroll
        for (int i = 0; i < 4; i++) {
            int lin = i * 256 + tid;
            int r = lin >> 4, c4 = lin & 15;
            *reinterpret_cast<uint4*>(&Ks[r * 68 + c4 * 4]) = cvt4(kreg[i]);
            int idx = i * 8 + w;
            int c4v = (idx & 7) * 2 + (lane >> 4);
            int rv  = (lane & 15) + 16 * (idx >> 3);
            Vts[(c4v * 4 + 0) * 68 + rv] = f2tf(vreg[i].x);
            Vts[(c4v * 4 + 1) * 68 + rv] = f2tf(vreg[i].y);
            Vts[(c4v * 4 + 2) * 68 + rv] = f2tf(vreg[i].z);
            Vts[(c4v * 4 + 3) * 68 + rv] = f2tf(vreg[i].w);
        }
        __syncthreads();

        // prefetch next tile
        if (kt + 1 < NT) {
            const int kv0 = (kt + 1) * 64;
#pragma unroll
            for (int i = 0; i < 4; i++) {
                int lin = i * 256 + tid;
                int r = lin >> 4, c4 = lin & 15;
                kreg[i] = *reinterpret_cast<const float4*>(
                    &g_qkv[base + (size_t)(kv0 + r) * QKV_ + H_ + c4 * 4]);
                int idx = i * 8 + w;
                int c4v = (idx & 7) * 2 + (lane >> 4);
                int rv  = (lane & 15) + 16 * (idx >> 3);
                vreg[i] = *reinterpret_cast<const float4*>(
                    &g_qkv[base + (size_t)(kv0 + rv) * QKV_ + 2 * H_ + c4v * 4]);
            }
        }

        // S = Q K^T : warp tile 32(q) x 32(kv)
        float sacc[2][4][4];
#pragma unroll
        for (int mt = 0; mt < 2; mt++)
#pragma unroll
            for (int n = 0; n < 4; n++)
#pragma unroll
                for (int j = 0; j < 4; j++) sacc[mt][n][j] = 0.0f;

#pragma unroll
        for (int ko8 = 0; ko8 < 8; ko8++) {
            const int ko = ko8 * 8;
            uint32_t a[2][4];
            ldsm_x4(a[0], Qb + 4u * (aoffQ0 + ko));
            ldsm_x4(a[1], Qb + 4u * (aoffQ1 + ko));
#pragma unroll
            for (int n = 0; n < 4; n++) {
                uint32_t bb[2];
                ldsm_x2(bb, Kb + 4u * (boffK + n * 8 * 68 + ko));
                mma_tf32(sacc[0][n], a[0], bb);
                mma_tf32(sacc[1][n], a[1], bb);
            }
        }

        // online softmax per mt, rows (r0, r0+8) over this warp's kv half
#pragma unroll
        for (int mt = 0; mt < 2; mt++) {
            float m0 = -1e30f, m1 = -1e30f;
#pragma unroll
            for (int n = 0; n < 4; n++) {
                m0 = fmaxf(m0, fmaxf(sacc[mt][n][0], sacc[mt][n][1]));
                m1 = fmaxf(m1, fmaxf(sacc[mt][n][2], sacc[mt][n][3]));
            }
            m0 = fmaxf(m0, __shfl_xor_sync(0xffffffffu, m0, 1));
            m0 = fmaxf(m0, __shfl_xor_sync(0xffffffffu, m0, 2));
            m1 = fmaxf(m1, __shfl_xor_sync(0xffffffffu, m1, 1));
            m1 = fmaxf(m1, __shfl_xor_sync(0xffffffffu, m1, 2));
            float mn0 = fmaxf(m_r[mt][0], m0);
            float mn1 = fmaxf(m_r[mt][1], m1);
            float al0 = __expf(m_r[mt][0] - mn0);
            float al1 = __expf(m_r[mt][1] - mn1);
            m_r[mt][0] = mn0; m_r[mt][1] = mn1;

            float s0 = 0.0f, s1 = 0.0f;
#pragma unroll
            for (int n = 0; n < 4; n++) {
                sacc[mt][n][0] = __expf(sacc[mt][n][0] - mn0);
                sacc[mt][n][1] = __expf(sacc[mt][n][1] - mn0);
                sacc[mt][n][2] = __expf(sacc[mt][n][2] - mn1);
                sacc[mt][n][3] = __expf(sacc[mt][n][3] - mn1);
                s0 += sacc[mt][n][0] + sacc[mt][n][1];
                s1 += sacc[mt][n][2] + sacc[mt][n][3];
            }
            s0 += __shfl_xor_sync(0xffffffffu, s0, 1);
            s0 += __shfl_xor_sync(0xffffffffu, s0, 2);
            s1 += __shfl_xor_sync(0xffffffffu, s1, 1);
            s1 += __shfl_xor_sync(0xffffffffu, s1, 2);
            l_r[mt][0] = l_r[mt][0] * al0 + s0;
            l_r[mt][1] = l_r[mt][1] * al1 + s1;
#pragma unroll
            for (int n = 0; n < 8; n++) {
                oacc[mt][n][0] *= al0;
                oacc[mt][n][1] *= al0;
                oacc[mt][n][2] *= al1;
                oacc[mt][n][3] *= al1;
            }
            // write P (warp-private rows x cols)
            int r0 = mw * 32 + mt * 16 + g;
            int cb = nw * 32 + 2 * t;
#pragma unroll
            for (int n = 0; n < 4; n++) {
                Ps[r0 * 68 + cb + 8 * n]           = f2tf(sacc[mt][n][0]);
                Ps[r0 * 68 + cb + 8 * n + 1]       = f2tf(sacc[mt][n][1]);
                Ps[(r0 + 8) * 68 + cb + 8 * n]     = f2tf(sacc[mt][n][2]);
                Ps[(r0 + 8) * 68 + cb + 8 * n + 1] = f2tf(sacc[mt][n][3]);
            }
        }
        __syncwarp();

        // O += P V : warp tile 32(q) x 64(h), k = its 32 kv
#pragma unroll
        for (int ko8 = 0; ko8 < 4; ko8++) {
            const int ko = ko8 * 8;
            uint32_t a[2][4];
            ldsm_x4(a[0], Pb + 4u * (aoffP0 + ko));
            ldsm_x4(a[1], Pb + 4u * (aoffP1 + ko));
#pragma unroll
            for (int n = 0; n < 8; n++) {
                uint32_t bb[2];
                ldsm_x2(bb, Vb + 4u * (boffV + n * 8 * 68 + ko));
                mma_tf32(oacc[0][n], a[0], bb);
                mma_tf32(oacc[1][n], a[1], bb);
            }
        }
    }

    // ---- merge kv halves ----
    __syncthreads();
    if (nw == 1) {
#pragma unroll
        for (int mt = 0; mt < 2; mt++) {
            int r0 = mw * 32 + mt * 16 + g;
#pragma unroll
            for (int n = 0; n < 8; n++) {
                int col = 8 * n + 2 * t;
                Psf[r0 * 68 + col]           = oacc[mt][n][0];
                Psf[r0 * 68 + col + 1]       = oacc[mt][n][1];
                Psf[(r0 + 8) * 68 + col]     = oacc[mt][n][2];
                Psf[(r0 + 8) * 68 + col + 1] = oacc[mt][n][3];
            }
            if (t == 0) {
                sm_m[r0] = m_r[mt][0]; sm_l[r0] = l_r[mt][0];
                sm_m[r0 + 8] = m_r[mt][1]; sm_l[r0 + 8] = l_r[mt][1];
            }
        }
    }
    __syncthreads();
    if (nw == 0) {
#pragma unroll
        for (int mt = 0; mt < 2; mt++) {
            int r0 = mw * 32 + mt * 16 + g;
#pragma unroll
            for (int half = 0; half < 2; half++) {
                int row = r0 + 8 * half;
                float mA = m_r[mt][half], lA = l_r[mt][half];
                float mB = sm_m[row],     lB = sm_l[row];
                float mm = fmaxf(mA, mB);
                float fA = __expf(mA - mm), fB = __expf(mB - mm);
                float inv = 1.0f / (lA * fA + lB * fB);
                fA *= inv; fB *= inv;
                size_t orow = (size_t)b * S_ + q0 + row;
#pragma unroll
                for (int n = 0; n < 8; n++) {
                    int col = 8 * n + 2 * t;
                    float x0 = oacc[mt][n][2 * half]     * fA + Psf[row * 68 + col]     * fB;
                    float x1 = oacc[mt][n][2 * half + 1] * fA + Psf[row * 68 + col + 1] * fB;
                    *reinterpret_cast<float2*>(&g_ctx[orow * H_ + col]) =
                        make_float2(x0, x1);
                }
            }
        }
    }
}

// ---------------------------------------------------------------------------
// Kernel 3: out projection. out[16384,1024] = ctx[16384,64] @ W_out[64,1024] + b
// BM=128, BN=128, K=64 single pass, ldmatrix A fragments.
// ---------------------------------------------------------------------------
#define OUT_SMEM_WORDS (128 * 68 + 64 * 136)

__global__ __launch_bounds__(256) void out_kernel(const float* __restrict__ W,
                                                  const float* __restrict__ bias,
                                                  float* __restrict__ out) {
    extern __shared__ uint32_t sm2[];
    uint32_t* Cs  = sm2;                 // [128][68] (m x k)
    uint32_t* Ws2 = sm2 + 128 * 68;      // [64][136] (k x n)

    const int m0   = blockIdx.y * 128;
    const int n0   = blockIdx.x * 128;
    const int tid  = threadIdx.x;
    const int w    = tid >> 5;
    const int lane = tid & 31;
    const int g    = lane >> 2;
    const int t    = lane & 3;
    const int mw   = w >> 1;
    const int nw   = w & 1;

    const uint32_t Cb = smem_u32(Cs);
    const int aoff0 = (mw * 32 + (lane & 15)) * 68 + (lane >> 4) * 4;
    const int aoff1 = aoff0 + 16 * 68;

    // ctx tile, coalesced (16 float4 per row)
#pragma unroll
    for (int i = 0; i < 8; i++) {
        int lin = i * 256 + tid;
        int r = lin >> 4, c4 = lin & 15;
        float4 v = *reinterpret_cast<const float4*>(
            &g_ctx[(size_t)(m0 + r) * H_ + c4 * 4]);
        *reinterpret_cast<uint4*>(&Cs[r * 68 + c4 * 4]) = cvt4(v);
    }
    // W tile natural [k][n]
#pragma unroll
    for (int i = 0; i < 8; i++) {
        int lin = i * 256 + tid;
        int r = lin >> 5, c4 = lin & 31;
        float4 v = *reinterpret_cast<const float4*>(
            &W[(size_t)r * E_ + n0 + c4 * 4]);
        *reinterpret_cast<uint4*>(&Ws2[r * 136 + c4 * 4]) = cvt4(v);
    }
    __syncthreads();

    float acc[2][8][4];
#pragma unroll
    for (int mt = 0; mt < 2; mt++)
#pragma unroll
        for (int n = 0; n < 8; n++)
#pragma unroll
            for (int j = 0; j < 4; j++) acc[mt][n][j] = 0.0f;

#pragma unroll
    for (int ko8 = 0; ko8 < 8; ko8++) {
        const int ko = ko8 * 8;
        uint32_t a[2][4];
        ldsm_x4(a[0], Cb + 4u * (aoff0 + ko));
        ldsm_x4(a[1], Cb + 4u * (aoff1 + ko));
#pragma unroll
        for (int n = 0; n < 8; n++) {
            uint32_t bb[2];
            int nc = nw * 64 + 8 * n + g;
            bb[0] = Ws2[(ko + t) * 136 + nc];
            bb[1] = Ws2[(ko + t + 4) * 136 + nc];
            mma_tf32(acc[0][n], a[0], bb);
            mma_tf32(acc[1][n], a[1], bb);
        }
    }

#pragma unroll
    for (int n = 0; n < 8; n++) {
        int col = n0 + nw * 64 + 8 * n + 2 * t;
        float b0 = bias[col], b1 = bias[col + 1];
#pragma unroll
        for (int mt = 0; mt < 2; mt++) {
            int row = m0 + mw * 32 + mt * 16 + g;
            float2 v0 = make_float2(acc[mt][n][0] + b0, acc[mt][n][1] + b1);
            *reinterpret_cast<float2*>(&out[(size_t)row * E_ + col]) = v0;
            float2 v1 = make_float2(acc[mt][n][2] + b0, acc[mt][n][3] + b1);
            *reinterpret_cast<float2*>(&out[(size_t)(row + 8) * E_ + col]) = v1;
        }
    }
}

// ---------------------------------------------------------------------------
extern "C" void kernel_launch(void* const* d_in, const int* in_sizes, int n_in,
                              void* d_out, int out_size) {
    const float* x     = (const float*)d_in[0];
    const float* W_qkv = (const float*)d_in[1];
    const float* b_qkv = (const float*)d_in[2];
    const float* W_out = (const float*)d_in[3];
    const float* b_out = (const float*)d_in[4];
    float* out = (float*)d_out;

    qkv_kernel<<<M_TOT / 128, 256>>>(x, W_qkv, b_qkv);

    {
        size_t smem = ATTN_SMEM_WORDS * sizeof(uint32_t);   // ~105 KB
        cudaFuncSetAttribute(attn_kernel,
                             cudaFuncAttributeMaxDynamicSharedMemorySize,
                             (int)smem);
        dim3 grid(S_ / 128, B_);
        attn_kernel<<<grid, 256, smem>>>();
    }
    {
        size_t smem = OUT_SMEM_WORDS * sizeof(uint32_t);    // ~70 KB
        cudaFuncSetAttribute(out_kernel,
                             cudaFuncAttributeMaxDynamicSharedMemorySize,
                             (int)smem);
        dim3 grid(E_ / 128, M_TOT / 128);
        out_kernel<<<grid, 256, smem>>>(W_out, b_out, out);
    }
}

// round 6
// speedup vs baseline: 3.5856x; 1.0001x over previous
#include <cuda_runtime.h>
#include <stdint.h>
#include <math.h>

#define B_    4
#define S_    4096
#define E_    1024
#define H_    64
#define QKV_  192
#define M_TOT (B_ * S_)   // 16384

__device__ float g_qkv[B_ * S_ * QKV_];   // [16384, 192]
__device__ float g_ctx[B_ * S_ * H_];     // [16384, 64]

// ---------------------------------------------------------------------------
// helpers
// ---------------------------------------------------------------------------
__device__ __forceinline__ uint32_t f2tf(float f) {
    uint32_t u;
    asm("cvt.rna.tf32.f32 %0, %1;" : "=r"(u) : "f"(f));
    return u;
}
__device__ __forceinline__ uint4 cvt4(float4 v) {
    uint4 u;
    u.x = f2tf(v.x); u.y = f2tf(v.y); u.z = f2tf(v.z); u.w = f2tf(v.w);
    return u;
}
__device__ __forceinline__ void mma_tf32(float d[4], const uint32_t a[4],
                                         const uint32_t b[2]) {
    asm volatile(
        "mma.sync.aligned.m16n8k8.row.col.f32.tf32.tf32.f32 "
        "{%0,%1,%2,%3},{%4,%5,%6,%7},{%8,%9},{%0,%1,%2,%3};\n"
        : "+f"(d[0]), "+f"(d[1]), "+f"(d[2]), "+f"(d[3])
        : "r"(a[0]), "r"(a[1]), "r"(a[2]), "r"(a[3]),
          "r"(b[0]), "r"(b[1]));
}
// tf32 fragment loads via b16 ldmatrix (1 row = 16B = 4 tf32).
__device__ __forceinline__ void ldsm_x4(uint32_t d[4], uint32_t saddr) {
    asm volatile("ldmatrix.sync.aligned.m8n8.x4.shared.b16 {%0,%1,%2,%3}, [%4];"
                 : "=r"(d[0]), "=r"(d[1]), "=r"(d[2]), "=r"(d[3]) : "r"(saddr));
}
__device__ __forceinline__ void ldsm_x2(uint32_t d[2], uint32_t saddr) {
    asm volatile("ldmatrix.sync.aligned.m8n8.x2.shared.b16 {%0,%1}, [%2];"
                 : "=r"(d[0]), "=r"(d[1]) : "r"(saddr));
}
__device__ __forceinline__ uint32_t smem_u32(const void* p) {
    return (uint32_t)__cvta_generic_to_shared(p);
}

// ---------------------------------------------------------------------------
// Kernel 1: QKV projection. C[16384,192] = x[16384,1024] @ W[1024,192] + b
// BM=128, BN=192, BK=32, 8 warps (4x2), warp tile 32x96. LDG prefetch + ldmatrix A.
// ---------------------------------------------------------------------------
__global__ __launch_bounds__(256) void qkv_kernel(const float* __restrict__ A,
                                                  const float* __restrict__ W,
                                                  const float* __restrict__ bias) {
    __shared__ uint32_t As[128 * 36];   // [m][k] stride 36
    __shared__ uint32_t Ws[32 * 200];   // [k][n] stride 200

    const int m0   = blockIdx.x * 128;
    const int tid  = threadIdx.x;
    const int w    = tid >> 5;
    const int lane = tid & 31;
    const int g    = lane >> 2;
    const int t    = lane & 3;
    const int mw   = w >> 1;
    const int nw   = w & 1;

    const uint32_t Ab = smem_u32(As);
    // per-lane ldmatrix offsets (words) for A fragments, mt = 0/1
    const int aoff0 = (mw * 32 + (lane & 15)) * 36 + (lane >> 4) * 4;
    const int aoff1 = aoff0 + 16 * 36;

    float acc[2][12][4];
#pragma unroll
    for (int mt = 0; mt < 2; mt++)
#pragma unroll
        for (int n = 0; n < 12; n++)
#pragma unroll
            for (int j = 0; j < 4; j++) acc[mt][n][j] = 0.0f;

    float4 areg[4], wreg[6];
    // prefetch k0 = 0 (coalesced: 8 consecutive lanes per row)
#pragma unroll
    for (int i = 0; i < 4; i++) {
        int lin = i * 256 + tid;
        int r = lin >> 3, c4 = lin & 7;
        areg[i] = *reinterpret_cast<const float4*>(&A[(size_t)(m0 + r) * E_ + c4 * 4]);
    }
#pragma unroll
    for (int i = 0; i < 6; i++) {
        int lin = i * 256 + tid;
        int r = lin / 48, c = lin % 48;
        wreg[i] = *reinterpret_cast<const float4*>(&W[(size_t)r * QKV_ + c * 4]);
    }

    for (int k0 = 0; k0 < E_; k0 += 32) {
        __syncthreads();
#pragma unroll
        for (int i = 0; i < 4; i++) {
            int lin = i * 256 + tid;
            int r = lin >> 3, c4 = lin & 7;
            *reinterpret_cast<uint4*>(&As[r * 36 + c4 * 4]) = cvt4(areg[i]);
        }
#pragma unroll
        for (int i = 0; i < 6; i++) {
            int lin = i * 256 + tid;
            int r = lin / 48, c = lin % 48;
            *reinterpret_cast<uint4*>(&Ws[r * 200 + c * 4]) = cvt4(wreg[i]);
        }
        __syncthreads();

        if (k0 + 32 < E_) {
#pragma unroll
            for (int i = 0; i < 4; i++) {
                int lin = i * 256 + tid;
                int r = lin >> 3, c4 = lin & 7;
                areg[i] = *reinterpret_cast<const float4*>(
                    &A[(size_t)(m0 + r) * E_ + k0 + 32 + c4 * 4]);
            }
#pragma unroll
            for (int i = 0; i < 6; i++) {
                int lin = i * 256 + tid;
                int r = lin / 48, c = lin % 48;
                wreg[i] = *reinterpret_cast<const float4*>(
                    &W[(size_t)(k0 + 32 + r) * QKV_ + c * 4]);
            }
        }

#pragma unroll
        for (int ko8 = 0; ko8 < 4; ko8++) {
            const int ko = ko8 * 8;
            uint32_t a[2][4];
            ldsm_x4(a[0], Ab + 4u * (aoff0 + ko));
            ldsm_x4(a[1], Ab + 4u * (aoff1 + ko));
#pragma unroll
            for (int n = 0; n < 12; n++) {
                uint32_t b[2];
                int nc = nw * 96 + 8 * n + g;
                b[0] = Ws[(ko + t) * 200 + nc];
                b[1] = Ws[(ko + t + 4) * 200 + nc];
                mma_tf32(acc[0][n], a[0], b);
                mma_tf32(acc[1][n], a[1], b);
            }
        }
    }

#pragma unroll
    for (int n = 0; n < 12; n++) {
        int col = nw * 96 + 8 * n + 2 * t;
        float b0 = bias[col], b1 = bias[col + 1];
#pragma unroll
        for (int mt = 0; mt < 2; mt++) {
            int row = m0 + mw * 32 + mt * 16 + g;
            float2 v0 = make_float2(acc[mt][n][0] + b0, acc[mt][n][1] + b1);
            *reinterpret_cast<float2*>(&g_qkv[(size_t)row * QKV_ + col]) = v0;
            float2 v1 = make_float2(acc[mt][n][2] + b0, acc[mt][n][3] + b1);
            *reinterpret_cast<float2*>(&g_qkv[(size_t)(row + 8) * QKV_ + col]) = v1;
        }
    }
}

// ---------------------------------------------------------------------------
// Kernel 2: flash attention. BQ=128, BK=64. 8 warps = 4(m=32) x 2(kv-half).
// Per-warp online softmax over its kv half; final cross-warp merge.
// ---------------------------------------------------------------------------
#define Q_OFF 0
#define K_OFF (128 * 68)
#define V_OFF (K_OFF + 64 * 68)
#define P_OFF (V_OFF + 64 * 68)
#define MS_OFF (P_OFF + 128 * 68)
#define LS_OFF (MS_OFF + 128)
#define ATTN_SMEM_WORDS (LS_OFF + 128)

__global__ __launch_bounds__(256) void attn_kernel() {
    extern __shared__ uint32_t sm[];
    uint32_t* Qs  = sm + Q_OFF;     // [128 q][68] (q x h)
    uint32_t* Ks  = sm + K_OFF;     // [64 kv][68] (kv x h)
    uint32_t* Vts = sm + V_OFF;     // [64 h][68]  (h x kv)
    uint32_t* Ps  = sm + P_OFF;     // [128 q][68] (q x kv)
    float* sm_m = reinterpret_cast<float*>(sm + MS_OFF);
    float* sm_l = reinterpret_cast<float*>(sm + LS_OFF);
    float* Psf  = reinterpret_cast<float*>(Ps);

    const int b    = blockIdx.y;
    const int q0   = blockIdx.x * 128;
    const int tid  = threadIdx.x;
    const int w    = tid >> 5;
    const int lane = tid & 31;
    const int g    = lane >> 2;
    const int t    = lane & 3;
    const int mw   = w >> 1;            // 0..3 : 32 q rows
    const int nw   = w & 1;             // 0..1 : kv half
    const size_t base = (size_t)b * S_ * QKV_;

    const uint32_t Qb = smem_u32(Qs);
    const uint32_t Kb = smem_u32(Ks);
    const uint32_t Vb = smem_u32(Vts);
    const uint32_t Pb = smem_u32(Ps);

    // ldmatrix per-lane offsets (words)
    const int aoffQ0 = (mw * 32 + (lane & 15)) * 68 + (lane >> 4) * 4;
    const int aoffQ1 = aoffQ0 + 16 * 68;
    const int boffK  = (nw * 32 + (lane & 7)) * 68 + ((lane >> 3) & 1) * 4;
    const int aoffP0 = aoffQ0 + nw * 32;
    const int aoffP1 = aoffQ1 + nw * 32;
    const int boffV  = (lane & 7) * 68 + nw * 32 + ((lane >> 3) & 1) * 4;

    // Load Q (scaled), coalesced, f2tf, float4 STS.
#pragma unroll
    for (int i = 0; i < 8; i++) {
        int lin = i * 256 + tid;
        int r = lin >> 4, c4 = lin & 15;
        float4 v = *reinterpret_cast<const float4*>(
            &g_qkv[base + (size_t)(q0 + r) * QKV_ + c4 * 4]);
        v.x *= 0.125f; v.y *= 0.125f; v.z *= 0.125f; v.w *= 0.125f;
        *reinterpret_cast<uint4*>(&Qs[r * 68 + c4 * 4]) = cvt4(v);
    }

    float oacc[2][8][4];
#pragma unroll
    for (int mt = 0; mt < 2; mt++)
#pragma unroll
        for (int n = 0; n < 8; n++)
#pragma unroll
            for (int j = 0; j < 4; j++) oacc[mt][n][j] = 0.0f;
    float m_r[2][2], l_r[2][2];
#pragma unroll
    for (int mt = 0; mt < 2; mt++) {
        m_r[mt][0] = -1e30f; m_r[mt][1] = -1e30f;
        l_r[mt][0] = 0.0f;   l_r[mt][1] = 0.0f;
    }

    // prefetch tile 0 into regs
    float4 kreg[4], vreg[4];
    {
        const int kv0 = 0;
#pragma unroll
        for (int i = 0; i < 4; i++) {
            int lin = i * 256 + tid;
            int r = lin >> 4, c4 = lin & 15;
            kreg[i] = *reinterpret_cast<const float4*>(
                &g_qkv[base + (size_t)(kv0 + r) * QKV_ + H_ + c4 * 4]);
            int idx = i * 8 + w;
            int c4v = (idx & 7) * 2 + (lane >> 4);
            int rv  = (lane & 15) + 16 * (idx >> 3);
            vreg[i] = *reinterpret_cast<const float4*>(
                &g_qkv[base + (size_t)(kv0 + rv) * QKV_ + 2 * H_ + c4v * 4]);
        }
    }

    const int NT = S_ / 64;
    for (int kt = 0; kt < NT; kt++) {
        __syncthreads();   // previous tile consumers done
        // STS K natural, V transposed
#pragma unroll
        for (int i = 0; i < 4; i++) {
            int lin = i * 256 + tid;
            int r = lin >> 4, c4 = lin & 15;
            *reinterpret_cast<uint4*>(&Ks[r * 68 + c4 * 4]) = cvt4(kreg[i]);
            int idx = i * 8 + w;
            int c4v = (idx & 7) * 2 + (lane >> 4);
            int rv  = (lane & 15) + 16 * (idx >> 3);
            Vts[(c4v * 4 + 0) * 68 + rv] = f2tf(vreg[i].x);
            Vts[(c4v * 4 + 1) * 68 + rv] = f2tf(vreg[i].y);
            Vts[(c4v * 4 + 2) * 68 + rv] = f2tf(vreg[i].z);
            Vts[(c4v * 4 + 3) * 68 + rv] = f2tf(vreg[i].w);
        }
        __syncthreads();

        // prefetch next tile
        if (kt + 1 < NT) {
            const int kv0 = (kt + 1) * 64;
#pragma unroll
            for (int i = 0; i < 4; i++) {
                int lin = i * 256 + tid;
                int r = lin >> 4, c4 = lin & 15;
                kreg[i] = *reinterpret_cast<const float4*>(
                    &g_qkv[base + (size_t)(kv0 + r) * QKV_ + H_ + c4 * 4]);
                int idx = i * 8 + w;
                int c4v = (idx & 7) * 2 + (lane >> 4);
                int rv  = (lane & 15) + 16 * (idx >> 3);
                vreg[i] = *reinterpret_cast<const float4*>(
                    &g_qkv[base + (size_t)(kv0 + rv) * QKV_ + 2 * H_ + c4v * 4]);
            }
        }

        // S = Q K^T : warp tile 32(q) x 32(kv)
        float sacc[2][4][4];
#pragma unroll
        for (int mt = 0; mt < 2; mt++)
#pragma unroll
            for (int n = 0; n < 4; n++)
#pragma unroll
                for (int j = 0; j < 4; j++) sacc[mt][n][j] = 0.0f;

#pragma unroll
        for (int ko8 = 0; ko8 < 8; ko8++) {
            const int ko = ko8 * 8;
            uint32_t a[2][4];
            ldsm_x4(a[0], Qb + 4u * (aoffQ0 + ko));
            ldsm_x4(a[1], Qb + 4u * (aoffQ1 + ko));
#pragma unroll
            for (int n = 0; n < 4; n++) {
                uint32_t bb[2];
                ldsm_x2(bb, Kb + 4u * (boffK + n * 8 * 68 + ko));
                mma_tf32(sacc[0][n], a[0], bb);
                mma_tf32(sacc[1][n], a[1], bb);
            }
        }

        // online softmax per mt, rows (r0, r0+8) over this warp's kv half
#pragma unroll
        for (int mt = 0; mt < 2; mt++) {
            float m0 = -1e30f, m1 = -1e30f;
#pragma unroll
            for (int n = 0; n < 4; n++) {
                m0 = fmaxf(m0, fmaxf(sacc[mt][n][0], sacc[mt][n][1]));
                m1 = fmaxf(m1, fmaxf(sacc[mt][n][2], sacc[mt][n][3]));
            }
            m0 = fmaxf(m0, __shfl_xor_sync(0xffffffffu, m0, 1));
            m0 = fmaxf(m0, __shfl_xor_sync(0xffffffffu, m0, 2));
            m1 = fmaxf(m1, __shfl_xor_sync(0xffffffffu, m1, 1));
            m1 = fmaxf(m1, __shfl_xor_sync(0xffffffffu, m1, 2));
            float mn0 = fmaxf(m_r[mt][0], m0);
            float mn1 = fmaxf(m_r[mt][1], m1);
            float al0 = __expf(m_r[mt][0] - mn0);
            float al1 = __expf(m_r[mt][1] - mn1);
            m_r[mt][0] = mn0; m_r[mt][1] = mn1;

            float s0 = 0.0f, s1 = 0.0f;
#pragma unroll
            for (int n = 0; n < 4; n++) {
                sacc[mt][n][0] = __expf(sacc[mt][n][0] - mn0);
                sacc[mt][n][1] = __expf(sacc[mt][n][1] - mn0);
                sacc[mt][n][2] = __expf(sacc[mt][n][2] - mn1);
                sacc[mt][n][3] = __expf(sacc[mt][n][3] - mn1);
                s0 += sacc[mt][n][0] + sacc[mt][n][1];
                s1 += sacc[mt][n][2] + sacc[mt][n][3];
            }
            s0 += __shfl_xor_sync(0xffffffffu, s0, 1);
            s0 += __shfl_xor_sync(0xffffffffu, s0, 2);
            s1 += __shfl_xor_sync(0xffffffffu, s1, 1);
            s1 += __shfl_xor_sync(0xffffffffu, s1, 2);
            l_r[mt][0] = l_r[mt][0] * al0 + s0;
            l_r[mt][1] = l_r[mt][1] * al1 + s1;
#pragma unroll
            for (int n = 0; n < 8; n++) {
                oacc[mt][n][0] *= al0;
                oacc[mt][n][1] *= al0;
                oacc[mt][n][2] *= al1;
                oacc[mt][n][3] *= al1;
            }
            // write P (warp-private rows x cols)
            int r0 = mw * 32 + mt * 16 + g;
            int cb = nw * 32 + 2 * t;
#pragma unroll
            for (int n = 0; n < 4; n++) {
                Ps[r0 * 68 + cb + 8 * n]           = f2tf(sacc[mt][n][0]);
                Ps[r0 * 68 + cb + 8 * n + 1]       = f2tf(sacc[mt][n][1]);
                Ps[(r0 + 8) * 68 + cb + 8 * n]     = f2tf(sacc[mt][n][2]);
                Ps[(r0 + 8) * 68 + cb + 8 * n + 1] = f2tf(sacc[mt][n][3]);
            }
        }
        __syncwarp();

        // O += P V : warp tile 32(q) x 64(h), k = its 32 kv
#pragma unroll
        for (int ko8 = 0; ko8 < 4; ko8++) {
            const int ko = ko8 * 8;
            uint32_t a[2][4];
            ldsm_x4(a[0], Pb + 4u * (aoffP0 + ko));
            ldsm_x4(a[1], Pb + 4u * (aoffP1 + ko));
#pragma unroll
            for (int n = 0; n < 8; n++) {
                uint32_t bb[2];
                ldsm_x2(bb, Vb + 4u * (boffV + n * 8 * 68 + ko));
                mma_tf32(oacc[0][n], a[0], bb);
                mma_tf32(oacc[1][n], a[1], bb);
            }
        }
    }

    // ---- merge kv halves ----
    __syncthreads();
    if (nw == 1) {
#pragma unroll
        for (int mt = 0; mt < 2; mt++) {
            int r0 = mw * 32 + mt * 16 + g;
#pragma unroll
            for (int n = 0; n < 8; n++) {
                int col = 8 * n + 2 * t;
                Psf[r0 * 68 + col]           = oacc[mt][n][0];
                Psf[r0 * 68 + col + 1]       = oacc[mt][n][1];
                Psf[(r0 + 8) * 68 + col]     = oacc[mt][n][2];
                Psf[(r0 + 8) * 68 + col + 1] = oacc[mt][n][3];
            }
            if (t == 0) {
                sm_m[r0] = m_r[mt][0]; sm_l[r0] = l_r[mt][0];
                sm_m[r0 + 8] = m_r[mt][1]; sm_l[r0 + 8] = l_r[mt][1];
            }
        }
    }
    __syncthreads();
    if (nw == 0) {
#pragma unroll
        for (int mt = 0; mt < 2; mt++) {
            int r0 = mw * 32 + mt * 16 + g;
#pragma unroll
            for (int half = 0; half < 2; half++) {
                int row = r0 + 8 * half;
                float mA = m_r[mt][half], lA = l_r[mt][half];
                float mB = sm_m[row],     lB = sm_l[row];
                float mm = fmaxf(mA, mB);
                float fA = __expf(mA - mm), fB = __expf(mB - mm);
                float inv = 1.0f / (lA * fA + lB * fB);
                fA *= inv; fB *= inv;
                size_t orow = (size_t)b * S_ + q0 + row;
#pragma unroll
                for (int n = 0; n < 8; n++) {
                    int col = 8 * n + 2 * t;
                    float x0 = oacc[mt][n][2 * half]     * fA + Psf[row * 68 + col]     * fB;
                    float x1 = oacc[mt][n][2 * half + 1] * fA + Psf[row * 68 + col + 1] * fB;
                    *reinterpret_cast<float2*>(&g_ctx[orow * H_ + col]) =
                        make_float2(x0, x1);
                }
            }
        }
    }
}

// ---------------------------------------------------------------------------
// Kernel 3: out projection. out[16384,1024] = ctx[16384,64] @ W_out[64,1024] + b
// BM=128, BN=128, K=64 single pass, ldmatrix A fragments.
// ---------------------------------------------------------------------------
#define OUT_SMEM_WORDS (128 * 68 + 64 * 136)

__global__ __launch_bounds__(256) void out_kernel(const float* __restrict__ W,
                                                  const float* __restrict__ bias,
                                                  float* __restrict__ out) {
    extern __shared__ uint32_t sm2[];
    uint32_t* Cs  = sm2;                 // [128][68] (m x k)
    uint32_t* Ws2 = sm2 + 128 * 68;      // [64][136] (k x n)

    const int m0   = blockIdx.y * 128;
    const int n0   = blockIdx.x * 128;
    const int tid  = threadIdx.x;
    const int w    = tid >> 5;
    const int lane = tid & 31;
    const int g    = lane >> 2;
    const int t    = lane & 3;
    const int mw   = w >> 1;
    const int nw   = w & 1;

    const uint32_t Cb = smem_u32(Cs);
    const int aoff0 = (mw * 32 + (lane & 15)) * 68 + (lane >> 4) * 4;
    const int aoff1 = aoff0 + 16 * 68;

    // ctx tile, coalesced (16 float4 per row)
#pragma unroll
    for (int i = 0; i < 8; i++) {
        int lin = i * 256 + tid;
        int r = lin >> 4, c4 = lin & 15;
        float4 v = *reinterpret_cast<const float4*>(
            &g_ctx[(size_t)(m0 + r) * H_ + c4 * 4]);
        *reinterpret_cast<uint4*>(&Cs[r * 68 + c4 * 4]) = cvt4(v);
    }
    // W tile natural [k][n]
#pragma unroll
    for (int i = 0; i < 8; i++) {
        int lin = i * 256 + tid;
        int r = lin >> 5, c4 = lin & 31;
        float4 v = *reinterpret_cast<const float4*>(
            &W[(size_t)r * E_ + n0 + c4 * 4]);
        *reinterpret_cast<uint4*>(&Ws2[r * 136 + c4 * 4]) = cvt4(v);
    }
    __syncthreads();

    float acc[2][8][4];
#pragma unroll
    for (int mt = 0; mt < 2; mt++)
#pragma unroll
        for (int n = 0; n < 8; n++)
#pragma unroll
            for (int j = 0; j < 4; j++) acc[mt][n][j] = 0.0f;

#pragma unroll
    for (int ko8 = 0; ko8 < 8; ko8++) {
        const int ko = ko8 * 8;
        uint32_t a[2][4];
        ldsm_x4(a[0], Cb + 4u * (aoff0 + ko));
        ldsm_x4(a[1], Cb + 4u * (aoff1 + ko));
#pragma unroll
        for (int n = 0; n < 8; n++) {
            uint32_t bb[2];
            int nc = nw * 64 + 8 * n + g;
            bb[0] = Ws2[(ko + t) * 136 + nc];
            bb[1] = Ws2[(ko + t + 4) * 136 + nc];
            mma_tf32(acc[0][n], a[0], bb);
            mma_tf32(acc[1][n], a[1], bb);
        }
    }

#pragma unroll
    for (int n = 0; n < 8; n++) {
        int col = n0 + nw * 64 + 8 * n + 2 * t;
        float b0 = bias[col], b1 = bias[col + 1];
#pragma unroll
        for (int mt = 0; mt < 2; mt++) {
            int row = m0 + mw * 32 + mt * 16 + g;
            float2 v0 = make_float2(acc[mt][n][0] + b0, acc[mt][n][1] + b1);
            *reinterpret_cast<float2*>(&out[(size_t)row * E_ + col]) = v0;
            float2 v1 = make_float2(acc[mt][n][2] + b0, acc[mt][n][3] + b1);
            *reinterpret_cast<float2*>(&out[(size_t)(row + 8) * E_ + col]) = v1;
        }
    }
}

// ---------------------------------------------------------------------------
extern "C" void kernel_launch(void* const* d_in, const int* in_sizes, int n_in,
                              void* d_out, int out_size) {
    const float* x     = (const float*)d_in[0];
    const float* W_qkv = (const float*)d_in[1];
    const float* b_qkv = (const float*)d_in[2];
    const float* W_out = (const float*)d_in[3];
    const float* b_out = (const float*)d_in[4];
    float* out = (float*)d_out;

    qkv_kernel<<<M_TOT / 128, 256>>>(x, W_qkv, b_qkv);

    {
        size_t smem = ATTN_SMEM_WORDS * sizeof(uint32_t);   // ~105 KB
        cudaFuncSetAttribute(attn_kernel,
                             cudaFuncAttributeMaxDynamicSharedMemorySize,
                             (int)smem);
        dim3 grid(S_ / 128, B_);
        attn_kernel<<<grid, 256, smem>>>();
    }
    {
        size_t smem = OUT_SMEM_WORDS * sizeof(uint32_t);    // ~70 KB
        cudaFuncSetAttribute(out_kernel,
                             cudaFuncAttributeMaxDynamicSharedMemorySize,
                             (int)smem);
        dim3 grid(E_ / 128, M_TOT / 128);
        out_kernel<<<grid, 256, smem>>>(W_out, b_out, out);
    }
}

// round 7
// speedup vs baseline: 6.7658x; 1.8869x over previous
#include <cuda_runtime.h>
#include <cuda_fp16.h>
#include <stdint.h>
#include <math.h>

#define B_    4
#define S_    4096
#define E_    1024
#define H_    64
#define QKV_  192
#define M_TOT (B_ * S_)   // 16384

__device__ __half g_qkv[B_ * S_ * QKV_];   // [16384, 192] fp16 (q pre-scaled)
__device__ __half g_ctx[B_ * S_ * H_];     // [16384, 64]  fp16

// ---------------------------------------------------------------------------
// helpers
// ---------------------------------------------------------------------------
__device__ __forceinline__ uint32_t h2u(__half2 h) {
    return *reinterpret_cast<uint32_t*>(&h);
}
__device__ __forceinline__ uint2 f4h(float4 v) {
    uint2 u;
    u.x = h2u(__floats2half2_rn(v.x, v.y));
    u.y = h2u(__floats2half2_rn(v.z, v.w));
    return u;
}
// D += A(16x16) * B(16x8), fp16 in, fp32 accum
__device__ __forceinline__ void mma_f16(float d[4], const uint32_t a[4],
                                        const uint32_t b[2]) {
    asm volatile(
        "mma.sync.aligned.m16n8k16.row.col.f32.f16.f16.f32 "
        "{%0,%1,%2,%3},{%4,%5,%6,%7},{%8,%9},{%0,%1,%2,%3};\n"
        : "+f"(d[0]), "+f"(d[1]), "+f"(d[2]), "+f"(d[3])
        : "r"(a[0]), "r"(a[1]), "r"(a[2]), "r"(a[3]),
          "r"(b[0]), "r"(b[1]));
}
__device__ __forceinline__ void ldsm_x4(uint32_t d[4], uint32_t saddr) {
    asm volatile("ldmatrix.sync.aligned.m8n8.x4.shared.b16 {%0,%1,%2,%3}, [%4];"
                 : "=r"(d[0]), "=r"(d[1]), "=r"(d[2]), "=r"(d[3]) : "r"(saddr));
}
__device__ __forceinline__ void ldsm_x2(uint32_t d[2], uint32_t saddr) {
    asm volatile("ldmatrix.sync.aligned.m8n8.x2.shared.b16 {%0,%1}, [%2];"
                 : "=r"(d[0]), "=r"(d[1]) : "r"(saddr));
}
__device__ __forceinline__ void ldsm_x2_t(uint32_t d[2], uint32_t saddr) {
    asm volatile("ldmatrix.sync.aligned.m8n8.x2.trans.shared.b16 {%0,%1}, [%2];"
                 : "=r"(d[0]), "=r"(d[1]) : "r"(saddr));
}
__device__ __forceinline__ uint32_t smem_u32(const void* p) {
    return (uint32_t)__cvta_generic_to_shared(p);
}

// ---------------------------------------------------------------------------
// Kernel 1: QKV projection. C[16384,192] = x[16384,1024] @ W[1024,192] + b
// BM=128, BN=192, BK=32. 8 warps (4m x 2n), warp tile 32x96, fp16 MMA.
// ---------------------------------------------------------------------------
__global__ __launch_bounds__(256) void qkv_kernel(const float* __restrict__ A,
                                                  const float* __restrict__ W,
                                                  const float* __restrict__ bias) {
    __shared__ __half As[128 * 40];    // [m][k] stride 40 halves
    __shared__ __half Ws[32 * 200];    // [k][n] stride 200 halves (natural)

    const int m0   = blockIdx.x * 128;
    const int tid  = threadIdx.x;
    const int w    = tid >> 5;
    const int lane = tid & 31;
    const int g    = lane >> 2;
    const int t    = lane & 3;
    const int mw   = w >> 1;
    const int nw   = w & 1;

    const uint32_t Ab = smem_u32(As);
    const uint32_t Wb = smem_u32(Ws);
    // A-fragment ldmatrix byte offsets (per mt)
    const uint32_t aoff0 = 2u * ((mw * 32 + (lane & 15)) * 40 + (lane >> 4) * 8);
    const uint32_t aoff1 = aoff0 + 2u * (16 * 40);
    // B-fragment (trans) row part
    const uint32_t brow = (lane & 7) + ((lane >> 3) & 1) * 8;

    float acc[2][12][4];
#pragma unroll
    for (int mt = 0; mt < 2; mt++)
#pragma unroll
        for (int n = 0; n < 12; n++)
#pragma unroll
            for (int j = 0; j < 4; j++) acc[mt][n][j] = 0.0f;

    float4 areg[4], wreg[6];
#pragma unroll
    for (int i = 0; i < 4; i++) {
        int lin = i * 256 + tid;
        int r = lin >> 3, c4 = lin & 7;
        areg[i] = *reinterpret_cast<const float4*>(&A[(size_t)(m0 + r) * E_ + c4 * 4]);
    }
#pragma unroll
    for (int i = 0; i < 6; i++) {
        int lin = i * 256 + tid;
        int r = lin / 48, c = lin % 48;
        wreg[i] = *reinterpret_cast<const float4*>(&W[(size_t)r * QKV_ + c * 4]);
    }

    for (int k0 = 0; k0 < E_; k0 += 32) {
        __syncthreads();
#pragma unroll
        for (int i = 0; i < 4; i++) {
            int lin = i * 256 + tid;
            int r = lin >> 3, c4 = lin & 7;
            *reinterpret_cast<uint2*>(&As[r * 40 + c4 * 4]) = f4h(areg[i]);
        }
#pragma unroll
        for (int i = 0; i < 6; i++) {
            int lin = i * 256 + tid;
            int r = lin / 48, c = lin % 48;
            *reinterpret_cast<uint2*>(&Ws[r * 200 + c * 4]) = f4h(wreg[i]);
        }
        __syncthreads();

        if (k0 + 32 < E_) {
#pragma unroll
            for (int i = 0; i < 4; i++) {
                int lin = i * 256 + tid;
                int r = lin >> 3, c4 = lin & 7;
                areg[i] = *reinterpret_cast<const float4*>(
                    &A[(size_t)(m0 + r) * E_ + k0 + 32 + c4 * 4]);
            }
#pragma unroll
            for (int i = 0; i < 6; i++) {
                int lin = i * 256 + tid;
                int r = lin / 48, c = lin % 48;
                wreg[i] = *reinterpret_cast<const float4*>(
                    &W[(size_t)(k0 + 32 + r) * QKV_ + c * 4]);
            }
        }

#pragma unroll
        for (int ko16 = 0; ko16 < 2; ko16++) {
            const int ko = ko16 * 16;
            uint32_t a[2][4];
            ldsm_x4(a[0], Ab + aoff0 + 2u * ko);
            ldsm_x4(a[1], Ab + aoff1 + 2u * ko);
#pragma unroll
            for (int n = 0; n < 12; n++) {
                uint32_t b[2];
                int nc = nw * 96 + 8 * n;
                ldsm_x2_t(b, Wb + 2u * ((ko + brow) * 200 + nc));
                mma_f16(acc[0][n], a[0], b);
                mma_f16(acc[1][n], a[1], b);
            }
        }
    }

    // epilogue: bias, q-scale, fp16 store
#pragma unroll
    for (int n = 0; n < 12; n++) {
        int col = nw * 96 + 8 * n + 2 * t;
        float sc = (col < 64) ? 0.125f : 1.0f;
        float b0 = bias[col], b1 = bias[col + 1];
#pragma unroll
        for (int mt = 0; mt < 2; mt++) {
            int row = m0 + mw * 32 + mt * 16 + g;
            __half2 v0 = __floats2half2_rn((acc[mt][n][0] + b0) * sc,
                                           (acc[mt][n][1] + b1) * sc);
            *reinterpret_cast<uint32_t*>(&g_qkv[(size_t)row * QKV_ + col]) = h2u(v0);
            __half2 v1 = __floats2half2_rn((acc[mt][n][2] + b0) * sc,
                                           (acc[mt][n][3] + b1) * sc);
            *reinterpret_cast<uint32_t*>(&g_qkv[(size_t)(row + 8) * QKV_ + col]) = h2u(v1);
        }
    }
}

// ---------------------------------------------------------------------------
// Kernel 2: flash attention, fp16 MMA. BQ=128, BK=64. 8 warps = 4(m) x 2(kv).
// ---------------------------------------------------------------------------
// half-word offsets
#define Q_OFFH 0
#define K_OFFH (128 * 72)
#define V_OFFH (K_OFFH + 64 * 72)
#define P_OFFH (V_OFFH + 64 * 72)
#define ATTN_SMEM_HALVES (P_OFFH + 128 * 72)   // 27648 halves = 55296 B
// merge scratch (float words, overlaps Q/K/V after the loop)
#define OF_OFFW 0
#define MS_OFFW (128 * 68)
#define LS_OFFW (MS_OFFW + 128)

__global__ __launch_bounds__(256) void attn_kernel() {
    extern __shared__ __half smh[];
    __half* Qs = smh + Q_OFFH;      // [128 q][72]  (q x h)
    __half* Ks = smh + K_OFFH;      // [64 kv][72]  (kv x h)
    __half* Vs = smh + V_OFFH;      // [64 kv][72]  (kv x h)  natural
    __half* Ps = smh + P_OFFH;      // [128 q][72]  (q x kv)
    float* Of   = reinterpret_cast<float*>(smh) + OF_OFFW;
    float* sm_m = reinterpret_cast<float*>(smh) + MS_OFFW;
    float* sm_l = reinterpret_cast<float*>(smh) + LS_OFFW;

    const int b    = blockIdx.y;
    const int q0   = blockIdx.x * 128;
    const int tid  = threadIdx.x;
    const int w    = tid >> 5;
    const int lane = tid & 31;
    const int g    = lane >> 2;
    const int t    = lane & 3;
    const int mw   = w >> 1;        // 0..3 : 32 q rows
    const int nw   = w & 1;         // 0..1 : kv half
    const __half* qkv = g_qkv + (size_t)b * S_ * QKV_;

    const uint32_t Qb = smem_u32(Qs);
    const uint32_t Kb = smem_u32(Ks);
    const uint32_t Vb = smem_u32(Vs);
    const uint32_t Pb = smem_u32(Ps);

    const uint32_t brow = (lane & 7) + ((lane >> 3) & 1) * 8;
    const uint32_t aoffQ0 = 2u * ((mw * 32 + (lane & 15)) * 72 + (lane >> 4) * 8);
    const uint32_t aoffQ1 = aoffQ0 + 2u * (16 * 72);
    const uint32_t aoffP0 = aoffQ0 + 2u * (nw * 32);
    const uint32_t aoffP1 = aoffQ1 + 2u * (nw * 32);

    // Load Q (already scaled, fp16): 128 rows x 8 uint4
#pragma unroll
    for (int i = 0; i < 4; i++) {
        int lin = i * 256 + tid;
        int r = lin >> 3, c8 = lin & 7;
        uint4 v = *reinterpret_cast<const uint4*>(
            &qkv[(size_t)(q0 + r) * QKV_ + c8 * 8]);
        *reinterpret_cast<uint4*>(&Qs[r * 72 + c8 * 8]) = v;
    }

    float oacc[2][8][4];
#pragma unroll
    for (int mt = 0; mt < 2; mt++)
#pragma unroll
        for (int n = 0; n < 8; n++)
#pragma unroll
            for (int j = 0; j < 4; j++) oacc[mt][n][j] = 0.0f;
    float m_r[2][2], l_r[2][2];
#pragma unroll
    for (int mt = 0; mt < 2; mt++) {
        m_r[mt][0] = -1e30f; m_r[mt][1] = -1e30f;
        l_r[mt][0] = 0.0f;   l_r[mt][1] = 0.0f;
    }

    // prefetch tile 0
    uint4 kreg[2], vreg[2];
#pragma unroll
    for (int i = 0; i < 2; i++) {
        int lin = i * 256 + tid;
        int r = lin >> 3, c8 = lin & 7;
        kreg[i] = *reinterpret_cast<const uint4*>(
            &qkv[(size_t)r * QKV_ + H_ + c8 * 8]);
        vreg[i] = *reinterpret_cast<const uint4*>(
            &qkv[(size_t)r * QKV_ + 2 * H_ + c8 * 8]);
    }

    const int NT = S_ / 64;
    for (int kt = 0; kt < NT; kt++) {
        __syncthreads();
#pragma unroll
        for (int i = 0; i < 2; i++) {
            int lin = i * 256 + tid;
            int r = lin >> 3, c8 = lin & 7;
            *reinterpret_cast<uint4*>(&Ks[r * 72 + c8 * 8]) = kreg[i];
            *reinterpret_cast<uint4*>(&Vs[r * 72 + c8 * 8]) = vreg[i];
        }
        __syncthreads();

        if (kt + 1 < NT) {
            const int kv0 = (kt + 1) * 64;
#pragma unroll
            for (int i = 0; i < 2; i++) {
                int lin = i * 256 + tid;
                int r = lin >> 3, c8 = lin & 7;
                kreg[i] = *reinterpret_cast<const uint4*>(
                    &qkv[(size_t)(kv0 + r) * QKV_ + H_ + c8 * 8]);
                vreg[i] = *reinterpret_cast<const uint4*>(
                    &qkv[(size_t)(kv0 + r) * QKV_ + 2 * H_ + c8 * 8]);
            }
        }

        // S = Q K^T : warp tile 32(q) x 32(kv), k = 64
        float sacc[2][4][4];
#pragma unroll
        for (int mt = 0; mt < 2; mt++)
#pragma unroll
            for (int n = 0; n < 4; n++)
#pragma unroll
                for (int j = 0; j < 4; j++) sacc[mt][n][j] = 0.0f;

#pragma unroll
        for (int ko16 = 0; ko16 < 4; ko16++) {
            const int ko = ko16 * 16;
            uint32_t a[2][4];
            ldsm_x4(a[0], Qb + aoffQ0 + 2u * ko);
            ldsm_x4(a[1], Qb + aoffQ1 + 2u * ko);
#pragma unroll
            for (int n = 0; n < 4; n++) {
                uint32_t bb[2];
                // K rows (= S cols) nw*32 + 8n + (lane&7), cols ko(+8)
                ldsm_x2(bb, Kb + 2u * ((nw * 32 + 8 * n + (lane & 7)) * 72 +
                                        ko + ((lane >> 3) & 1) * 8));
                mma_f16(sacc[0][n], a[0], bb);
                mma_f16(sacc[1][n], a[1], bb);
            }
        }

        // online softmax per mt over this warp's kv half
#pragma unroll
        for (int mt = 0; mt < 2; mt++) {
            float m0 = -1e30f, m1 = -1e30f;
#pragma unroll
            for (int n = 0; n < 4; n++) {
                m0 = fmaxf(m0, fmaxf(sacc[mt][n][0], sacc[mt][n][1]));
                m1 = fmaxf(m1, fmaxf(sacc[mt][n][2], sacc[mt][n][3]));
            }
            m0 = fmaxf(m0, __shfl_xor_sync(0xffffffffu, m0, 1));
            m0 = fmaxf(m0, __shfl_xor_sync(0xffffffffu, m0, 2));
            m1 = fmaxf(m1, __shfl_xor_sync(0xffffffffu, m1, 1));
            m1 = fmaxf(m1, __shfl_xor_sync(0xffffffffu, m1, 2));
            float mn0 = fmaxf(m_r[mt][0], m0);
            float mn1 = fmaxf(m_r[mt][1], m1);
            float al0 = __expf(m_r[mt][0] - mn0);
            float al1 = __expf(m_r[mt][1] - mn1);
            m_r[mt][0] = mn0; m_r[mt][1] = mn1;

            float s0 = 0.0f, s1 = 0.0f;
#pragma unroll
            for (int n = 0; n < 4; n++) {
                sacc[mt][n][0] = __expf(sacc[mt][n][0] - mn0);
                sacc[mt][n][1] = __expf(sacc[mt][n][1] - mn0);
                sacc[mt][n][2] = __expf(sacc[mt][n][2] - mn1);
                sacc[mt][n][3] = __expf(sacc[mt][n][3] - mn1);
                s0 += sacc[mt][n][0] + sacc[mt][n][1];
                s1 += sacc[mt][n][2] + sacc[mt][n][3];
            }
            s0 += __shfl_xor_sync(0xffffffffu, s0, 1);
            s0 += __shfl_xor_sync(0xffffffffu, s0, 2);
            s1 += __shfl_xor_sync(0xffffffffu, s1, 1);
            s1 += __shfl_xor_sync(0xffffffffu, s1, 2);
            l_r[mt][0] = l_r[mt][0] * al0 + s0;
            l_r[mt][1] = l_r[mt][1] * al1 + s1;
#pragma unroll
            for (int n = 0; n < 8; n++) {
                oacc[mt][n][0] *= al0;
                oacc[mt][n][1] *= al0;
                oacc[mt][n][2] *= al1;
                oacc[mt][n][3] *= al1;
            }
            // write P fp16 (warp-private rows x cols)
            int r0 = mw * 32 + mt * 16 + g;
            int cb = nw * 32 + 2 * t;
#pragma unroll
            for (int n = 0; n < 4; n++) {
                *reinterpret_cast<uint32_t*>(&Ps[r0 * 72 + cb + 8 * n]) =
                    h2u(__floats2half2_rn(sacc[mt][n][0], sacc[mt][n][1]));
                *reinterpret_cast<uint32_t*>(&Ps[(r0 + 8) * 72 + cb + 8 * n]) =
                    h2u(__floats2half2_rn(sacc[mt][n][2], sacc[mt][n][3]));
            }
        }
        __syncwarp();

        // O += P V : warp tile 32(q) x 64(h), k = warp's 32 kv
#pragma unroll
        for (int ko16 = 0; ko16 < 2; ko16++) {
            const int ko = ko16 * 16;
            uint32_t a[2][4];
            ldsm_x4(a[0], Pb + aoffP0 + 2u * ko);
            ldsm_x4(a[1], Pb + aoffP1 + 2u * ko);
#pragma unroll
            for (int n = 0; n < 8; n++) {
                uint32_t bb[2];
                // V natural [kv][h], trans ldmatrix: rows kv = nw*32+ko+brow, cols 8n
                ldsm_x2_t(bb, Vb + 2u * ((nw * 32 + ko + brow) * 72 + 8 * n));
                mma_f16(oacc[0][n], a[0], bb);
                mma_f16(oacc[1][n], a[1], bb);
            }
        }
    }

    // ---- merge kv halves ----
    __syncthreads();
    if (nw == 1) {
#pragma unroll
        for (int mt = 0; mt < 2; mt++) {
            int r0 = mw * 32 + mt * 16 + g;
#pragma unroll
            for (int n = 0; n < 8; n++) {
                int col = 8 * n + 2 * t;
                Of[r0 * 68 + col]           = oacc[mt][n][0];
                Of[r0 * 68 + col + 1]       = oacc[mt][n][1];
                Of[(r0 + 8) * 68 + col]     = oacc[mt][n][2];
                Of[(r0 + 8) * 68 + col + 1] = oacc[mt][n][3];
            }
            if (t == 0) {
                sm_m[r0] = m_r[mt][0]; sm_l[r0] = l_r[mt][0];
                sm_m[r0 + 8] = m_r[mt][1]; sm_l[r0 + 8] = l_r[mt][1];
            }
        }
    }
    __syncthreads();
    if (nw == 0) {
#pragma unroll
        for (int mt = 0; mt < 2; mt++) {
            int r0 = mw * 32 + mt * 16 + g;
#pragma unroll
            for (int half = 0; half < 2; half++) {
                int row = r0 + 8 * half;
                float mA = m_r[mt][half], lA = l_r[mt][half];
                float mB = sm_m[row],     lB = sm_l[row];
                float mm = fmaxf(mA, mB);
                float fA = __expf(mA - mm), fB = __expf(mB - mm);
                float inv = 1.0f / (lA * fA + lB * fB);
                fA *= inv; fB *= inv;
                size_t orow = (size_t)b * S_ + q0 + row;
#pragma unroll
                for (int n = 0; n < 8; n++) {
                    int col = 8 * n + 2 * t;
                    float x0 = oacc[mt][n][2 * half]     * fA + Of[row * 68 + col]     * fB;
                    float x1 = oacc[mt][n][2 * half + 1] * fA + Of[row * 68 + col + 1] * fB;
                    *reinterpret_cast<uint32_t*>(&g_ctx[orow * H_ + col]) =
                        h2u(__floats2half2_rn(x0, x1));
                }
            }
        }
    }
}

// ---------------------------------------------------------------------------
// Kernel 3: out projection. out[16384,1024] = ctx[16384,64] @ W_out[64,1024] + b
// BM=128, BN=128, K=64 single pass, fp16 MMA.
// ---------------------------------------------------------------------------
__global__ __launch_bounds__(256) void out_kernel(const float* __restrict__ W,
                                                  const float* __restrict__ bias,
                                                  float* __restrict__ out) {
    __shared__ __half Cs[128 * 72];    // [m][k] stride 72
    __shared__ __half Ws2[64 * 136];   // [k][n] stride 136 (natural)

    const int m0   = blockIdx.y * 128;
    const int n0   = blockIdx.x * 128;
    const int tid  = threadIdx.x;
    const int w    = tid >> 5;
    const int lane = tid & 31;
    const int g    = lane >> 2;
    const int t    = lane & 3;
    const int mw   = w >> 1;
    const int nw   = w & 1;

    const uint32_t Cb = smem_u32(Cs);
    const uint32_t Wb = smem_u32(Ws2);
    const uint32_t brow = (lane & 7) + ((lane >> 3) & 1) * 8;
    const uint32_t aoff0 = 2u * ((mw * 32 + (lane & 15)) * 72 + (lane >> 4) * 8);
    const uint32_t aoff1 = aoff0 + 2u * (16 * 72);

    // ctx tile: 128 rows x 8 uint4 (fp16 direct)
#pragma unroll
    for (int i = 0; i < 4; i++) {
        int lin = i * 256 + tid;
        int r = lin >> 3, c8 = lin & 7;
        uint4 v = *reinterpret_cast<const uint4*>(&g_ctx[(size_t)(m0 + r) * H_ + c8 * 8]);
        *reinterpret_cast<uint4*>(&Cs[r * 72 + c8 * 8]) = v;
    }
    // W tile natural [k][n]: 64 x 128 fp32 -> fp16
#pragma unroll
    for (int i = 0; i < 8; i++) {
        int lin = i * 256 + tid;
        int r = lin >> 5, c4 = lin & 31;
        float4 v = *reinterpret_cast<const float4*>(&W[(size_t)r * E_ + n0 + c4 * 4]);
        *reinterpret_cast<uint2*>(&Ws2[r * 136 + c4 * 4]) = f4h(v);
    }
    __syncthreads();

    float acc[2][8][4];
#pragma unroll
    for (int mt = 0; mt < 2; mt++)
#pragma unroll
        for (int n = 0; n < 8; n++)
#pragma unroll
            for (int j = 0; j < 4; j++) acc[mt][n][j] = 0.0f;

#pragma unroll
    for (int ko16 = 0; ko16 < 4; ko16++) {
        const int ko = ko16 * 16;
        uint32_t a[2][4];
        ldsm_x4(a[0], Cb + aoff0 + 2u * ko);
        ldsm_x4(a[1], Cb + aoff1 + 2u * ko);
#pragma unroll
        for (int n = 0; n < 8; n++) {
            uint32_t bb[2];
            int nc = nw * 64 + 8 * n;
            ldsm_x2_t(bb, Wb + 2u * ((ko + brow) * 136 + nc));
            mma_f16(acc[0][n], a[0], bb);
            mma_f16(acc[1][n], a[1], bb);
        }
    }

#pragma unroll
    for (int n = 0; n < 8; n++) {
        int col = n0 + nw * 64 + 8 * n + 2 * t;
        float b0 = bias[col], b1 = bias[col + 1];
#pragma unroll
        for (int mt = 0; mt < 2; mt++) {
            int row = m0 + mw * 32 + mt * 16 + g;
            float2 v0 = make_float2(acc[mt][n][0] + b0, acc[mt][n][1] + b1);
            *reinterpret_cast<float2*>(&out[(size_t)row * E_ + col]) = v0;
            float2 v1 = make_float2(acc[mt][n][2] + b0, acc[mt][n][3] + b1);
            *reinterpret_cast<float2*>(&out[(size_t)(row + 8) * E_ + col]) = v1;
        }
    }
}

// ---------------------------------------------------------------------------
extern "C" void kernel_launch(void* const* d_in, const int* in_sizes, int n_in,
                              void* d_out, int out_size) {
    const float* x     = (const float*)d_in[0];
    const float* W_qkv = (const float*)d_in[1];
    const float* b_qkv = (const float*)d_in[2];
    const float* W_out = (const float*)d_in[3];
    const float* b_out = (const float*)d_in[4];
    float* out = (float*)d_out;

    qkv_kernel<<<M_TOT / 128, 256>>>(x, W_qkv, b_qkv);

    {
        size_t smem = ATTN_SMEM_HALVES * sizeof(__half);   // 55296 B
        cudaFuncSetAttribute(attn_kernel,
                             cudaFuncAttributeMaxDynamicSharedMemorySize,
                             (int)smem);
        dim3 grid(S_ / 128, B_);
        attn_kernel<<<grid, 256, smem>>>();
    }
    {
        dim3 grid(E_ / 128, M_TOT / 128);
        out_kernel<<<grid, 256>>>(W_out, b_out, out);
    }
}

// round 8
// speedup vs baseline: 6.7734x; 1.0011x over previous
#include <cuda_runtime.h>
#include <cuda_fp16.h>
#include <stdint.h>
#include <math.h>

#define B_    4
#define S_    4096
#define E_    1024
#define H_    64
#define QKV_  192
#define M_TOT (B_ * S_)   // 16384

__device__ __half g_qkv[B_ * S_ * QKV_];   // [16384, 192] fp16 (q pre-scaled)
__device__ __half g_ctx[B_ * S_ * H_];     // [16384, 64]  fp16

// ---------------------------------------------------------------------------
// helpers
// ---------------------------------------------------------------------------
__device__ __forceinline__ uint32_t h2u(__half2 h) {
    return *reinterpret_cast<uint32_t*>(&h);
}
__device__ __forceinline__ uint2 f4h(float4 v) {
    uint2 u;
    u.x = h2u(__floats2half2_rn(v.x, v.y));
    u.y = h2u(__floats2half2_rn(v.z, v.w));
    return u;
}
// D += A(16x16) * B(16x8), fp16 in, fp32 accum
__device__ __forceinline__ void mma_f16(float d[4], const uint32_t a[4],
                                        const uint32_t b[2]) {
    asm volatile(
        "mma.sync.aligned.m16n8k16.row.col.f32.f16.f16.f32 "
        "{%0,%1,%2,%3},{%4,%5,%6,%7},{%8,%9},{%0,%1,%2,%3};\n"
        : "+f"(d[0]), "+f"(d[1]), "+f"(d[2]), "+f"(d[3])
        : "r"(a[0]), "r"(a[1]), "r"(a[2]), "r"(a[3]),
          "r"(b[0]), "r"(b[1]));
}
__device__ __forceinline__ void ldsm_x4(uint32_t d[4], uint32_t saddr) {
    asm volatile("ldmatrix.sync.aligned.m8n8.x4.shared.b16 {%0,%1,%2,%3}, [%4];"
                 : "=r"(d[0]), "=r"(d[1]), "=r"(d[2]), "=r"(d[3]) : "r"(saddr));
}
__device__ __forceinline__ void ldsm_x2(uint32_t d[2], uint32_t saddr) {
    asm volatile("ldmatrix.sync.aligned.m8n8.x2.shared.b16 {%0,%1}, [%2];"
                 : "=r"(d[0]), "=r"(d[1]) : "r"(saddr));
}
__device__ __forceinline__ void ldsm_x2_t(uint32_t d[2], uint32_t saddr) {
    asm volatile("ldmatrix.sync.aligned.m8n8.x2.trans.shared.b16 {%0,%1}, [%2];"
                 : "=r"(d[0]), "=r"(d[1]) : "r"(saddr));
}
__device__ __forceinline__ uint32_t smem_u32(const void* p) {
    return (uint32_t)__cvta_generic_to_shared(p);
}

// ---------------------------------------------------------------------------
// Kernel 1: QKV projection. C[16384,192] = x[16384,1024] @ W[1024,192] + b
// BM=128, BN=192, BK=32. 8 warps (4m x 2n), warp tile 32x96, fp16 MMA.
// ---------------------------------------------------------------------------
__global__ __launch_bounds__(256) void qkv_kernel(const float* __restrict__ A,
                                                  const float* __restrict__ W,
                                                  const float* __restrict__ bias) {
    __shared__ __half As[128 * 40];    // [m][k] stride 40 halves
    __shared__ __half Ws[32 * 200];    // [k][n] stride 200 halves (natural)

    const int m0   = blockIdx.x * 128;
    const int tid  = threadIdx.x;
    const int w    = tid >> 5;
    const int lane = tid & 31;
    const int g    = lane >> 2;
    const int t    = lane & 3;
    const int mw   = w >> 1;
    const int nw   = w & 1;

    const uint32_t Ab = smem_u32(As);
    const uint32_t Wb = smem_u32(Ws);
    // A-fragment ldmatrix byte offsets (per mt)
    const uint32_t aoff0 = 2u * ((mw * 32 + (lane & 15)) * 40 + (lane >> 4) * 8);
    const uint32_t aoff1 = aoff0 + 2u * (16 * 40);
    // B-fragment (trans) row part
    const uint32_t brow = (lane & 7) + ((lane >> 3) & 1) * 8;

    float acc[2][12][4];
#pragma unroll
    for (int mt = 0; mt < 2; mt++)
#pragma unroll
        for (int n = 0; n < 12; n++)
#pragma unroll
            for (int j = 0; j < 4; j++) acc[mt][n][j] = 0.0f;

    float4 areg[4], wreg[6];
#pragma unroll
    for (int i = 0; i < 4; i++) {
        int lin = i * 256 + tid;
        int r = lin >> 3, c4 = lin & 7;
        areg[i] = *reinterpret_cast<const float4*>(&A[(size_t)(m0 + r) * E_ + c4 * 4]);
    }
#pragma unroll
    for (int i = 0; i < 6; i++) {
        int lin = i * 256 + tid;
        int r = lin / 48, c = lin % 48;
        wreg[i] = *reinterpret_cast<const float4*>(&W[(size_t)r * QKV_ + c * 4]);
    }

    for (int k0 = 0; k0 < E_; k0 += 32) {
        __syncthreads();
#pragma unroll
        for (int i = 0; i < 4; i++) {
            int lin = i * 256 + tid;
            int r = lin >> 3, c4 = lin & 7;
            *reinterpret_cast<uint2*>(&As[r * 40 + c4 * 4]) = f4h(areg[i]);
        }
#pragma unroll
        for (int i = 0; i < 6; i++) {
            int lin = i * 256 + tid;
            int r = lin / 48, c = lin % 48;
            *reinterpret_cast<uint2*>(&Ws[r * 200 + c * 4]) = f4h(wreg[i]);
        }
        __syncthreads();

        if (k0 + 32 < E_) {
#pragma unroll
            for (int i = 0; i < 4; i++) {
                int lin = i * 256 + tid;
                int r = lin >> 3, c4 = lin & 7;
                areg[i] = *reinterpret_cast<const float4*>(
                    &A[(size_t)(m0 + r) * E_ + k0 + 32 + c4 * 4]);
            }
#pragma unroll
            for (int i = 0; i < 6; i++) {
                int lin = i * 256 + tid;
                int r = lin / 48, c = lin % 48;
                wreg[i] = *reinterpret_cast<const float4*>(
                    &W[(size_t)(k0 + 32 + r) * QKV_ + c * 4]);
            }
        }

#pragma unroll
        for (int ko16 = 0; ko16 < 2; ko16++) {
            const int ko = ko16 * 16;
            uint32_t a[2][4];
            ldsm_x4(a[0], Ab + aoff0 + 2u * ko);
            ldsm_x4(a[1], Ab + aoff1 + 2u * ko);
#pragma unroll
            for (int n = 0; n < 12; n++) {
                uint32_t b[2];
                int nc = nw * 96 + 8 * n;
                ldsm_x2_t(b, Wb + 2u * ((ko + brow) * 200 + nc));
                mma_f16(acc[0][n], a[0], b);
                mma_f16(acc[1][n], a[1], b);
            }
        }
    }

    // epilogue: bias, q-scale, fp16 store
#pragma unroll
    for (int n = 0; n < 12; n++) {
        int col = nw * 96 + 8 * n + 2 * t;
        float sc = (col < 64) ? 0.125f : 1.0f;
        float b0 = bias[col], b1 = bias[col + 1];
#pragma unroll
        for (int mt = 0; mt < 2; mt++) {
            int row = m0 + mw * 32 + mt * 16 + g;
            __half2 v0 = __floats2half2_rn((acc[mt][n][0] + b0) * sc,
                                           (acc[mt][n][1] + b1) * sc);
            *reinterpret_cast<uint32_t*>(&g_qkv[(size_t)row * QKV_ + col]) = h2u(v0);
            __half2 v1 = __floats2half2_rn((acc[mt][n][2] + b0) * sc,
                                           (acc[mt][n][3] + b1) * sc);
            *reinterpret_cast<uint32_t*>(&g_qkv[(size_t)(row + 8) * QKV_ + col]) = h2u(v1);
        }
    }
}

// ---------------------------------------------------------------------------
// Kernel 2: flash attention, fp16 MMA. BQ=128, BK=64. 8 warps = 4(m) x 2(kv).
// ---------------------------------------------------------------------------
// half-word offsets
#define Q_OFFH 0
#define K_OFFH (128 * 72)
#define V_OFFH (K_OFFH + 64 * 72)
#define P_OFFH (V_OFFH + 64 * 72)
#define ATTN_SMEM_HALVES (P_OFFH + 128 * 72)   // 27648 halves = 55296 B
// merge scratch (float words, overlaps Q/K/V after the loop)
#define OF_OFFW 0
#define MS_OFFW (128 * 68)
#define LS_OFFW (MS_OFFW + 128)

__global__ __launch_bounds__(256) void attn_kernel() {
    extern __shared__ __half smh[];
    __half* Qs = smh + Q_OFFH;      // [128 q][72]  (q x h)
    __half* Ks = smh + K_OFFH;      // [64 kv][72]  (kv x h)
    __half* Vs = smh + V_OFFH;      // [64 kv][72]  (kv x h)  natural
    __half* Ps = smh + P_OFFH;      // [128 q][72]  (q x kv)
    float* Of   = reinterpret_cast<float*>(smh) + OF_OFFW;
    float* sm_m = reinterpret_cast<float*>(smh) + MS_OFFW;
    float* sm_l = reinterpret_cast<float*>(smh) + LS_OFFW;

    const int b    = blockIdx.y;
    const int q0   = blockIdx.x * 128;
    const int tid  = threadIdx.x;
    const int w    = tid >> 5;
    const int lane = tid & 31;
    const int g    = lane >> 2;
    const int t    = lane & 3;
    const int mw   = w >> 1;        // 0..3 : 32 q rows
    const int nw   = w & 1;         // 0..1 : kv half
    const __half* qkv = g_qkv + (size_t)b * S_ * QKV_;

    const uint32_t Qb = smem_u32(Qs);
    const uint32_t Kb = smem_u32(Ks);
    const uint32_t Vb = smem_u32(Vs);
    const uint32_t Pb = smem_u32(Ps);

    const uint32_t brow = (lane & 7) + ((lane >> 3) & 1) * 8;
    const uint32_t aoffQ0 = 2u * ((mw * 32 + (lane & 15)) * 72 + (lane >> 4) * 8);
    const uint32_t aoffQ1 = aoffQ0 + 2u * (16 * 72);
    const uint32_t aoffP0 = aoffQ0 + 2u * (nw * 32);
    const uint32_t aoffP1 = aoffQ1 + 2u * (nw * 32);

    // Load Q (already scaled, fp16): 128 rows x 8 uint4
#pragma unroll
    for (int i = 0; i < 4; i++) {
        int lin = i * 256 + tid;
        int r = lin >> 3, c8 = lin & 7;
        uint4 v = *reinterpret_cast<const uint4*>(
            &qkv[(size_t)(q0 + r) * QKV_ + c8 * 8]);
        *reinterpret_cast<uint4*>(&Qs[r * 72 + c8 * 8]) = v;
    }

    float oacc[2][8][4];
#pragma unroll
    for (int mt = 0; mt < 2; mt++)
#pragma unroll
        for (int n = 0; n < 8; n++)
#pragma unroll
            for (int j = 0; j < 4; j++) oacc[mt][n][j] = 0.0f;
    float m_r[2][2], l_r[2][2];
#pragma unroll
    for (int mt = 0; mt < 2; mt++) {
        m_r[mt][0] = -1e30f; m_r[mt][1] = -1e30f;
        l_r[mt][0] = 0.0f;   l_r[mt][1] = 0.0f;
    }

    // prefetch tile 0
    uint4 kreg[2], vreg[2];
#pragma unroll
    for (int i = 0; i < 2; i++) {
        int lin = i * 256 + tid;
        int r = lin >> 3, c8 = lin & 7;
        kreg[i] = *reinterpret_cast<const uint4*>(
            &qkv[(size_t)r * QKV_ + H_ + c8 * 8]);
        vreg[i] = *reinterpret_cast<const uint4*>(
            &qkv[(size_t)r * QKV_ + 2 * H_ + c8 * 8]);
    }

    const int NT = S_ / 64;
    for (int kt = 0; kt < NT; kt++) {
        __syncthreads();
#pragma unroll
        for (int i = 0; i < 2; i++) {
            int lin = i * 256 + tid;
            int r = lin >> 3, c8 = lin & 7;
            *reinterpret_cast<uint4*>(&Ks[r * 72 + c8 * 8]) = kreg[i];
            *reinterpret_cast<uint4*>(&Vs[r * 72 + c8 * 8]) = vreg[i];
        }
        __syncthreads();

        if (kt + 1 < NT) {
            const int kv0 = (kt + 1) * 64;
#pragma unroll
            for (int i = 0; i < 2; i++) {
                int lin = i * 256 + tid;
                int r = lin >> 3, c8 = lin & 7;
                kreg[i] = *reinterpret_cast<const uint4*>(
                    &qkv[(size_t)(kv0 + r) * QKV_ + H_ + c8 * 8]);
                vreg[i] = *reinterpret_cast<const uint4*>(
                    &qkv[(size_t)(kv0 + r) * QKV_ + 2 * H_ + c8 * 8]);
            }
        }

        // S = Q K^T : warp tile 32(q) x 32(kv), k = 64
        float sacc[2][4][4];
#pragma unroll
        for (int mt = 0; mt < 2; mt++)
#pragma unroll
            for (int n = 0; n < 4; n++)
#pragma unroll
                for (int j = 0; j < 4; j++) sacc[mt][n][j] = 0.0f;

#pragma unroll
        for (int ko16 = 0; ko16 < 4; ko16++) {
            const int ko = ko16 * 16;
            uint32_t a[2][4];
            ldsm_x4(a[0], Qb + aoffQ0 + 2u * ko);
            ldsm_x4(a[1], Qb + aoffQ1 + 2u * ko);
#pragma unroll
            for (int n = 0; n < 4; n++) {
                uint32_t bb[2];
                // K rows (= S cols) nw*32 + 8n + (lane&7), cols ko(+8)
                ldsm_x2(bb, Kb + 2u * ((nw * 32 + 8 * n + (lane & 7)) * 72 +
                                        ko + ((lane >> 3) & 1) * 8));
                mma_f16(sacc[0][n], a[0], bb);
                mma_f16(sacc[1][n], a[1], bb);
            }
        }

        // online softmax per mt over this warp's kv half
#pragma unroll
        for (int mt = 0; mt < 2; mt++) {
            float m0 = -1e30f, m1 = -1e30f;
#pragma unroll
            for (int n = 0; n < 4; n++) {
                m0 = fmaxf(m0, fmaxf(sacc[mt][n][0], sacc[mt][n][1]));
                m1 = fmaxf(m1, fmaxf(sacc[mt][n][2], sacc[mt][n][3]));
            }
            m0 = fmaxf(m0, __shfl_xor_sync(0xffffffffu, m0, 1));
            m0 = fmaxf(m0, __shfl_xor_sync(0xffffffffu, m0, 2));
            m1 = fmaxf(m1, __shfl_xor_sync(0xffffffffu, m1, 1));
            m1 = fmaxf(m1, __shfl_xor_sync(0xffffffffu, m1, 2));
            float mn0 = fmaxf(m_r[mt][0], m0);
            float mn1 = fmaxf(m_r[mt][1], m1);
            float al0 = __expf(m_r[mt][0] - mn0);
            float al1 = __expf(m_r[mt][1] - mn1);
            m_r[mt][0] = mn0; m_r[mt][1] = mn1;

            float s0 = 0.0f, s1 = 0.0f;
#pragma unroll
            for (int n = 0; n < 4; n++) {
                sacc[mt][n][0] = __expf(sacc[mt][n][0] - mn0);
                sacc[mt][n][1] = __expf(sacc[mt][n][1] - mn0);
                sacc[mt][n][2] = __expf(sacc[mt][n][2] - mn1);
                sacc[mt][n][3] = __expf(sacc[mt][n][3] - mn1);
                s0 += sacc[mt][n][0] + sacc[mt][n][1];
                s1 += sacc[mt][n][2] + sacc[mt][n][3];
            }
            s0 += __shfl_xor_sync(0xffffffffu, s0, 1);
            s0 += __shfl_xor_sync(0xffffffffu, s0, 2);
            s1 += __shfl_xor_sync(0xffffffffu, s1, 1);
            s1 += __shfl_xor_sync(0xffffffffu, s1, 2);
            l_r[mt][0] = l_r[mt][0] * al0 + s0;
            l_r[mt][1] = l_r[mt][1] * al1 + s1;
#pragma unroll
            for (int n = 0; n < 8; n++) {
                oacc[mt][n][0] *= al0;
                oacc[mt][n][1] *= al0;
                oacc[mt][n][2] *= al1;
                oacc[mt][n][3] *= al1;
            }
            // write P fp16 (warp-private rows x cols)
            int r0 = mw * 32 + mt * 16 + g;
            int cb = nw * 32 + 2 * t;
#pragma unroll
            for (int n = 0; n < 4; n++) {
                *reinterpret_cast<uint32_t*>(&Ps[r0 * 72 + cb + 8 * n]) =
                    h2u(__floats2half2_rn(sacc[mt][n][0], sacc[mt][n][1]));
                *reinterpret_cast<uint32_t*>(&Ps[(r0 + 8) * 72 + cb + 8 * n]) =
                    h2u(__floats2half2_rn(sacc[mt][n][2], sacc[mt][n][3]));
            }
        }
        __syncwarp();

        // O += P V : warp tile 32(q) x 64(h), k = warp's 32 kv
#pragma unroll
        for (int ko16 = 0; ko16 < 2; ko16++) {
            const int ko = ko16 * 16;
            uint32_t a[2][4];
            ldsm_x4(a[0], Pb + aoffP0 + 2u * ko);
            ldsm_x4(a[1], Pb + aoffP1 + 2u * ko);
#pragma unroll
            for (int n = 0; n < 8; n++) {
                uint32_t bb[2];
                // V natural [kv][h], trans ldmatrix: rows kv = nw*32+ko+brow, cols 8n
                ldsm_x2_t(bb, Vb + 2u * ((nw * 32 + ko + brow) * 72 + 8 * n));
                mma_f16(oacc[0][n], a[0], bb);
                mma_f16(oacc[1][n], a[1], bb);
            }
        }
    }

    // ---- merge kv halves ----
    __syncthreads();
    if (nw == 1) {
#pragma unroll
        for (int mt = 0; mt < 2; mt++) {
            int r0 = mw * 32 + mt * 16 + g;
#pragma unroll
            for (int n = 0; n < 8; n++) {
                int col = 8 * n + 2 * t;
                Of[r0 * 68 + col]           = oacc[mt][n][0];
                Of[r0 * 68 + col + 1]       = oacc[mt][n][1];
                Of[(r0 + 8) * 68 + col]     = oacc[mt][n][2];
                Of[(r0 + 8) * 68 + col + 1] = oacc[mt][n][3];
            }
            if (t == 0) {
                sm_m[r0] = m_r[mt][0]; sm_l[r0] = l_r[mt][0];
                sm_m[r0 + 8] = m_r[mt][1]; sm_l[r0 + 8] = l_r[mt][1];
            }
        }
    }
    __syncthreads();
    if (nw == 0) {
#pragma unroll
        for (int mt = 0; mt < 2; mt++) {
            int r0 = mw * 32 + mt * 16 + g;
#pragma unroll
            for (int half = 0; half < 2; half++) {
                int row = r0 + 8 * half;
                float mA = m_r[mt][half], lA = l_r[mt][half];
                float mB = sm_m[row],     lB = sm_l[row];
                float mm = fmaxf(mA, mB);
                float fA = __expf(mA - mm), fB = __expf(mB - mm);
                float inv = 1.0f / (lA * fA + lB * fB);
                fA *= inv; fB *= inv;
                size_t orow = (size_t)b * S_ + q0 + row;
#pragma unroll
                for (int n = 0; n < 8; n++) {
                    int col = 8 * n + 2 * t;
                    float x0 = oacc[mt][n][2 * half]     * fA + Of[row * 68 + col]     * fB;
                    float x1 = oacc[mt][n][2 * half + 1] * fA + Of[row * 68 + col + 1] * fB;
                    *reinterpret_cast<uint32_t*>(&g_ctx[orow * H_ + col]) =
                        h2u(__floats2half2_rn(x0, x1));
                }
            }
        }
    }
}

// ---------------------------------------------------------------------------
// Kernel 3: out projection. out[16384,1024] = ctx[16384,64] @ W_out[64,1024] + b
// BM=128, BN=128, K=64 single pass, fp16 MMA.
// ---------------------------------------------------------------------------
__global__ __launch_bounds__(256) void out_kernel(const float* __restrict__ W,
                                                  const float* __restrict__ bias,
                                                  float* __restrict__ out) {
    __shared__ __half Cs[128 * 72];    // [m][k] stride 72
    __shared__ __half Ws2[64 * 136];   // [k][n] stride 136 (natural)

    const int m0   = blockIdx.y * 128;
    const int n0   = blockIdx.x * 128;
    const int tid  = threadIdx.x;
    const int w    = tid >> 5;
    const int lane = tid & 31;
    const int g    = lane >> 2;
    const int t    = lane & 3;
    const int mw   = w >> 1;
    const int nw   = w & 1;

    const uint32_t Cb = smem_u32(Cs);
    const uint32_t Wb = smem_u32(Ws2);
    const uint32_t brow = (lane & 7) + ((lane >> 3) & 1) * 8;
    const uint32_t aoff0 = 2u * ((mw * 32 + (lane & 15)) * 72 + (lane >> 4) * 8);
    const uint32_t aoff1 = aoff0 + 2u * (16 * 72);

    // ctx tile: 128 rows x 8 uint4 (fp16 direct)
#pragma unroll
    for (int i = 0; i < 4; i++) {
        int lin = i * 256 + tid;
        int r = lin >> 3, c8 = lin & 7;
        uint4 v = *reinterpret_cast<const uint4*>(&g_ctx[(size_t)(m0 + r) * H_ + c8 * 8]);
        *reinterpret_cast<uint4*>(&Cs[r * 72 + c8 * 8]) = v;
    }
    // W tile natural [k][n]: 64 x 128 fp32 -> fp16
#pragma unroll
    for (int i = 0; i < 8; i++) {
        int lin = i * 256 + tid;
        int r = lin >> 5, c4 = lin & 31;
        float4 v = *reinterpret_cast<const float4*>(&W[(size_t)r * E_ + n0 + c4 * 4]);
        *reinterpret_cast<uint2*>(&Ws2[r * 136 + c4 * 4]) = f4h(v);
    }
    __syncthreads();

    float acc[2][8][4];
#pragma unroll
    for (int mt = 0; mt < 2; mt++)
#pragma unroll
        for (int n = 0; n < 8; n++)
#pragma unroll
            for (int j = 0; j < 4; j++) acc[mt][n][j] = 0.0f;

#pragma unroll
    for (int ko16 = 0; ko16 < 4; ko16++) {
        const int ko = ko16 * 16;
        uint32_t a[2][4];
        ldsm_x4(a[0], Cb + aoff0 + 2u * ko);
        ldsm_x4(a[1], Cb + aoff1 + 2u * ko);
#pragma unroll
        for (int n = 0; n < 8; n++) {
            uint32_t bb[2];
            int nc = nw * 64 + 8 * n;
            ldsm_x2_t(bb, Wb + 2u * ((ko + brow) * 136 + nc));
            mma_f16(acc[0][n], a[0], bb);
            mma_f16(acc[1][n], a[1], bb);
        }
    }

#pragma unroll
    for (int n = 0; n < 8; n++) {
        int col = n0 + nw * 64 + 8 * n + 2 * t;
        float b0 = bias[col], b1 = bias[col + 1];
#pragma unroll
        for (int mt = 0; mt < 2; mt++) {
            int row = m0 + mw * 32 + mt * 16 + g;
            float2 v0 = make_float2(acc[mt][n][0] + b0, acc[mt][n][1] + b1);
            *reinterpret_cast<float2*>(&out[(size_t)row * E_ + col]) = v0;
            float2 v1 = make_float2(acc[mt][n][2] + b0, acc[mt][n][3] + b1);
            *reinterpret_cast<float2*>(&out[(size_t)(row + 8) * E_ + col]) = v1;
        }
    }
}

// ---------------------------------------------------------------------------
extern "C" void kernel_launch(void* const* d_in, const int* in_sizes, int n_in,
                              void* d_out, int out_size) {
    const float* x     = (const float*)d_in[0];
    const float* W_qkv = (const float*)d_in[1];
    const float* b_qkv = (const float*)d_in[2];
    const float* W_out = (const float*)d_in[3];
    const float* b_out = (const float*)d_in[4];
    float* out = (float*)d_out;

    qkv_kernel<<<M_TOT / 128, 256>>>(x, W_qkv, b_qkv);

    {
        size_t smem = ATTN_SMEM_HALVES * sizeof(__half);   // 55296 B
        cudaFuncSetAttribute(attn_kernel,
                             cudaFuncAttributeMaxDynamicSharedMemorySize,
                             (int)smem);
        dim3 grid(S_ / 128, B_);
        attn_kernel<<<grid, 256, smem>>>();
    }
    {
        dim3 grid(E_ / 128, M_TOT / 128);
        out_kernel<<<grid, 256>>>(W_out, b_out, out);
    }
}

// round 9
// speedup vs baseline: 6.9344x; 1.0238x over previous
#include <cuda_runtime.h>
#include <cuda_fp16.h>
#include <stdint.h>
#include <math.h>

#define B_    4
#define S_    4096
#define E_    1024
#define H_    64
#define QKV_  192
#define M_TOT (B_ * S_)   // 16384

// Q is pre-scaled by 0.125 * log2(e) so softmax runs in the exp2 domain.
#define QSCALE 0.18033688011112042f

__device__ __half g_qkv[B_ * S_ * QKV_];   // [16384, 192] fp16

// ---------------------------------------------------------------------------
// helpers
// ---------------------------------------------------------------------------
__device__ __forceinline__ uint32_t h2u(__half2 h) {
    return *reinterpret_cast<uint32_t*>(&h);
}
__device__ __forceinline__ uint2 f4h(float4 v) {
    uint2 u;
    u.x = h2u(__floats2half2_rn(v.x, v.y));
    u.y = h2u(__floats2half2_rn(v.z, v.w));
    return u;
}
__device__ __forceinline__ float ex2f(float x) {
    float y;
    asm("ex2.approx.ftz.f32 %0, %1;" : "=f"(y) : "f"(x));
    return y;
}
__device__ __forceinline__ void mma_f16(float d[4], const uint32_t a[4],
                                        const uint32_t b[2]) {
    asm volatile(
        "mma.sync.aligned.m16n8k16.row.col.f32.f16.f16.f32 "
        "{%0,%1,%2,%3},{%4,%5,%6,%7},{%8,%9},{%0,%1,%2,%3};\n"
        : "+f"(d[0]), "+f"(d[1]), "+f"(d[2]), "+f"(d[3])
        : "r"(a[0]), "r"(a[1]), "r"(a[2]), "r"(a[3]),
          "r"(b[0]), "r"(b[1]));
}
__device__ __forceinline__ void ldsm_x4(uint32_t d[4], uint32_t saddr) {
    asm volatile("ldmatrix.sync.aligned.m8n8.x4.shared.b16 {%0,%1,%2,%3}, [%4];"
                 : "=r"(d[0]), "=r"(d[1]), "=r"(d[2]), "=r"(d[3]) : "r"(saddr));
}
__device__ __forceinline__ void ldsm_x2(uint32_t d[2], uint32_t saddr) {
    asm volatile("ldmatrix.sync.aligned.m8n8.x2.shared.b16 {%0,%1}, [%2];"
                 : "=r"(d[0]), "=r"(d[1]) : "r"(saddr));
}
__device__ __forceinline__ void ldsm_x2_t(uint32_t d[2], uint32_t saddr) {
    asm volatile("ldmatrix.sync.aligned.m8n8.x2.trans.shared.b16 {%0,%1}, [%2];"
                 : "=r"(d[0]), "=r"(d[1]) : "r"(saddr));
}
__device__ __forceinline__ uint32_t smem_u32(const void* p) {
    return (uint32_t)__cvta_generic_to_shared(p);
}

// ---------------------------------------------------------------------------
// Kernel 1: QKV projection. C[16384,192] = x[16384,1024] @ W[1024,192] + b
// BM=64, BN=192, BK=32, grid 256, 2 CTAs/SM, double-buffered smem.
// 8 warps = 2m x 4n, warp tile 32 x 48.
// ---------------------------------------------------------------------------
__global__ __launch_bounds__(256, 2) void qkv_kernel(const float* __restrict__ A,
                                                     const float* __restrict__ W,
                                                     const float* __restrict__ bias) {
    __shared__ __half As[2][64 * 40];    // [m][k] stride 40
    __shared__ __half Ws[2][32 * 200];   // [k][n] stride 200

    const int m0   = blockIdx.x * 64;
    const int tid  = threadIdx.x;
    const int w    = tid >> 5;
    const int lane = tid & 31;
    const int g    = lane >> 2;
    const int t    = lane & 3;
    const int mw   = w >> 2;    // 0..1
    const int nw   = w & 3;     // 0..3

    const uint32_t brow = (lane & 7) + ((lane >> 3) & 1) * 8;
    const uint32_t aoff0 = 2u * ((mw * 32 + (lane & 15)) * 40 + (lane >> 4) * 8);
    const uint32_t aoff1 = aoff0 + 2u * (16 * 40);

    float acc[2][6][4];
#pragma unroll
    for (int mt = 0; mt < 2; mt++)
#pragma unroll
        for (int n = 0; n < 6; n++)
#pragma unroll
            for (int j = 0; j < 4; j++) acc[mt][n][j] = 0.0f;

    float4 areg[2], wreg[6];
    // prologue: tile 0 LDG + STS buf0
#pragma unroll
    for (int i = 0; i < 2; i++) {
        int lin = i * 256 + tid;
        int r = lin >> 3, c4 = lin & 7;
        areg[i] = *reinterpret_cast<const float4*>(&A[(size_t)(m0 + r) * E_ + c4 * 4]);
    }
#pragma unroll
    for (int i = 0; i < 6; i++) {
        int lin = i * 256 + tid;
        int r = lin / 48, c = lin % 48;
        wreg[i] = *reinterpret_cast<const float4*>(&W[(size_t)r * QKV_ + c * 4]);
    }
#pragma unroll
    for (int i = 0; i < 2; i++) {
        int lin = i * 256 + tid;
        int r = lin >> 3, c4 = lin & 7;
        *reinterpret_cast<uint2*>(&As[0][r * 40 + c4 * 4]) = f4h(areg[i]);
    }
#pragma unroll
    for (int i = 0; i < 6; i++) {
        int lin = i * 256 + tid;
        int r = lin / 48, c = lin % 48;
        *reinterpret_cast<uint2*>(&Ws[0][r * 200 + c * 4]) = f4h(wreg[i]);
    }

    for (int k0 = 0; k0 < E_; k0 += 32) {
        const int buf = (k0 >> 5) & 1;
        __syncthreads();   // STS of this buf done; MMA of other buf done
        const bool more = (k0 + 32 < E_);
        if (more) {
#pragma unroll
            for (int i = 0; i < 2; i++) {
                int lin = i * 256 + tid;
                int r = lin >> 3, c4 = lin & 7;
                areg[i] = *reinterpret_cast<const float4*>(
                    &A[(size_t)(m0 + r) * E_ + k0 + 32 + c4 * 4]);
            }
#pragma unroll
            for (int i = 0; i < 6; i++) {
                int lin = i * 256 + tid;
                int r = lin / 48, c = lin % 48;
                wreg[i] = *reinterpret_cast<const float4*>(
                    &W[(size_t)(k0 + 32 + r) * QKV_ + c * 4]);
            }
        }

        const uint32_t Ab = smem_u32(&As[buf][0]);
        const uint32_t Wb = smem_u32(&Ws[buf][0]);
#pragma unroll
        for (int ko16 = 0; ko16 < 2; ko16++) {
            const int ko = ko16 * 16;
            uint32_t a[2][4];
            ldsm_x4(a[0], Ab + aoff0 + 2u * ko);
            ldsm_x4(a[1], Ab + aoff1 + 2u * ko);
#pragma unroll
            for (int n = 0; n < 6; n++) {
                uint32_t b[2];
                int nc = nw * 48 + 8 * n;
                ldsm_x2_t(b, Wb + 2u * ((ko + brow) * 200 + nc));
                mma_f16(acc[0][n], a[0], b);
                mma_f16(acc[1][n], a[1], b);
            }
        }

        if (more) {
#pragma unroll
            for (int i = 0; i < 2; i++) {
                int lin = i * 256 + tid;
                int r = lin >> 3, c4 = lin & 7;
                *reinterpret_cast<uint2*>(&As[buf ^ 1][r * 40 + c4 * 4]) = f4h(areg[i]);
            }
#pragma unroll
            for (int i = 0; i < 6; i++) {
                int lin = i * 256 + tid;
                int r = lin / 48, c = lin % 48;
                *reinterpret_cast<uint2*>(&Ws[buf ^ 1][r * 200 + c * 4]) = f4h(wreg[i]);
            }
        }
    }

    // epilogue: bias; q columns (<64) get QSCALE (0.125 * log2e)
#pragma unroll
    for (int n = 0; n < 6; n++) {
        int col = nw * 48 + 8 * n + 2 * t;
        float sc = (col < 64) ? QSCALE : 1.0f;
        float b0 = bias[col], b1 = bias[col + 1];
#pragma unroll
        for (int mt = 0; mt < 2; mt++) {
            int row = m0 + mw * 32 + mt * 16 + g;
            __half2 v0 = __floats2half2_rn((acc[mt][n][0] + b0) * sc,
                                           (acc[mt][n][1] + b1) * sc);
            *reinterpret_cast<uint32_t*>(&g_qkv[(size_t)row * QKV_ + col]) = h2u(v0);
            __half2 v1 = __floats2half2_rn((acc[mt][n][2] + b0) * sc,
                                           (acc[mt][n][3] + b1) * sc);
            *reinterpret_cast<uint32_t*>(&g_qkv[(size_t)(row + 8) * QKV_ + col]) = h2u(v1);
        }
    }
}

// ---------------------------------------------------------------------------
// Kernel 2: flash attention + fused out-projection.
// BQ=128, BK=64. 8 warps = 4(m) x 2(kv half). exp2-domain softmax.
// Epilogue: ctx -> smem fp16, then out = ctx @ W_out + b in 8 chunks of 128.
// ---------------------------------------------------------------------------
// half-index offsets
#define Q_OFFH 0
#define K_OFFH (128 * 72)
#define V_OFFH (K_OFFH + 64 * 72)
#define P_OFFH (V_OFFH + 64 * 72)
#define OF_OFFW ((P_OFFH + 128 * 72) / 2)        // float-index offset of Of
#define MS_OFFW (OF_OFFW + 128 * 68)
#define LS_OFFW (MS_OFFW + 128)
#define ATTN_SMEM_BYTES ((LS_OFFW + 128) * 4)    // 91,648 B

__global__ __launch_bounds__(256) void attn_kernel(const float* __restrict__ Wout,
                                                   const float* __restrict__ bout,
                                                   float* __restrict__ out) {
    extern __shared__ __half smh[];
    __half* Qs = smh + Q_OFFH;      // [128 q][72]
    __half* Ks = smh + K_OFFH;      // [64 kv][72]
    __half* Vs = smh + V_OFFH;      // [64 kv][72]
    __half* Ps = smh + P_OFFH;      // [128 q][72]
    __half* Cs = smh + P_OFFH;      // ctx fp16 (reuses P after loop)
    __half* Wc = smh + Q_OFFH;      // W_out chunk [64][136] (reuses Q)
    float* Of   = reinterpret_cast<float*>(smh) + OF_OFFW;   // [128][68]
    float* sm_m = reinterpret_cast<float*>(smh) + MS_OFFW;
    float* sm_l = reinterpret_cast<float*>(smh) + LS_OFFW;

    const int b    = blockIdx.y;
    const int q0   = blockIdx.x * 128;
    const int tid  = threadIdx.x;
    const int w    = tid >> 5;
    const int lane = tid & 31;
    const int g    = lane >> 2;
    const int t    = lane & 3;
    const int mw   = w >> 1;        // 0..3 : 32 q rows
    const int nw   = w & 1;         // 0..1 : kv half
    const __half* qkv = g_qkv + (size_t)b * S_ * QKV_;

    const uint32_t Qb = smem_u32(Qs);
    const uint32_t Kb = smem_u32(Ks);
    const uint32_t Vb = smem_u32(Vs);
    const uint32_t Pb = smem_u32(Ps);

    const uint32_t brow = (lane & 7) + ((lane >> 3) & 1) * 8;
    const uint32_t aoffQ0 = 2u * ((mw * 32 + (lane & 15)) * 72 + (lane >> 4) * 8);
    const uint32_t aoffQ1 = aoffQ0 + 2u * (16 * 72);
    const uint32_t aoffP0 = aoffQ0 + 2u * (nw * 32);
    const uint32_t aoffP1 = aoffQ1 + 2u * (nw * 32);

    // Load Q (pre-scaled into exp2 domain by qkv epilogue)
#pragma unroll
    for (int i = 0; i < 4; i++) {
        int lin = i * 256 + tid;
        int r = lin >> 3, c8 = lin & 7;
        uint4 v = *reinterpret_cast<const uint4*>(
            &qkv[(size_t)(q0 + r) * QKV_ + c8 * 8]);
        *reinterpret_cast<uint4*>(&Qs[r * 72 + c8 * 8]) = v;
    }

    float oacc[2][8][4];
#pragma unroll
    for (int mt = 0; mt < 2; mt++)
#pragma unroll
        for (int n = 0; n < 8; n++)
#pragma unroll
            for (int j = 0; j < 4; j++) oacc[mt][n][j] = 0.0f;
    float m_r[2][2], l_r[2][2];
#pragma unroll
    for (int mt = 0; mt < 2; mt++) {
        m_r[mt][0] = -1e30f; m_r[mt][1] = -1e30f;
        l_r[mt][0] = 0.0f;   l_r[mt][1] = 0.0f;
    }

    // prefetch kv tile 0
    uint4 kreg[2], vreg[2];
#pragma unroll
    for (int i = 0; i < 2; i++) {
        int lin = i * 256 + tid;
        int r = lin >> 3, c8 = lin & 7;
        kreg[i] = *reinterpret_cast<const uint4*>(&qkv[(size_t)r * QKV_ + H_ + c8 * 8]);
        vreg[i] = *reinterpret_cast<const uint4*>(&qkv[(size_t)r * QKV_ + 2 * H_ + c8 * 8]);
    }

    const int NT = S_ / 64;
    for (int kt = 0; kt < NT; kt++) {
        __syncthreads();
#pragma unroll
        for (int i = 0; i < 2; i++) {
            int lin = i * 256 + tid;
            int r = lin >> 3, c8 = lin & 7;
            *reinterpret_cast<uint4*>(&Ks[r * 72 + c8 * 8]) = kreg[i];
            *reinterpret_cast<uint4*>(&Vs[r * 72 + c8 * 8]) = vreg[i];
        }
        __syncthreads();

        if (kt + 1 < NT) {
            const int kv0 = (kt + 1) * 64;
#pragma unroll
            for (int i = 0; i < 2; i++) {
                int lin = i * 256 + tid;
                int r = lin >> 3, c8 = lin & 7;
                kreg[i] = *reinterpret_cast<const uint4*>(
                    &qkv[(size_t)(kv0 + r) * QKV_ + H_ + c8 * 8]);
                vreg[i] = *reinterpret_cast<const uint4*>(
                    &qkv[(size_t)(kv0 + r) * QKV_ + 2 * H_ + c8 * 8]);
            }
        }

        // S = Q K^T : warp tile 32(q) x 32(kv), k = 64
        float sacc[2][4][4];
#pragma unroll
        for (int mt = 0; mt < 2; mt++)
#pragma unroll
            for (int n = 0; n < 4; n++)
#pragma unroll
                for (int j = 0; j < 4; j++) sacc[mt][n][j] = 0.0f;

#pragma unroll
        for (int ko16 = 0; ko16 < 4; ko16++) {
            const int ko = ko16 * 16;
            uint32_t a[2][4];
            ldsm_x4(a[0], Qb + aoffQ0 + 2u * ko);
            ldsm_x4(a[1], Qb + aoffQ1 + 2u * ko);
#pragma unroll
            for (int n = 0; n < 4; n++) {
                uint32_t bb[2];
                ldsm_x2(bb, Kb + 2u * ((nw * 32 + 8 * n + (lane & 7)) * 72 +
                                        ko + ((lane >> 3) & 1) * 8));
                mma_f16(sacc[0][n], a[0], bb);
                mma_f16(sacc[1][n], a[1], bb);
            }
        }

        // online softmax (exp2 domain) per mt over this warp's kv half
#pragma unroll
        for (int mt = 0; mt < 2; mt++) {
            float m0 = -1e30f, m1 = -1e30f;
#pragma unroll
            for (int n = 0; n < 4; n++) {
                m0 = fmaxf(m0, fmaxf(sacc[mt][n][0], sacc[mt][n][1]));
                m1 = fmaxf(m1, fmaxf(sacc[mt][n][2], sacc[mt][n][3]));
            }
            m0 = fmaxf(m0, __shfl_xor_sync(0xffffffffu, m0, 1));
            m0 = fmaxf(m0, __shfl_xor_sync(0xffffffffu, m0, 2));
            m1 = fmaxf(m1, __shfl_xor_sync(0xffffffffu, m1, 1));
            m1 = fmaxf(m1, __shfl_xor_sync(0xffffffffu, m1, 2));
            float mn0 = fmaxf(m_r[mt][0], m0);
            float mn1 = fmaxf(m_r[mt][1], m1);
            float al0 = ex2f(m_r[mt][0] - mn0);
            float al1 = ex2f(m_r[mt][1] - mn1);
            m_r[mt][0] = mn0; m_r[mt][1] = mn1;

            float s0 = 0.0f, s1 = 0.0f;
#pragma unroll
            for (int n = 0; n < 4; n++) {
                sacc[mt][n][0] = ex2f(sacc[mt][n][0] - mn0);
                sacc[mt][n][1] = ex2f(sacc[mt][n][1] - mn0);
                sacc[mt][n][2] = ex2f(sacc[mt][n][2] - mn1);
                sacc[mt][n][3] = ex2f(sacc[mt][n][3] - mn1);
                s0 += sacc[mt][n][0] + sacc[mt][n][1];
                s1 += sacc[mt][n][2] + sacc[mt][n][3];
            }
            s0 += __shfl_xor_sync(0xffffffffu, s0, 1);
            s0 += __shfl_xor_sync(0xffffffffu, s0, 2);
            s1 += __shfl_xor_sync(0xffffffffu, s1, 1);
            s1 += __shfl_xor_sync(0xffffffffu, s1, 2);
            l_r[mt][0] = l_r[mt][0] * al0 + s0;
            l_r[mt][1] = l_r[mt][1] * al1 + s1;
            if (al0 != 1.0f || al1 != 1.0f) {
#pragma unroll
                for (int n = 0; n < 8; n++) {
                    oacc[mt][n][0] *= al0;
                    oacc[mt][n][1] *= al0;
                    oacc[mt][n][2] *= al1;
                    oacc[mt][n][3] *= al1;
                }
            }
            int r0 = mw * 32 + mt * 16 + g;
            int cb = nw * 32 + 2 * t;
#pragma unroll
            for (int n = 0; n < 4; n++) {
                *reinterpret_cast<uint32_t*>(&Ps[r0 * 72 + cb + 8 * n]) =
                    h2u(__floats2half2_rn(sacc[mt][n][0], sacc[mt][n][1]));
                *reinterpret_cast<uint32_t*>(&Ps[(r0 + 8) * 72 + cb + 8 * n]) =
                    h2u(__floats2half2_rn(sacc[mt][n][2], sacc[mt][n][3]));
            }
        }
        __syncwarp();

        // O += P V : warp tile 32(q) x 64(h), k = warp's 32 kv
#pragma unroll
        for (int ko16 = 0; ko16 < 2; ko16++) {
            const int ko = ko16 * 16;
            uint32_t a[2][4];
            ldsm_x4(a[0], Pb + aoffP0 + 2u * ko);
            ldsm_x4(a[1], Pb + aoffP1 + 2u * ko);
#pragma unroll
            for (int n = 0; n < 8; n++) {
                uint32_t bb[2];
                ldsm_x2_t(bb, Vb + 2u * ((nw * 32 + ko + brow) * 72 + 8 * n));
                mma_f16(oacc[0][n], a[0], bb);
                mma_f16(oacc[1][n], a[1], bb);
            }
        }
    }

    // prefetch W_out chunk 0 early (hides LDG latency under merge)
    float4 wpre[8];
#pragma unroll
    for (int i = 0; i < 8; i++) {
        int lin = i * 256 + tid;
        int r = lin >> 5, c4 = lin & 31;
        wpre[i] = *reinterpret_cast<const float4*>(&Wout[(size_t)r * E_ + c4 * 4]);
    }

    // ---- merge kv halves -> ctx fp16 in Cs ----
    __syncthreads();
    if (nw == 1) {
#pragma unroll
        for (int mt = 0; mt < 2; mt++) {
            int r0 = mw * 32 + mt * 16 + g;
#pragma unroll
            for (int n = 0; n < 8; n++) {
                int col = 8 * n + 2 * t;
                Of[r0 * 68 + col]           = oacc[mt][n][0];
                Of[r0 * 68 + col + 1]       = oacc[mt][n][1];
                Of[(r0 + 8) * 68 + col]     = oacc[mt][n][2];
                Of[(r0 + 8) * 68 + col + 1] = oacc[mt][n][3];
            }
            if (t == 0) {
                sm_m[r0] = m_r[mt][0]; sm_l[r0] = l_r[mt][0];
                sm_m[r0 + 8] = m_r[mt][1]; sm_l[r0 + 8] = l_r[mt][1];
            }
        }
    }
    __syncthreads();
    if (nw == 0) {
#pragma unroll
        for (int mt = 0; mt < 2; mt++) {
            int r0 = mw * 32 + mt * 16 + g;
#pragma unroll
            for (int half = 0; half < 2; half++) {
                int row = r0 + 8 * half;
                float mA = m_r[mt][half], lA = l_r[mt][half];
                float mB = sm_m[row],     lB = sm_l[row];
                float mm = fmaxf(mA, mB);
                float fA = ex2f(mA - mm), fB = ex2f(mB - mm);
                float inv = 1.0f / (lA * fA + lB * fB);
                fA *= inv; fB *= inv;
#pragma unroll
                for (int n = 0; n < 8; n++) {
                    int col = 8 * n + 2 * t;
                    float x0 = oacc[mt][n][2 * half]     * fA + Of[row * 68 + col]     * fB;
                    float x1 = oacc[mt][n][2 * half + 1] * fA + Of[row * 68 + col + 1] * fB;
                    *reinterpret_cast<uint32_t*>(&Cs[row * 72 + col]) =
                        h2u(__floats2half2_rn(x0, x1));
                }
            }
        }
    }

    // ---- fused out projection: out[128, 1024] = Cs @ W_out + b ----
    const uint32_t Cb2 = smem_u32(Cs);
    const uint32_t Wb2 = smem_u32(Wc);
    const uint32_t aoffC0 = 2u * ((mw * 32 + (lane & 15)) * 72 + (lane >> 4) * 8);
    const uint32_t aoffC1 = aoffC0 + 2u * (16 * 72);
    const size_t orow0 = (size_t)b * S_ + q0;

    for (int ch = 0; ch < 8; ch++) {
        __syncthreads();   // Cs ready (ch 0) / previous chunk MMA done
#pragma unroll
        for (int i = 0; i < 8; i++) {
            int lin = i * 256 + tid;
            int r = lin >> 5, c4 = lin & 31;
            *reinterpret_cast<uint2*>(&Wc[r * 136 + c4 * 4]) = f4h(wpre[i]);
        }
        __syncthreads();

        if (ch + 1 < 8) {
#pragma unroll
            for (int i = 0; i < 8; i++) {
                int lin = i * 256 + tid;
                int r = lin >> 5, c4 = lin & 31;
                wpre[i] = *reinterpret_cast<const float4*>(
                    &Wout[(size_t)r * E_ + (ch + 1) * 128 + c4 * 4]);
            }
        }

        float acc[2][8][4];
#pragma unroll
        for (int mt = 0; mt < 2; mt++)
#pragma unroll
            for (int n = 0; n < 8; n++)
#pragma unroll
                for (int j = 0; j < 4; j++) acc[mt][n][j] = 0.0f;

#pragma unroll
        for (int ko16 = 0; ko16 < 4; ko16++) {
            const int ko = ko16 * 16;
            uint32_t a[2][4];
            ldsm_x4(a[0], Cb2 + aoffC0 + 2u * ko);
            ldsm_x4(a[1], Cb2 + aoffC1 + 2u * ko);
#pragma unroll
            for (int n = 0; n < 8; n++) {
                uint32_t bb[2];
                int nc = nw * 64 + 8 * n;
                ldsm_x2_t(bb, Wb2 + 2u * ((ko + brow) * 136 + nc));
                mma_f16(acc[0][n], a[0], bb);
                mma_f16(acc[1][n], a[1], bb);
            }
        }

#pragma unroll
        for (int n = 0; n < 8; n++) {
            int col = ch * 128 + nw * 64 + 8 * n + 2 * t;
            float2 bb = *reinterpret_cast<const float2*>(&bout[col]);
#pragma unroll
            for (int mt = 0; mt < 2; mt++) {
                int row = mw * 32 + mt * 16 + g;
                float2 v0 = make_float2(acc[mt][n][0] + bb.x, acc[mt][n][1] + bb.y);
                *reinterpret_cast<float2*>(&out[(orow0 + row) * E_ + col]) = v0;
                float2 v1 = make_float2(acc[mt][n][2] + bb.x, acc[mt][n][3] + bb.y);
                *reinterpret_cast<float2*>(&out[(orow0 + row + 8) * E_ + col]) = v1;
            }
        }
    }
}

// ---------------------------------------------------------------------------
extern "C" void kernel_launch(void* const* d_in, const int* in_sizes, int n_in,
                              void* d_out, int out_size) {
    const float* x     = (const float*)d_in[0];
    const float* W_qkv = (const float*)d_in[1];
    const float* b_qkv = (const float*)d_in[2];
    const float* W_out = (const float*)d_in[3];
    const float* b_out = (const float*)d_in[4];
    float* out = (float*)d_out;

    qkv_kernel<<<M_TOT / 64, 256>>>(x, W_qkv, b_qkv);

    {
        cudaFuncSetAttribute(attn_kernel,
                             cudaFuncAttributeMaxDynamicSharedMemorySize,
                             ATTN_SMEM_BYTES);
        dim3 grid(S_ / 128, B_);
        attn_kernel<<<grid, 256, ATTN_SMEM_BYTES>>>(W_out, b_out, out);
    }
}

// round 10
// speedup vs baseline: 7.1772x; 1.0350x over previous
#include <cuda_runtime.h>
#include <cuda_fp16.h>
#include <stdint.h>
#include <math.h>

#define B_    4
#define S_    4096
#define E_    1024
#define H_    64
#define QKV_  192
#define M_TOT (B_ * S_)   // 16384

// Q is pre-scaled by 0.125 * log2(e) so softmax runs in the exp2 domain.
#define QSCALE 0.18033688011112042f

__device__ __half g_qkv[B_ * S_ * QKV_];   // [16384, 192] fp16

// ---------------------------------------------------------------------------
// helpers
// ---------------------------------------------------------------------------
__device__ __forceinline__ uint32_t h2u(__half2 h) {
    return *reinterpret_cast<uint32_t*>(&h);
}
__device__ __forceinline__ uint2 f4h(float4 v) {
    uint2 u;
    u.x = h2u(__floats2half2_rn(v.x, v.y));
    u.y = h2u(__floats2half2_rn(v.z, v.w));
    return u;
}
__device__ __forceinline__ float ex2f(float x) {
    float y;
    asm("ex2.approx.ftz.f32 %0, %1;" : "=f"(y) : "f"(x));
    return y;
}
__device__ __forceinline__ void mma_f16(float d[4], const uint32_t a[4],
                                        const uint32_t b[2]) {
    asm volatile(
        "mma.sync.aligned.m16n8k16.row.col.f32.f16.f16.f32 "
        "{%0,%1,%2,%3},{%4,%5,%6,%7},{%8,%9},{%0,%1,%2,%3};\n"
        : "+f"(d[0]), "+f"(d[1]), "+f"(d[2]), "+f"(d[3])
        : "r"(a[0]), "r"(a[1]), "r"(a[2]), "r"(a[3]),
          "r"(b[0]), "r"(b[1]));
}
__device__ __forceinline__ void ldsm_x4(uint32_t d[4], uint32_t saddr) {
    asm volatile("ldmatrix.sync.aligned.m8n8.x4.shared.b16 {%0,%1,%2,%3}, [%4];"
                 : "=r"(d[0]), "=r"(d[1]), "=r"(d[2]), "=r"(d[3]) : "r"(saddr));
}
__device__ __forceinline__ void ldsm_x4_t(uint32_t d[4], uint32_t saddr) {
    asm volatile("ldmatrix.sync.aligned.m8n8.x4.trans.shared.b16 {%0,%1,%2,%3}, [%4];"
                 : "=r"(d[0]), "=r"(d[1]), "=r"(d[2]), "=r"(d[3]) : "r"(saddr));
}
__device__ __forceinline__ void ldsm_x2_t(uint32_t d[2], uint32_t saddr) {
    asm volatile("ldmatrix.sync.aligned.m8n8.x2.trans.shared.b16 {%0,%1}, [%2];"
                 : "=r"(d[0]), "=r"(d[1]) : "r"(saddr));
}
__device__ __forceinline__ uint32_t smem_u32(const void* p) {
    return (uint32_t)__cvta_generic_to_shared(p);
}

// ---------------------------------------------------------------------------
// Kernel 1: QKV projection. C[16384,192] = x[16384,1024] @ W[1024,192] + b
// BM=64, BN=192, BK=32, grid 256, 2 CTAs/SM, double-buffered smem.
// ---------------------------------------------------------------------------
__global__ __launch_bounds__(256, 2) void qkv_kernel(const float* __restrict__ A,
                                                     const float* __restrict__ W,
                                                     const float* __restrict__ bias) {
    __shared__ __half As[2][64 * 40];    // [m][k] stride 40
    __shared__ __half Ws[2][32 * 200];   // [k][n] stride 200

    const int m0   = blockIdx.x * 64;
    const int tid  = threadIdx.x;
    const int w    = tid >> 5;
    const int lane = tid & 31;
    const int g    = lane >> 2;
    const int t    = lane & 3;
    const int mw   = w >> 2;    // 0..1
    const int nw   = w & 3;     // 0..3

    const uint32_t brow = (lane & 7) + ((lane >> 3) & 1) * 8;
    const uint32_t aoff0 = 2u * ((mw * 32 + (lane & 15)) * 40 + (lane >> 4) * 8);
    const uint32_t aoff1 = aoff0 + 2u * (16 * 40);

    float acc[2][6][4];
#pragma unroll
    for (int mt = 0; mt < 2; mt++)
#pragma unroll
        for (int n = 0; n < 6; n++)
#pragma unroll
            for (int j = 0; j < 4; j++) acc[mt][n][j] = 0.0f;

    float4 areg[2], wreg[6];
#pragma unroll
    for (int i = 0; i < 2; i++) {
        int lin = i * 256 + tid;
        int r = lin >> 3, c4 = lin & 7;
        areg[i] = *reinterpret_cast<const float4*>(&A[(size_t)(m0 + r) * E_ + c4 * 4]);
    }
#pragma unroll
    for (int i = 0; i < 6; i++) {
        int lin = i * 256 + tid;
        int r = lin / 48, c = lin % 48;
        wreg[i] = *reinterpret_cast<const float4*>(&W[(size_t)r * QKV_ + c * 4]);
    }
#pragma unroll
    for (int i = 0; i < 2; i++) {
        int lin = i * 256 + tid;
        int r = lin >> 3, c4 = lin & 7;
        *reinterpret_cast<uint2*>(&As[0][r * 40 + c4 * 4]) = f4h(areg[i]);
    }
#pragma unroll
    for (int i = 0; i < 6; i++) {
        int lin = i * 256 + tid;
        int r = lin / 48, c = lin % 48;
        *reinterpret_cast<uint2*>(&Ws[0][r * 200 + c * 4]) = f4h(wreg[i]);
    }

    for (int k0 = 0; k0 < E_; k0 += 32) {
        const int buf = (k0 >> 5) & 1;
        __syncthreads();
        const bool more = (k0 + 32 < E_);
        if (more) {
#pragma unroll
            for (int i = 0; i < 2; i++) {
                int lin = i * 256 + tid;
                int r = lin >> 3, c4 = lin & 7;
                areg[i] = *reinterpret_cast<const float4*>(
                    &A[(size_t)(m0 + r) * E_ + k0 + 32 + c4 * 4]);
            }
#pragma unroll
            for (int i = 0; i < 6; i++) {
                int lin = i * 256 + tid;
                int r = lin / 48, c = lin % 48;
                wreg[i] = *reinterpret_cast<const float4*>(
                    &W[(size_t)(k0 + 32 + r) * QKV_ + c * 4]);
            }
        }

        const uint32_t Ab = smem_u32(&As[buf][0]);
        const uint32_t Wb = smem_u32(&Ws[buf][0]);
#pragma unroll
        for (int ko16 = 0; ko16 < 2; ko16++) {
            const int ko = ko16 * 16;
            uint32_t a[2][4];
            ldsm_x4(a[0], Ab + aoff0 + 2u * ko);
            ldsm_x4(a[1], Ab + aoff1 + 2u * ko);
#pragma unroll
            for (int n = 0; n < 6; n++) {
                uint32_t b[2];
                int nc = nw * 48 + 8 * n;
                ldsm_x2_t(b, Wb + 2u * ((ko + brow) * 200 + nc));
                mma_f16(acc[0][n], a[0], b);
                mma_f16(acc[1][n], a[1], b);
            }
        }

        if (more) {
#pragma unroll
            for (int i = 0; i < 2; i++) {
                int lin = i * 256 + tid;
                int r = lin >> 3, c4 = lin & 7;
                *reinterpret_cast<uint2*>(&As[buf ^ 1][r * 40 + c4 * 4]) = f4h(areg[i]);
            }
#pragma unroll
            for (int i = 0; i < 6; i++) {
                int lin = i * 256 + tid;
                int r = lin / 48, c = lin % 48;
                *reinterpret_cast<uint2*>(&Ws[buf ^ 1][r * 200 + c * 4]) = f4h(wreg[i]);
            }
        }
    }

#pragma unroll
    for (int n = 0; n < 6; n++) {
        int col = nw * 48 + 8 * n + 2 * t;
        float sc = (col < 64) ? QSCALE : 1.0f;
        float b0 = bias[col], b1 = bias[col + 1];
#pragma unroll
        for (int mt = 0; mt < 2; mt++) {
            int row = m0 + mw * 32 + mt * 16 + g;
            __half2 v0 = __floats2half2_rn((acc[mt][n][0] + b0) * sc,
                                           (acc[mt][n][1] + b1) * sc);
            *reinterpret_cast<uint32_t*>(&g_qkv[(size_t)row * QKV_ + col]) = h2u(v0);
            __half2 v1 = __floats2half2_rn((acc[mt][n][2] + b0) * sc,
                                           (acc[mt][n][3] + b1) * sc);
            *reinterpret_cast<uint32_t*>(&g_qkv[(size_t)(row + 8) * QKV_ + col]) = h2u(v1);
        }
    }
}

// ---------------------------------------------------------------------------
// Kernel 2: flash attention + fused out-projection.
// BQ=64, BK=64, grid 256, 2 CTAs/SM. 8 warps = 4(m, 16 rows) x 2(kv half).
// Q fragments in registers (loop-invariant); P kept in registers (C->A frag
// identity); K/V fragments via ldmatrix.x4 pairs. exp2-domain softmax.
// ---------------------------------------------------------------------------
// half-index offsets
#define Q_OFFH 0
#define K_OFFH (64 * 72)
#define V_OFFH (2 * 64 * 72)
#define CS_OFFH V_OFFH                      // ctx fp16 reuses V region
#define WC_OFFH 0                           // W chunk [64][136] reuses Q+K
#define OF_OFFW ((3 * 64 * 72) / 2)         // float idx: after Q/K/V
#define MS_OFFW (OF_OFFW + 64 * 68)
#define LS_OFFW (MS_OFFW + 64)
#define ATTN_SMEM_BYTES ((LS_OFFW + 64) * 4)   // 45,568 B -> 2 CTAs/SM

__global__ __launch_bounds__(256, 2) void attn_kernel(const float* __restrict__ Wout,
                                                      const float* __restrict__ bout,
                                                      float* __restrict__ out) {
    extern __shared__ __half smh[];
    __half* Qs = smh + Q_OFFH;      // [64 q][72]
    __half* Ks = smh + K_OFFH;      // [64 kv][72]
    __half* Vs = smh + V_OFFH;      // [64 kv][72]
    __half* Cs = smh + CS_OFFH;     // ctx fp16 (after loop)
    __half* Wc = smh + WC_OFFH;     // W_out chunk [64][136]
    float* Of   = reinterpret_cast<float*>(smh) + OF_OFFW;   // [64][68]
    float* sm_m = reinterpret_cast<float*>(smh) + MS_OFFW;
    float* sm_l = reinterpret_cast<float*>(smh) + LS_OFFW;

    const int b    = blockIdx.y;
    const int q0   = blockIdx.x * 64;
    const int tid  = threadIdx.x;
    const int w    = tid >> 5;
    const int lane = tid & 31;
    const int g    = lane >> 2;
    const int t    = lane & 3;
    const int mw   = w >> 1;        // 0..3 : 16 q rows
    const int nw   = w & 1;         // 0..1 : kv half
    const __half* qkv = g_qkv + (size_t)b * S_ * QKV_;

    const uint32_t Qb = smem_u32(Qs);
    const uint32_t Kb = smem_u32(Ks);
    const uint32_t Vb = smem_u32(Vs);

    // per-lane ldmatrix byte offsets
    const uint32_t aoffQ = 2u * ((mw * 16 + (lane & 15)) * 72 + (lane >> 4) * 8);
    // K x4 (pairs of n-groups): row = nw*32 + 16*nj + (lane&7) + ((lane>>4)&1)*8
    const uint32_t koffK = 2u * ((nw * 32 + (lane & 7) + ((lane >> 4) & 1) * 8) * 72 +
                                 ((lane >> 3) & 1) * 8);
    // V x4 trans (pairs of n-groups): row = nw*32 + 16*kp + (lane&7) + ((lane>>3)&1)*8
    const uint32_t voffV = 2u * ((nw * 32 + (lane & 7) + ((lane >> 3) & 1) * 8) * 72 +
                                 ((lane >> 4) & 1) * 8);

    // Load Q (pre-scaled into exp2 domain)
#pragma unroll
    for (int i = 0; i < 2; i++) {
        int lin = i * 256 + tid;
        int r = lin >> 3, c8 = lin & 7;
        uint4 v = *reinterpret_cast<const uint4*>(
            &qkv[(size_t)(q0 + r) * QKV_ + c8 * 8]);
        *reinterpret_cast<uint4*>(&Qs[r * 72 + c8 * 8]) = v;
    }

    // prefetch kv tile 0
    uint4 kreg[2], vreg[2];
#pragma unroll
    for (int i = 0; i < 2; i++) {
        int lin = i * 256 + tid;
        int r = lin >> 3, c8 = lin & 7;
        kreg[i] = *reinterpret_cast<const uint4*>(&qkv[(size_t)r * QKV_ + H_ + c8 * 8]);
        vreg[i] = *reinterpret_cast<const uint4*>(&qkv[(size_t)r * QKV_ + 2 * H_ + c8 * 8]);
    }
    __syncthreads();

    // hoist Q fragments (loop-invariant): 4 ko16 x 4 regs = 16 regs
    uint32_t qfrag[4][4];
#pragma unroll
    for (int ko16 = 0; ko16 < 4; ko16++)
        ldsm_x4(qfrag[ko16], Qb + aoffQ + 2u * (ko16 * 16));

    float oacc[8][4];
#pragma unroll
    for (int n = 0; n < 8; n++)
#pragma unroll
        for (int j = 0; j < 4; j++) oacc[n][j] = 0.0f;
    float mr0 = -1e30f, mr1 = -1e30f, l0 = 0.0f, l1 = 0.0f;

    const int NT = S_ / 64;
    for (int kt = 0; kt < NT; kt++) {
        __syncthreads();
#pragma unroll
        for (int i = 0; i < 2; i++) {
            int lin = i * 256 + tid;
            int r = lin >> 3, c8 = lin & 7;
            *reinterpret_cast<uint4*>(&Ks[r * 72 + c8 * 8]) = kreg[i];
            *reinterpret_cast<uint4*>(&Vs[r * 72 + c8 * 8]) = vreg[i];
        }
        __syncthreads();

        if (kt + 1 < NT) {
            const int kv0 = (kt + 1) * 64;
#pragma unroll
            for (int i = 0; i < 2; i++) {
                int lin = i * 256 + tid;
                int r = lin >> 3, c8 = lin & 7;
                kreg[i] = *reinterpret_cast<const uint4*>(
                    &qkv[(size_t)(kv0 + r) * QKV_ + H_ + c8 * 8]);
                vreg[i] = *reinterpret_cast<const uint4*>(
                    &qkv[(size_t)(kv0 + r) * QKV_ + 2 * H_ + c8 * 8]);
            }
        }

        // S = Q K^T : warp tile 16(q) x 32(kv), k = 64
        float sacc[4][4];
#pragma unroll
        for (int n = 0; n < 4; n++)
#pragma unroll
            for (int j = 0; j < 4; j++) sacc[n][j] = 0.0f;

#pragma unroll
        for (int ko16 = 0; ko16 < 4; ko16++) {
#pragma unroll
            for (int nj = 0; nj < 2; nj++) {
                uint32_t kf[4];
                ldsm_x4(kf, Kb + koffK + 2u * (nj * 16 * 72 + ko16 * 16));
                mma_f16(sacc[2 * nj],     qfrag[ko16], kf);
                mma_f16(sacc[2 * nj + 1], qfrag[ko16], kf + 2);
            }
        }

        // online softmax (exp2 domain); lane rows g (c0,c1) and g+8 (c2,c3)
        float m0 = -1e30f, m1 = -1e30f;
#pragma unroll
        for (int n = 0; n < 4; n++) {
            m0 = fmaxf(m0, fmaxf(sacc[n][0], sacc[n][1]));
            m1 = fmaxf(m1, fmaxf(sacc[n][2], sacc[n][3]));
        }
        m0 = fmaxf(m0, __shfl_xor_sync(0xffffffffu, m0, 1));
        m0 = fmaxf(m0, __shfl_xor_sync(0xffffffffu, m0, 2));
        m1 = fmaxf(m1, __shfl_xor_sync(0xffffffffu, m1, 1));
        m1 = fmaxf(m1, __shfl_xor_sync(0xffffffffu, m1, 2));
        float mn0 = fmaxf(mr0, m0);
        float mn1 = fmaxf(mr1, m1);
        float al0 = ex2f(mr0 - mn0);
        float al1 = ex2f(mr1 - mn1);
        mr0 = mn0; mr1 = mn1;

        float s0 = 0.0f, s1 = 0.0f;
#pragma unroll
        for (int n = 0; n < 4; n++) {
            sacc[n][0] = ex2f(sacc[n][0] - mn0);
            sacc[n][1] = ex2f(sacc[n][1] - mn0);
            sacc[n][2] = ex2f(sacc[n][2] - mn1);
            sacc[n][3] = ex2f(sacc[n][3] - mn1);
            s0 += sacc[n][0] + sacc[n][1];
            s1 += sacc[n][2] + sacc[n][3];
        }
        s0 += __shfl_xor_sync(0xffffffffu, s0, 1);
        s0 += __shfl_xor_sync(0xffffffffu, s0, 2);
        s1 += __shfl_xor_sync(0xffffffffu, s1, 1);
        s1 += __shfl_xor_sync(0xffffffffu, s1, 2);
        l0 = l0 * al0 + s0;
        l1 = l1 * al1 + s1;
        if (al0 != 1.0f || al1 != 1.0f) {
#pragma unroll
            for (int n = 0; n < 8; n++) {
                oacc[n][0] *= al0;
                oacc[n][1] *= al0;
                oacc[n][2] *= al1;
                oacc[n][3] *= al1;
            }
        }

        // P: C-fragment -> A-fragment in registers (no smem round trip)
#pragma unroll
        for (int kp = 0; kp < 2; kp++) {
            uint32_t pf[4];
            pf[0] = h2u(__floats2half2_rn(sacc[2 * kp][0],     sacc[2 * kp][1]));
            pf[1] = h2u(__floats2half2_rn(sacc[2 * kp][2],     sacc[2 * kp][3]));
            pf[2] = h2u(__floats2half2_rn(sacc[2 * kp + 1][0], sacc[2 * kp + 1][1]));
            pf[3] = h2u(__floats2half2_rn(sacc[2 * kp + 1][2], sacc[2 * kp + 1][3]));
#pragma unroll
            for (int nj = 0; nj < 4; nj++) {
                uint32_t vf[4];
                ldsm_x4_t(vf, Vb + voffV + 2u * (kp * 16 * 72 + nj * 16));
                mma_f16(oacc[2 * nj],     pf, vf);
                mma_f16(oacc[2 * nj + 1], pf, vf + 2);
            }
        }
    }

    // prefetch W_out chunk 0 (hidden under merge)
    float4 wpre[8];
#pragma unroll
    for (int i = 0; i < 8; i++) {
        int lin = i * 256 + tid;
        int r = lin >> 5, c4 = lin & 31;
        wpre[i] = *reinterpret_cast<const float4*>(&Wout[(size_t)r * E_ + c4 * 4]);
    }

    // ---- merge kv halves -> ctx fp16 in Cs ----
    const int r0 = mw * 16 + g;
    __syncthreads();
    if (nw == 1) {
#pragma unroll
        for (int n = 0; n < 8; n++) {
            int col = 8 * n + 2 * t;
            Of[r0 * 68 + col]           = oacc[n][0];
            Of[r0 * 68 + col + 1]       = oacc[n][1];
            Of[(r0 + 8) * 68 + col]     = oacc[n][2];
            Of[(r0 + 8) * 68 + col + 1] = oacc[n][3];
        }
        if (t == 0) {
            sm_m[r0] = mr0; sm_l[r0] = l0;
            sm_m[r0 + 8] = mr1; sm_l[r0 + 8] = l1;
        }
    }
    __syncthreads();
    if (nw == 0) {
#pragma unroll
        for (int half = 0; half < 2; half++) {
            int row = r0 + 8 * half;
            float mA = half ? mr1 : mr0, lA = half ? l1 : l0;
            float mB = sm_m[row],        lB = sm_l[row];
            float mm = fmaxf(mA, mB);
            float fA = ex2f(mA - mm), fB = ex2f(mB - mm);
            float inv = 1.0f / (lA * fA + lB * fB);
            fA *= inv; fB *= inv;
#pragma unroll
            for (int n = 0; n < 8; n++) {
                int col = 8 * n + 2 * t;
                float x0 = oacc[n][2 * half]     * fA + Of[row * 68 + col]     * fB;
                float x1 = oacc[n][2 * half + 1] * fA + Of[row * 68 + col + 1] * fB;
                *reinterpret_cast<uint32_t*>(&Cs[row * 72 + col]) =
                    h2u(__floats2half2_rn(x0, x1));
            }
        }
    }

    // ---- fused out projection: out[64, 1024] = Cs @ W_out + b ----
    const uint32_t Cb2 = smem_u32(Cs);
    const uint32_t Wb2 = smem_u32(Wc);
    const uint32_t brow = (lane & 7) + ((lane >> 3) & 1) * 8;
    const uint32_t aoffC = 2u * ((mw * 16 + (lane & 15)) * 72 + (lane >> 4) * 8);
    const size_t orow0 = (size_t)b * S_ + q0;

    for (int ch = 0; ch < 8; ch++) {
        __syncthreads();   // Cs ready (ch 0) / previous chunk done
#pragma unroll
        for (int i = 0; i < 8; i++) {
            int lin = i * 256 + tid;
            int r = lin >> 5, c4 = lin & 31;
            *reinterpret_cast<uint2*>(&Wc[r * 136 + c4 * 4]) = f4h(wpre[i]);
        }
        __syncthreads();

        if (ch + 1 < 8) {
#pragma unroll
            for (int i = 0; i < 8; i++) {
                int lin = i * 256 + tid;
                int r = lin >> 5, c4 = lin & 31;
                wpre[i] = *reinterpret_cast<const float4*>(
                    &Wout[(size_t)r * E_ + (ch + 1) * 128 + c4 * 4]);
            }
        }

        float acc[8][4];
#pragma unroll
        for (int n = 0; n < 8; n++)
#pragma unroll
            for (int j = 0; j < 4; j++) acc[n][j] = 0.0f;

#pragma unroll
        for (int ko16 = 0; ko16 < 4; ko16++) {
            const int ko = ko16 * 16;
            uint32_t a[4];
            ldsm_x4(a, Cb2 + aoffC + 2u * ko);
#pragma unroll
            for (int n = 0; n < 8; n++) {
                uint32_t bb[2];
                int nc = nw * 64 + 8 * n;
                ldsm_x2_t(bb, Wb2 + 2u * ((ko + brow) * 136 + nc));
                mma_f16(acc[n], a, bb);
            }
        }

#pragma unroll
        for (int n = 0; n < 8; n++) {
            int col = ch * 128 + nw * 64 + 8 * n + 2 * t;
            float2 bb = *reinterpret_cast<const float2*>(&bout[col]);
            float2 v0 = make_float2(acc[n][0] + bb.x, acc[n][1] + bb.y);
            *reinterpret_cast<float2*>(&out[(orow0 + r0) * E_ + col]) = v0;
            float2 v1 = make_float2(acc[n][2] + bb.x, acc[n][3] + bb.y);
            *reinterpret_cast<float2*>(&out[(orow0 + r0 + 8) * E_ + col]) = v1;
        }
    }
}

// ---------------------------------------------------------------------------
extern "C" void kernel_launch(void* const* d_in, const int* in_sizes, int n_in,
                              void* d_out, int out_size) {
    const float* x     = (const float*)d_in[0];
    const float* W_qkv = (const float*)d_in[1];
    const float* b_qkv = (const float*)d_in[2];
    const float* W_out = (const float*)d_in[3];
    const float* b_out = (const float*)d_in[4];
    float* out = (float*)d_out;

    qkv_kernel<<<M_TOT / 64, 256>>>(x, W_qkv, b_qkv);

    {
        cudaFuncSetAttribute(attn_kernel,
                             cudaFuncAttributeMaxDynamicSharedMemorySize,
                             ATTN_SMEM_BYTES);
        dim3 grid(S_ / 64, B_);
        attn_kernel<<<grid, 256, ATTN_SMEM_BYTES>>>(W_out, b_out, out);
    }
}